// round 9
// baseline (speedup 1.0000x reference)
#include <cuda_runtime.h>
#include <cuda_fp16.h>
#include <cuda_bf16.h>
#include <math.h>
#include <stdint.h>
#include <stddef.h>

#define BSZ 4
#define CCH 12
#define HH 384
#define WW 384
#define HW (HH*WW)
#define NN 4096

// ---------------- static device scratch (no allocs allowed) ----------------
__device__ __half         g_h1n[(size_t)BSZ*HW*64];   // conv1 out, NHWC fp16
__device__ __half         g_h2n[(size_t)BSZ*HW*64];   // conv2 out, NHWC fp16
__device__ __nv_bfloat16  g_adjb[(size_t)2*NN*NN];    // adj bf16
__device__ __half         g_w2t[9*64*64];             // conv2 w [tap][co][ci]
__device__ __half         g_w3t[9*8*64];              // conv3 w [tap][o pad8][ci]
__device__ __nv_bfloat16  g_st [(size_t)2*256*NN];    // s^T  [c][b*64+o][m]
__device__ __nv_bfloat16  g_s3t[(size_t)2*144*NN];    // s3^T [c][b*36+o][m]
__device__ float          g_g  [(size_t)2*NN*256];    // relu(adj@s) [c][m][256]
__device__ float          g_t3 [(size_t)2*NN*144];    // adj@s3 [c][m][144]
__device__ float          g_tmp2[BSZ*2*HW];
__device__ float          g_oimg[BSZ*2*HW];
__device__ float2         g_k[(size_t)CCH*BSZ*HW];
__device__ float2         g_tw128[64];
__device__ float2         g_tw384[384];

// ---------------- mma / ldmatrix wrappers ----------------
__device__ __forceinline__ void mma_f16(float c[4], unsigned a0, unsigned a1,
                                        unsigned a2, unsigned a3,
                                        unsigned b0, unsigned b1) {
    asm volatile("mma.sync.aligned.m16n8k16.row.col.f32.f16.f16.f32 "
        "{%0,%1,%2,%3}, {%4,%5,%6,%7}, {%8,%9}, {%0,%1,%2,%3};"
        : "+f"(c[0]), "+f"(c[1]), "+f"(c[2]), "+f"(c[3])
        : "r"(a0), "r"(a1), "r"(a2), "r"(a3), "r"(b0), "r"(b1));
}
__device__ __forceinline__ void mma_bf16(float c[4], unsigned a0, unsigned a1,
                                         unsigned a2, unsigned a3,
                                         unsigned b0, unsigned b1) {
    asm volatile("mma.sync.aligned.m16n8k16.row.col.f32.bf16.bf16.f32 "
        "{%0,%1,%2,%3}, {%4,%5,%6,%7}, {%8,%9}, {%0,%1,%2,%3};"
        : "+f"(c[0]), "+f"(c[1]), "+f"(c[2]), "+f"(c[3])
        : "r"(a0), "r"(a1), "r"(a2), "r"(a3), "r"(b0), "r"(b1));
}
__device__ __forceinline__ void ldsm_x4(unsigned r[4], uint32_t a) {
    asm volatile("ldmatrix.sync.aligned.m8n8.x4.shared.b16 {%0,%1,%2,%3}, [%4];"
        : "=r"(r[0]), "=r"(r[1]), "=r"(r[2]), "=r"(r[3]) : "r"(a));
}
__device__ __forceinline__ void ldsm_x2(unsigned& r0, unsigned& r1, uint32_t a) {
    asm volatile("ldmatrix.sync.aligned.m8n8.x2.shared.b16 {%0,%1}, [%2];"
        : "=r"(r0), "=r"(r1) : "r"(a));
}

// ---------------- init ----------------
__global__ void init_tw_k() {
    int t = threadIdx.x;
    if (t < 64) { float s, c; sincospif(-(float)t / 64.f, &s, &c);  g_tw128[t] = make_float2(c, s); }
    {            float s, c; sincospif(-(float)t / 192.f, &s, &c); g_tw384[t] = make_float2(c, s); }
}
__global__ void prep_w_k(const float* __restrict__ cw2, const float* __restrict__ cw3) {
    int i = blockIdx.x * 256 + threadIdx.x;
    if (i < 9 * 64 * 64) {
        int tap = i / 4096, r = i % 4096, co = r >> 6, ci = r & 63;
        g_w2t[i] = __float2half(cw2[(co * 64 + ci) * 9 + tap]);
    }
    if (i < 9 * 8 * 64) {
        int tap = i / 512, r = i % 512, o = r >> 6, ci = r & 63;
        g_w3t[i] = __float2half((o < 2) ? cw3[(o * 64 + ci) * 9 + tap] : 0.f);
    }
}
__global__ __launch_bounds__(256) void adj_cvt_k(const float* __restrict__ adj) {
    size_t i = ((size_t)blockIdx.x * 256 + threadIdx.x) * 4;
    float4 v = *(const float4*)(adj + i);
    __nv_bfloat162* o = (__nv_bfloat162*)(g_adjb + i);
    o[0] = __floats2bfloat162_rn(v.x, v.y);
    o[1] = __floats2bfloat162_rn(v.z, v.w);
}

// ---------------- conv1: 2 -> 64, relu; 4 px x 8 ch per thread ----------------
__global__ __launch_bounds__(256) void conv1_k(const float* __restrict__ in,
                                               const float* __restrict__ w,
                                               const float* __restrict__ bias) {
    __shared__ float ws[18 * 64];   // [q=ci*9+tap][co]
    for (int i = threadIdx.x; i < 1152; i += 256) {
        int co = i / 18, q = i % 18;
        ws[q * 64 + co] = w[i];
    }
    __syncthreads();
    int tid = threadIdx.x;
    int cog = tid & 7;
    int pq  = tid >> 3;
    int chunk = blockIdx.x % 3;
    int rowid = blockIdx.x / 3;
    int y = rowid % HH, b = rowid / HH;
    int px0 = chunk * 128 + pq * 4;
    float iv[2][3][6];
#pragma unroll
    for (int ci = 0; ci < 2; ci++) {
        const float* base = in + (b * 2 + ci) * HW;
#pragma unroll
        for (int ry = 0; ry < 3; ry++) {
            int yy = y + ry - 1; bool yok = (unsigned)yy < HH;
#pragma unroll
            for (int cx = 0; cx < 6; cx++) {
                int xx = px0 + cx - 1;
                iv[ci][ry][cx] = (yok && (unsigned)xx < WW) ? __ldg(base + yy * WW + xx) : 0.f;
            }
        }
    }
    float acc[4][8];
    float bz[8];
#pragma unroll
    for (int j = 0; j < 8; j++) bz[j] = __ldg(bias + cog * 8 + j);
#pragma unroll
    for (int px = 0; px < 4; px++)
#pragma unroll
        for (int j = 0; j < 8; j++) acc[px][j] = bz[j];
#pragma unroll
    for (int ci = 0; ci < 2; ci++)
#pragma unroll
        for (int ky = 0; ky < 3; ky++)
#pragma unroll
            for (int kx = 0; kx < 3; kx++) {
                int q = ci * 9 + ky * 3 + kx;
                const float4* wp = (const float4*)&ws[q * 64 + cog * 8];
                float4 wa = wp[0], wb = wp[1];
                float w8[8] = {wa.x, wa.y, wa.z, wa.w, wb.x, wb.y, wb.z, wb.w};
#pragma unroll
                for (int px = 0; px < 4; px++) {
                    float v = iv[ci][ky][kx + px];
#pragma unroll
                    for (int j = 0; j < 8; j++) acc[px][j] += v * w8[j];
                }
            }
#pragma unroll
    for (int px = 0; px < 4; px++) {
        size_t p = (size_t)b * HW + (size_t)y * WW + (px0 + px);
        __half2 h4[4];
#pragma unroll
        for (int j = 0; j < 8; j += 2)
            h4[j >> 1] = __floats2half2_rn(fmaxf(acc[px][j], 0.f), fmaxf(acc[px][j + 1], 0.f));
        *(uint4*)(g_h1n + p * 64 + cog * 8) = *(const uint4*)h4;
    }
}

// ---------------- conv2: 64->64 mma fp16; ALL 9 taps of B + A in dyn smem ----------------
// grid (6, 192, 4), 128 thr = 4 warps; main loop has ZERO syncthreads.
__global__ __launch_bounds__(128) void conv2_mma(const float* __restrict__ bias) {
    extern __shared__ uint4 dsm[];
    uint4* s_b = dsm;            // [tap 9][co 64][chunk 8 swz] = 4608 uint4 (72KB)
    uint4* s_a = dsm + 4608;     // [row 4][px 66][chunk 8 swz] = 2112 uint4 (33.8KB)
    int x0 = blockIdx.x * 64, y0 = blockIdx.y * 2, b = blockIdx.z;
    int tid = threadIdx.x, wid = tid >> 5, lane = tid & 31;
    int g = lane >> 2, t = lane & 3;
    // stage B: all 9 taps
    for (int idx = tid; idx < 4608; idx += 128) {
        int tap = idx >> 9, rem = idx & 511, co = rem >> 3, cc = rem & 7;
        s_b[tap * 512 + co * 8 + (cc ^ (co & 7))] =
            *(const uint4*)(g_w2t + tap * 4096 + co * 64 + cc * 8);
    }
    // stage A tile (rows y0-1..y0+2, px x0-1..x0+64), halo zero
    for (int idx = tid; idx < 2112; idx += 128) {
        int r = idx / 528, rem = idx % 528, p = rem >> 3, cc = rem & 7;
        int gx = x0 - 1 + p, yy = y0 - 1 + r;
        uint4 v = make_uint4(0, 0, 0, 0);
        if ((unsigned)gx < WW && (unsigned)yy < HH)
            v = *(const uint4*)(g_h1n + ((size_t)(b * HH + yy) * WW + gx) * 64 + cc * 8);
        s_a[(r * 66 + p) * 8 + (cc ^ (p & 7))] = v;
    }
    __syncthreads();
    uint32_t sa = (uint32_t)__cvta_generic_to_shared(s_a);
    uint32_t sbq = (uint32_t)__cvta_generic_to_shared(s_b);
    int lrow = lane & 7, msel = lane >> 3;
    int a_pofs = ((msel & 1) << 3) + lrow;
    int a_hi = msel >> 1;
    int lq = lane >> 3;                     // 0..3 for B x4
    float acc[2][8][4];
#pragma unroll
    for (int r = 0; r < 2; r++)
#pragma unroll
        for (int i = 0; i < 8; i++)
#pragma unroll
            for (int j = 0; j < 4; j++) acc[r][i][j] = 0.f;

#pragma unroll
    for (int ky = 0; ky < 3; ky++)
#pragma unroll
        for (int kx = 0; kx < 3; kx++) {
            int tap = ky * 3 + kx;
            int p = wid * 16 + kx + a_pofs;
            int psw = p & 7;
            int arow0 = (ky * 66 + p) * 8, arow1 = arow0 + 528;
            uint32_t sbt = sbq + tap * 512 * 16;
#pragma unroll
            for (int kk = 0; kk < 4; kk++) {
                unsigned a0[4], a1[4];
                int chunk = 2 * kk + a_hi;
                ldsm_x4(a0, sa + (arow0 + (chunk ^ psw)) * 16);
                ldsm_x4(a1, sa + (arow1 + (chunk ^ psw)) * 16);
#pragma unroll
                for (int ntp = 0; ntp < 4; ntp++) {
                    // x4 B: matrices (lq): {nt,klo},{nt,khi},{nt+1,klo},{nt+1,khi}
                    int co_b = (2 * ntp + (lq >> 1)) * 8 + lrow;
                    int bch = 2 * kk + (lq & 1);
                    unsigned br[4];
                    ldsm_x4(br, sbt + (co_b * 8 + (bch ^ lrow)) * 16);
                    mma_f16(acc[0][2 * ntp],     a0[0], a0[1], a0[2], a0[3], br[0], br[1]);
                    mma_f16(acc[0][2 * ntp + 1], a0[0], a0[1], a0[2], a0[3], br[2], br[3]);
                    mma_f16(acc[1][2 * ntp],     a1[0], a1[1], a1[2], a1[3], br[0], br[1]);
                    mma_f16(acc[1][2 * ntp + 1], a1[0], a1[1], a1[2], a1[3], br[2], br[3]);
                }
            }
        }
    int px1 = x0 + wid * 16 + g;
#pragma unroll
    for (int r = 0; r < 2; r++) {
        int y = y0 + r;
        __half* o1 = g_h2n + ((size_t)(b * HH + y) * WW + px1) * 64;
        __half* o2 = o1 + 8 * 64;
#pragma unroll
        for (int nt = 0; nt < 8; nt++) {
            int n = nt * 8 + 2 * t;
            float b0 = __ldg(bias + n), b1 = __ldg(bias + n + 1);
            *(__half2*)(o1 + n) = __floats2half2_rn(fmaxf(acc[r][nt][0] + b0, 0.f), fmaxf(acc[r][nt][1] + b1, 0.f));
            *(__half2*)(o2 + n) = __floats2half2_rn(fmaxf(acc[r][nt][2] + b0, 0.f), fmaxf(acc[r][nt][3] + b1, 0.f));
        }
    }
}

// ---------------- conv3: 64->2 mma fp16, smem+ldmatrix, M=32/warp ----------------
__global__ __launch_bounds__(128) void conv3_mma(const float* __restrict__ bias) {
    __shared__ uint4 s_a[4 * 66 * 8];
    __shared__ uint4 s_b3[576];
    int x0 = blockIdx.x * 64, y0 = blockIdx.y * 2, b = blockIdx.z;
    int tid = threadIdx.x, wid = tid >> 5, lane = tid & 31;
    int g = lane >> 2, t = lane & 3;
    for (int idx = tid; idx < 2112; idx += 128) {
        int r = idx / 528, rem = idx % 528, p = rem >> 3, cc = rem & 7;
        int gx = x0 - 1 + p, yy = y0 - 1 + r;
        uint4 v = make_uint4(0, 0, 0, 0);
        if ((unsigned)gx < WW && (unsigned)yy < HH)
            v = *(const uint4*)(g_h2n + ((size_t)(b * HH + yy) * WW + gx) * 64 + cc * 8);
        s_a[(r * 66 + p) * 8 + (cc ^ (p & 7))] = v;
    }
    for (int idx = tid; idx < 576; idx += 128) {
        int tap = idx / 64, rem = idx % 64, co = rem >> 3, cc = rem & 7;
        s_b3[tap * 64 + co * 8 + (cc ^ co)] =
            *(const uint4*)(g_w3t + tap * 512 + co * 64 + cc * 8);
    }
    __syncthreads();
    uint32_t sa = (uint32_t)__cvta_generic_to_shared(s_a);
    uint32_t sb = (uint32_t)__cvta_generic_to_shared(s_b3);
    int lrow = lane & 7, msel = lane >> 3;
    int a_pofs = ((msel & 1) << 3) + lrow;
    int a_hi = msel >> 1;
    int b_hi = (lane >> 3) & 1;
    float acc[2][4];
#pragma unroll
    for (int r = 0; r < 2; r++)
#pragma unroll
        for (int j = 0; j < 4; j++) acc[r][j] = 0.f;
    for (int ky = 0; ky < 3; ky++)
        for (int kx = 0; kx < 3; kx++) {
            int tap = ky * 3 + kx;
            int p = wid * 16 + kx + a_pofs;
            int psw = p & 7;
            int arow0 = (ky * 66 + p) * 8, arow1 = arow0 + 528;
#pragma unroll
            for (int kk = 0; kk < 4; kk++) {
                unsigned a0[4], a1[4];
                int chunk = 2 * kk + a_hi;
                ldsm_x4(a0, sa + (arow0 + (chunk ^ psw)) * 16);
                ldsm_x4(a1, sa + (arow1 + (chunk ^ psw)) * 16);
                unsigned b0, b1;
                int bch = 2 * kk + b_hi;
                ldsm_x2(b0, b1, sb + (tap * 64 + lrow * 8 + (bch ^ lrow)) * 16);
                mma_f16(acc[0], a0[0], a0[1], a0[2], a0[3], b0, b1);
                mma_f16(acc[1], a1[0], a1[1], a1[2], a1[3], b0, b1);
            }
        }
    if (t == 0) {
        float b0 = __ldg(bias + 0), b1 = __ldg(bias + 1);
        int px1 = x0 + wid * 16 + g, px2 = px1 + 8;
#pragma unroll
        for (int r = 0; r < 2; r++) {
            int base = (y0 + r) * WW;
            g_tmp2[(b * 2 + 0) * HW + base + px1] = acc[r][0] + b0;
            g_tmp2[(b * 2 + 1) * HW + base + px1] = acc[r][1] + b1;
            g_tmp2[(b * 2 + 0) * HW + base + px2] = acc[r][2] + b0;
            g_tmp2[(b * 2 + 1) * HW + base + px2] = acc[r][3] + b1;
        }
    }
}

// ---------------- GCN: s^T = (feat @ W1)^T, bf16, coalesced via smem transpose ----------------
__global__ __launch_bounds__(128) void gcn_s_k(const float* __restrict__ in,
                                               const float* __restrict__ W1) {
    __shared__ float w[36 * 64];
    __shared__ __nv_bfloat16 tb[16][136];
    for (int i = threadIdx.x; i < 2304; i += 128) w[i] = W1[i];
    __syncthreads();
    int idx = blockIdx.x * 128 + threadIdx.x;
    int n = idx & 4095, b = (idx >> 12) & 3, c = idx >> 14;
    int n0 = (blockIdx.x * 128) & 4095;
    int gy = n >> 6, gx = n & 63;
    const float* base = in + (b * 2 + c) * HW + (gy * 6) * WW + gx * 6;
    float f[36];
#pragma unroll
    for (int py = 0; py < 6; py++)
#pragma unroll
        for (int px = 0; px < 6; px++) f[py * 6 + px] = __ldg(base + py * WW + px);
    float acc[64];
#pragma unroll
    for (int o = 0; o < 64; o++) acc[o] = 0.f;
#pragma unroll
    for (int ff = 0; ff < 36; ff++) {
        float fv = f[ff];
        const float* wr = &w[ff * 64];
#pragma unroll
        for (int o = 0; o < 64; o++) acc[o] += fv * wr[o];
    }
    int nl = threadIdx.x;
    size_t orow = (size_t)(c * 256 + b * 64);
    for (int ch = 0; ch < 4; ch++) {
        __syncthreads();
#pragma unroll
        for (int o = 0; o < 16; o++) tb[o][nl] = __float2bfloat16(acc[ch * 16 + o]);
        __syncthreads();
        int r = nl >> 3, cw = (nl & 7) * 16;
        const uint4* src = (const uint4*)&tb[r][cw];
        uint4 v0 = src[0], v1 = src[1];
        uint4* dst = (uint4*)(g_st + (orow + ch * 16 + r) * NN + n0 + cw);
        dst[0] = v0; dst[1] = v1;
    }
}

// ---------------- GCN: s3^T = (g @ W3)^T, bf16, coalesced via smem transpose ----------------
__global__ __launch_bounds__(128) void gcn_s3_k(const float* __restrict__ W3) {
    __shared__ float w[64 * 36];
    __shared__ __nv_bfloat16 tb[36][136];
    for (int i = threadIdx.x; i < 2304; i += 128) w[i] = W3[i];
    __syncthreads();
    int idx = blockIdx.x * 128 + threadIdx.x;
    int n = idx & 4095, b = (idx >> 12) & 3, c = idx >> 14;
    int n0 = (blockIdx.x * 128) & 4095;
    const float* gb = g_g + (size_t)(c * NN + n) * 256 + b * 64;
    float acc[36];
#pragma unroll
    for (int o = 0; o < 36; o++) acc[o] = 0.f;
#pragma unroll
    for (int k = 0; k < 64; k += 4) {
        float4 g4 = *(const float4*)(gb + k);
        float gv[4] = {g4.x, g4.y, g4.z, g4.w};
#pragma unroll
        for (int kk = 0; kk < 4; kk++) {
            const float* wr = &w[(k + kk) * 36];
            float gvv = gv[kk];
#pragma unroll
            for (int o = 0; o < 36; o++) acc[o] += gvv * wr[o];
        }
    }
    int nl = threadIdx.x;
#pragma unroll
    for (int o = 0; o < 36; o++) tb[o][nl] = __float2bfloat16(acc[o]);
    __syncthreads();
    size_t orow = (size_t)(c * 144 + b * 36);
    for (int rr = nl; rr < 288; rr += 128) {
        int r = rr >> 3, cw = (rr & 7) * 16;
        const uint4* src = (const uint4*)&tb[r][cw];
        uint4 v0 = src[0], v1 = src[1];
        uint4* dst = (uint4*)(g_s3t + (orow + r) * NN + n0 + cw);
        dst[0] = v0; dst[1] = v1;
    }
}

// ---------------- adj GEMM via bf16 mma, M=32/warp, clamped N tail ----------------
template<int NT>
__global__ __launch_bounds__(128) void gemm_mma(int which, int Nvalid) {
    int c = blockIdx.z;
    const __nv_bfloat16* A = g_adjb + (size_t)c * NN * NN;
    const __nv_bfloat16* Bm; float* C; int Ncols;
    if (which == 0) { Bm = g_st  + (size_t)c * 256 * NN; C = g_g  + (size_t)c * NN * 256; Ncols = 256; }
    else            { Bm = g_s3t + (size_t)c * 144 * NN; C = g_t3 + (size_t)c * NN * 144; Ncols = 144; }
    int n0 = blockIdx.x * (NT * 8);
    int m0 = blockIdx.y * 128;
    int wid = threadIdx.x >> 5, lane = threadIdx.x & 31;
    int g = lane >> 2, t = lane & 3;
    int r1 = m0 + wid * 32 + g;
    const __nv_bfloat16* ar0 = A + (size_t)r1 * NN;
    const __nv_bfloat16* ar1 = ar0 + (size_t)8 * NN;
    const __nv_bfloat16* ar2 = ar0 + (size_t)16 * NN;
    const __nv_bfloat16* ar3 = ar0 + (size_t)24 * NN;
    const __nv_bfloat16* br[NT];
#pragma unroll
    for (int nt = 0; nt < NT; nt++) {
        int nc = n0 + nt * 8 + g;
        br[nt] = Bm + (size_t)(nc < Nvalid ? nc : Nvalid - 1) * NN;
    }
    float acc[2][NT][4];
#pragma unroll
    for (int r = 0; r < 2; r++)
#pragma unroll
        for (int i = 0; i < NT; i++)
#pragma unroll
            for (int j = 0; j < 4; j++) acc[r][i][j] = 0.f;
#pragma unroll 2
    for (int k0 = 0; k0 < NN; k0 += 16) {
        int kb = k0 + 2 * t;
        unsigned a0 = *(const unsigned*)(ar0 + kb);
        unsigned a1 = *(const unsigned*)(ar1 + kb);
        unsigned a2 = *(const unsigned*)(ar0 + kb + 8);
        unsigned a3 = *(const unsigned*)(ar1 + kb + 8);
        unsigned c0 = *(const unsigned*)(ar2 + kb);
        unsigned c1 = *(const unsigned*)(ar3 + kb);
        unsigned c2 = *(const unsigned*)(ar2 + kb + 8);
        unsigned c3 = *(const unsigned*)(ar3 + kb + 8);
#pragma unroll
        for (int nt = 0; nt < NT; nt++) {
            unsigned b0 = *(const unsigned*)(br[nt] + kb);
            unsigned b1 = *(const unsigned*)(br[nt] + kb + 8);
            mma_bf16(acc[0][nt], a0, a1, a2, a3, b0, b1);
            mma_bf16(acc[1][nt], c0, c1, c2, c3, b0, b1);
        }
    }
#pragma unroll
    for (int r = 0; r < 2; r++) {
        int ra = r1 + r * 16, rb = ra + 8;
#pragma unroll
        for (int nt = 0; nt < NT; nt++) {
            if (n0 + nt * 8 >= Nvalid) continue;
            int n = n0 + nt * 8 + 2 * t;
            float v0 = acc[r][nt][0], v1 = acc[r][nt][1], v2 = acc[r][nt][2], v3 = acc[r][nt][3];
            if (which == 0) { v0 = fmaxf(v0, 0.f); v1 = fmaxf(v1, 0.f); v2 = fmaxf(v2, 0.f); v3 = fmaxf(v3, 0.f); }
            *(float2*)(C + (size_t)ra * Ncols + n) = make_float2(v0, v1);
            *(float2*)(C + (size_t)rb * Ncols + n) = make_float2(v2, v3);
        }
    }
}

// ---------------- combine: out = in + (1-arf)*tmp2 + arf*tmp3 ----------------
__global__ __launch_bounds__(256) void combine_k(const float* __restrict__ in,
                                                 const float* __restrict__ arf) {
    int g = blockIdx.x * 256 + threadIdx.x;
    int p = g % HW, b = g / HW;
    int x = p % WW, y = p / WW;
    float a = __ldg(arf);
    int gy = y / 6, py = y - gy * 6, gx = x / 6, px = x - gx * 6;
    int n = gy * 64 + gx, f = py * 6 + px;
#pragma unroll
    for (int c = 0; c < 2; c++) {
        float t3v = g_t3[(size_t)(c * NN + n) * 144 + b * 36 + f];
        int li = (b * 2 + c) * HW + p;
        g_oimg[li] = in[li] + (1.f - a) * g_tmp2[li] + a * t3v;
    }
}

__device__ __forceinline__ float2 cadd(float2 a, float2 b) { return make_float2(a.x + b.x, a.y + b.y); }
__device__ __forceinline__ float2 csub(float2 a, float2 b) { return make_float2(a.x - b.x, a.y - b.y); }

// ---------------- fwd row FFT; fused z=(-1)^(x+y)*oimg*csm at load ----------------
__global__ __launch_bounds__(192) void fft_row_fwd_k(const float* __restrict__ csr,
                                                     const float* __restrict__ csi) {
    __shared__ float2 sb[384];
    int line = blockIdx.x;
    float2* base = g_k + (size_t)line * 384;
    int tid = threadIdx.x;
    {
        int img = line / HH, y = line % HH;
        int b = img & 3, c = img >> 2;
        const float* o0 = g_oimg + (size_t)(b * 2 + 0) * HW + y * WW;
        const float* o1 = g_oimg + (size_t)(b * 2 + 1) * HW + y * WW;
        const float* cr = csr + (size_t)(b * CCH + c) * HW + y * WW;
        const float* ci = csi + (size_t)(b * CCH + c) * HW + y * WW;
        for (int i = tid; i < 384; i += 192) {
            float orr = o0[i], oii = o1[i];
            float crv = __ldg(cr + i), civ = __ldg(ci + i);
            float sgn = ((i + y) & 1) ? -1.f : 1.f;
            float2 z = make_float2(sgn * (orr * crv - oii * civ), sgn * (orr * civ + oii * crv));
            int r = i % 3, q = i / 3;
            sb[r * 128 + q] = z;
        }
    }
    __syncthreads();
    int r = tid >> 6, bf = tid & 63, off = r << 7;
#pragma unroll
    for (int len = 128; len >= 2; len >>= 1) {
        int h = len >> 1;
        int grp = bf / h, t = bf - grp * h;
        int i1 = off + grp * len + t;
        float2 u = sb[i1], v = sb[i1 + h];
        sb[i1] = cadd(u, v);
        float2 d = csub(u, v);
        float2 w = g_tw128[t * (128 / len)];
        sb[i1 + h] = make_float2(d.x * w.x - d.y * w.y, d.x * w.y + d.y * w.x);
        __syncthreads();
    }
    for (int k = tid; k < 384; k += 192) {
        int k0 = k & 127;
        int rv = __brev((unsigned)k0) >> 25;
        float2 y0 = sb[rv], y1 = sb[128 + rv], y2 = sb[256 + rv];
        float2 c1 = g_tw384[k], c2 = g_tw384[(2 * k) % 384];
        float xr = y0.x + c1.x * y1.x - c1.y * y1.y + c2.x * y2.x - c2.y * y2.y;
        float xi = y0.y + c1.x * y1.y + c1.y * y1.x + c2.x * y2.y + c2.y * y2.x;
        base[k] = make_float2(xr, xi);
    }
}

// ---------------- FUSED column pass: fwd FFT -> DC -> inverse FFT ----------------
// grid 48*48, 192 thr, 8 columns per block; one g_k round trip total.
__global__ __launch_bounds__(192) void fft_col_fused_k(const int* __restrict__ mask,
                                                       const float* __restrict__ tkr,
                                                       const float* __restrict__ tki) {
    __shared__ float2 sb[8 * 384];
    int img = blockIdx.x / 48, cg = blockIdx.x % 48;
    float2* base = g_k + (size_t)img * HW + cg * 8;
    int tid = threadIdx.x;
    // load (y natural order -> fwd decomposition layout)
    for (int i = tid; i < 3072; i += 192) {
        int col = i & 7, yy = i >> 3;
        float2 Z = base[(size_t)yy * 384 + col];
        sb[col * 384 + (yy % 3) * 128 + yy / 3] = Z;
    }
    __syncthreads();
    // forward butterflies
#pragma unroll
    for (int len = 128; len >= 2; len >>= 1) {
        int h = len >> 1;
        for (int widx = tid; widx < 1536; widx += 192) {
            int seg = widx >> 6, bf = widx & 63;
            int boff = (seg / 3) * 384 + (seg % 3) * 128;
            int grp = bf / h, t = bf - grp * h;
            int i1 = boff + grp * len + t;
            float2 u = sb[i1], v = sb[i1 + h];
            sb[i1] = cadd(u, v);
            float2 d = csub(u, v);
            float2 w = g_tw128[t * (128 / len)];
            sb[i1 + h] = make_float2(d.x * w.x - d.y * w.y, d.x * w.y + d.y * w.x);
        }
        __syncthreads();
    }
    // radix-3 combine -> X[k], apply data consistency; hold in registers
    float2 val[16];
    for (int ii = 0; ii < 16; ii++) {
        int i = tid + ii * 192;
        int col = i & 7, k = i >> 3;
        int k0 = k & 127;
        int rv = __brev((unsigned)k0) >> 25;
        int cb = col * 384;
        float2 y0 = sb[cb + rv], y1 = sb[cb + 128 + rv], y2 = sb[cb + 256 + rv];
        float2 c1 = g_tw384[k], c2 = g_tw384[(2 * k) % 384];
        float xr = y0.x + c1.x * y1.x - c1.y * y1.y + c2.x * y2.x - c2.y * y2.y;
        float xi = y0.y + c1.x * y1.y + c1.y * y1.x + c2.x * y2.y + c2.y * y2.x;
        int gx = cg * 8 + col;
        int p = k * 384 + gx;
        float mv = (float)__ldg(mask + p);
        float sgn = ((gx + k) & 1) ? -1.f : 1.f;
        float coef = 384.f * 0.999999f * mv * sgn;
        float om = 1.f - mv;
        size_t gidx = (size_t)img * HW + p;
        val[ii] = make_float2(om * xr + coef * __ldg(tkr + gidx),
                              om * xi + coef * __ldg(tki + gidx));
    }
    __syncthreads();
    // redeposit X[k] in inverse decomposition layout
    for (int ii = 0; ii < 16; ii++) {
        int i = tid + ii * 192;
        int col = i & 7, k = i >> 3;
        sb[col * 384 + (k % 3) * 128 + k / 3] = val[ii];
    }
    __syncthreads();
    // inverse butterflies (conjugated twiddles)
#pragma unroll
    for (int len = 128; len >= 2; len >>= 1) {
        int h = len >> 1;
        for (int widx = tid; widx < 1536; widx += 192) {
            int seg = widx >> 6, bf = widx & 63;
            int boff = (seg / 3) * 384 + (seg % 3) * 128;
            int grp = bf / h, t = bf - grp * h;
            int i1 = boff + grp * len + t;
            float2 u = sb[i1], v = sb[i1 + h];
            sb[i1] = cadd(u, v);
            float2 d = csub(u, v);
            float2 w = g_tw128[t * (128 / len)];
            sb[i1 + h] = make_float2(d.x * w.x + d.y * w.y, -d.x * w.y + d.y * w.x);
        }
        __syncthreads();
    }
    // inverse radix-3 combine + 1/384 scale, store (y natural)
    for (int i = tid; i < 3072; i += 192) {
        int col = i & 7, k = i >> 3;
        int k0 = k & 127;
        int rv = __brev((unsigned)k0) >> 25;
        int cb = col * 384;
        float2 y0 = sb[cb + rv], y1 = sb[cb + 128 + rv], y2 = sb[cb + 256 + rv];
        float2 c1 = g_tw384[k], c2 = g_tw384[(2 * k) % 384];
        float s1 = -c1.y, s2 = -c2.y;
        float xr = (y0.x + c1.x * y1.x - s1 * y1.y + c2.x * y2.x - s2 * y2.y) * (1.f / 384.f);
        float xi = (y0.y + c1.x * y1.y + s1 * y1.x + c2.x * y2.y + s2 * y2.x) * (1.f / 384.f);
        base[(size_t)k * 384 + col] = make_float2(xr, xi);
    }
}

// ---------------- fused inverse row FFT (12 coils) + coil combine ----------------
__global__ __launch_bounds__(384) void invrow_final_k(const float* __restrict__ csr,
                                                      const float* __restrict__ csi,
                                                      float* __restrict__ out) {
    __shared__ float2 sb[12][384];
    int y = blockIdx.x % HH, b = blockIdx.x / HH;
    int tid = threadIdx.x;
    int r0 = tid % 3, q0 = tid / 3;
#pragma unroll
    for (int c = 0; c < CCH; c++) {
        float2 z = g_k[((size_t)(c * BSZ + b)) * HW + (size_t)y * 384 + tid];
        sb[c][r0 * 128 + q0] = z;
    }
    __syncthreads();
#pragma unroll
    for (int len = 128; len >= 2; len >>= 1) {
        int h = len >> 1;
        for (int widx = tid; widx < 2304; widx += 384) {
            int line = widx / 192, bf = widx % 192;
            int seg = bf >> 6, b6 = bf & 63;
            int grp = b6 / h, t = b6 - grp * h;
            int i1 = seg * 128 + grp * len + t;
            float2 u = sb[line][i1], v = sb[line][i1 + h];
            sb[line][i1] = cadd(u, v);
            float2 d = csub(u, v);
            float2 w = g_tw128[t * (128 / len)];
            sb[line][i1 + h] = make_float2(d.x * w.x + d.y * w.y, -d.x * w.y + d.y * w.x);
        }
        __syncthreads();
    }
    int k = tid;
    int k0 = k & 127;
    int rv = __brev((unsigned)k0) >> 25;
    float2 c1 = g_tw384[k], c2 = g_tw384[(2 * k) % 384];
    float s1 = -c1.y, s2 = -c2.y;
    float rr = 0.f, ri = 0.f;
    const float* crb = csr + (size_t)b * CCH * HW + (size_t)y * WW + k;
    const float* cib = csi + (size_t)b * CCH * HW + (size_t)y * WW + k;
#pragma unroll
    for (int c = 0; c < CCH; c++) {
        float2 y0 = sb[c][rv], y1 = sb[c][128 + rv], y2 = sb[c][256 + rv];
        float xr = (y0.x + c1.x * y1.x - s1 * y1.y + c2.x * y2.x - s2 * y2.y) * (1.f / 384.f);
        float xi = (y0.y + c1.x * y1.y + s1 * y1.x + c2.x * y2.y + s2 * y2.x) * (1.f / 384.f);
        float cr = __ldg(crb + (size_t)c * HW);
        float ci = __ldg(cib + (size_t)c * HW);
        rr += xr * cr + xi * ci;
        ri += xi * cr - xr * ci;
    }
    float sgn = ((k + y) & 1) ? -1.f : 1.f;
    out[(size_t)(b * 2 + 0) * HW + (size_t)y * WW + k] = sgn * rr;
    out[(size_t)(b * 2 + 1) * HW + (size_t)y * WW + k] = sgn * ri;
}

// ---------------- launch ----------------
extern "C" void kernel_launch(void* const* d_in, const int* in_sizes, int n_in,
                              void* d_out, int out_size) {
    (void)in_sizes; (void)n_in; (void)out_size;
    const float* input = (const float*)d_in[0];
    const float* adj   = (const float*)d_in[1];
    const int*   mask  = (const int*)  d_in[2];
    const float* csr   = (const float*)d_in[3];
    const float* csi   = (const float*)d_in[4];
    const float* tkr   = (const float*)d_in[5];
    const float* tki   = (const float*)d_in[6];
    const float* W1    = (const float*)d_in[7];
    const float* W3    = (const float*)d_in[8];
    const float* arf   = (const float*)d_in[9];
    const float* cw1   = (const float*)d_in[10];
    const float* cb1   = (const float*)d_in[11];
    const float* cw2   = (const float*)d_in[12];
    const float* cb2   = (const float*)d_in[13];
    const float* cw3   = (const float*)d_in[14];
    const float* cb3   = (const float*)d_in[15];
    float* out = (float*)d_out;

    const int CONV2_SMEM = (4608 + 2112) * 16;   // 107520 B
    cudaFuncSetAttribute(conv2_mma, cudaFuncAttributeMaxDynamicSharedMemorySize, CONV2_SMEM);

    // Order chosen so gemm_mma<8>(which=0) is launch index 3 (the ncu-captured slot).
    prep_w_k<<<144, 256>>>(cw2, cw3);                        // 0
    gcn_s_k<<<256, 128>>>(input, W1);                        // 1
    adj_cvt_k<<<32768, 256>>>(adj);                          // 2
    gemm_mma<8><<<dim3(4, 32, 2), 128>>>(0, 256);            // 3  <-- profiled
    conv1_k<<<4608, 256>>>(input, cw1, cb1);                 // 4
    conv2_mma<<<dim3(6, 192, 4), 128, CONV2_SMEM>>>(cb2);    // 5
    conv3_mma<<<dim3(6, 192, 4), 128>>>(cb3);                // 6
    gcn_s3_k<<<256, 128>>>(W3);                              // 7
    gemm_mma<8><<<dim3(3, 32, 2), 128>>>(1, 144);            // 8

    // combine + FFT chain
    combine_k<<<2304, 256>>>(input, arf);
    init_tw_k<<<1, 384>>>();
    fft_row_fwd_k<<<48 * 384, 192>>>(csr, csi);
    fft_col_fused_k<<<48 * 48, 192>>>(mask, tkr, tki);
    invrow_final_k<<<4 * 384, 384>>>(csr, csi, out);
}

// round 10
// speedup vs baseline: 1.2948x; 1.2948x over previous
#include <cuda_runtime.h>
#include <cuda_fp16.h>
#include <cuda_bf16.h>
#include <math.h>
#include <stdint.h>
#include <stddef.h>

#define BSZ 4
#define CCH 12
#define HH 384
#define WW 384
#define HW (HH*WW)
#define NN 4096

// ---------------- static device scratch (no allocs allowed) ----------------
__device__ __half         g_h1n[(size_t)BSZ*HW*64];   // conv1 out, NHWC fp16
__device__ __half         g_h2n[(size_t)BSZ*HW*64];   // conv2 out, NHWC fp16
__device__ __nv_bfloat16  g_adjb[(size_t)2*NN*NN];    // adj bf16
__device__ __half         g_w2t[9*64*64];             // conv2 w [tap][co][ci]
__device__ __half         g_w3t[9*8*64];              // conv3 w [tap][o pad8][ci]
__device__ __nv_bfloat16  g_st [(size_t)2*256*NN];    // s^T  [c][b*64+o][m]
__device__ __nv_bfloat16  g_s3t[(size_t)2*144*NN];    // s3^T [c][b*36+o][m]
__device__ float          g_g  [(size_t)2*NN*256];    // relu(adj@s) [c][m][256]
__device__ float          g_t3 [(size_t)2*NN*144];    // adj@s3 [c][m][144]
__device__ float          g_tmp2[BSZ*2*HW];
__device__ float          g_oimg[BSZ*2*HW];
__device__ float2         g_k[(size_t)CCH*BSZ*HW];
__device__ float2         g_tw128[64];
__device__ float2         g_tw384[384];

// ---------------- mma / ldmatrix / cp.async wrappers ----------------
__device__ __forceinline__ void mma_f16(float c[4], unsigned a0, unsigned a1,
                                        unsigned a2, unsigned a3,
                                        unsigned b0, unsigned b1) {
    asm volatile("mma.sync.aligned.m16n8k16.row.col.f32.f16.f16.f32 "
        "{%0,%1,%2,%3}, {%4,%5,%6,%7}, {%8,%9}, {%0,%1,%2,%3};"
        : "+f"(c[0]), "+f"(c[1]), "+f"(c[2]), "+f"(c[3])
        : "r"(a0), "r"(a1), "r"(a2), "r"(a3), "r"(b0), "r"(b1));
}
__device__ __forceinline__ void mma_bf16(float c[4], unsigned a0, unsigned a1,
                                         unsigned a2, unsigned a3,
                                         unsigned b0, unsigned b1) {
    asm volatile("mma.sync.aligned.m16n8k16.row.col.f32.bf16.bf16.f32 "
        "{%0,%1,%2,%3}, {%4,%5,%6,%7}, {%8,%9}, {%0,%1,%2,%3};"
        : "+f"(c[0]), "+f"(c[1]), "+f"(c[2]), "+f"(c[3])
        : "r"(a0), "r"(a1), "r"(a2), "r"(a3), "r"(b0), "r"(b1));
}
__device__ __forceinline__ void ldsm_x4(unsigned r[4], uint32_t a) {
    asm volatile("ldmatrix.sync.aligned.m8n8.x4.shared.b16 {%0,%1,%2,%3}, [%4];"
        : "=r"(r[0]), "=r"(r[1]), "=r"(r[2]), "=r"(r[3]) : "r"(a));
}
__device__ __forceinline__ void ldsm_x2(unsigned& r0, unsigned& r1, uint32_t a) {
    asm volatile("ldmatrix.sync.aligned.m8n8.x2.shared.b16 {%0,%1}, [%2];"
        : "=r"(r0), "=r"(r1) : "r"(a));
}
#define CP_ASYNC16(dst, src) \
    asm volatile("cp.async.cg.shared.global [%0], [%1], 16;" :: "r"(dst), "l"(src))
#define CP_COMMIT()  asm volatile("cp.async.commit_group;")
#define CP_WAIT0()   asm volatile("cp.async.wait_group 0;")

// ---------------- init ----------------
__global__ void init_tw_k() {
    int t = threadIdx.x;
    if (t < 64) { float s, c; sincospif(-(float)t / 64.f, &s, &c);  g_tw128[t] = make_float2(c, s); }
    {            float s, c; sincospif(-(float)t / 192.f, &s, &c); g_tw384[t] = make_float2(c, s); }
}
__global__ void prep_w_k(const float* __restrict__ cw2, const float* __restrict__ cw3) {
    int i = blockIdx.x * 256 + threadIdx.x;
    if (i < 9 * 64 * 64) {
        int tap = i / 4096, r = i % 4096, co = r >> 6, ci = r & 63;
        g_w2t[i] = __float2half(cw2[(co * 64 + ci) * 9 + tap]);
    }
    if (i < 9 * 8 * 64) {
        int tap = i / 512, r = i % 512, o = r >> 6, ci = r & 63;
        g_w3t[i] = __float2half((o < 2) ? cw3[(o * 64 + ci) * 9 + tap] : 0.f);
    }
}
__global__ __launch_bounds__(256) void adj_cvt_k(const float* __restrict__ adj) {
    size_t i = ((size_t)blockIdx.x * 256 + threadIdx.x) * 4;
    float4 v = *(const float4*)(adj + i);
    __nv_bfloat162* o = (__nv_bfloat162*)(g_adjb + i);
    o[0] = __floats2bfloat162_rn(v.x, v.y);
    o[1] = __floats2bfloat162_rn(v.z, v.w);
}

// ---------------- conv1: 2 -> 64, relu; 4 px x 8 ch per thread ----------------
__global__ __launch_bounds__(256) void conv1_k(const float* __restrict__ in,
                                               const float* __restrict__ w,
                                               const float* __restrict__ bias) {
    __shared__ float ws[18 * 64];
    for (int i = threadIdx.x; i < 1152; i += 256) {
        int co = i / 18, q = i % 18;
        ws[q * 64 + co] = w[i];
    }
    __syncthreads();
    int tid = threadIdx.x;
    int cog = tid & 7;
    int pq  = tid >> 3;
    int chunk = blockIdx.x % 3;
    int rowid = blockIdx.x / 3;
    int y = rowid % HH, b = rowid / HH;
    int px0 = chunk * 128 + pq * 4;
    float iv[2][3][6];
#pragma unroll
    for (int ci = 0; ci < 2; ci++) {
        const float* base = in + (b * 2 + ci) * HW;
#pragma unroll
        for (int ry = 0; ry < 3; ry++) {
            int yy = y + ry - 1; bool yok = (unsigned)yy < HH;
#pragma unroll
            for (int cx = 0; cx < 6; cx++) {
                int xx = px0 + cx - 1;
                iv[ci][ry][cx] = (yok && (unsigned)xx < WW) ? __ldg(base + yy * WW + xx) : 0.f;
            }
        }
    }
    float acc[4][8];
    float bz[8];
#pragma unroll
    for (int j = 0; j < 8; j++) bz[j] = __ldg(bias + cog * 8 + j);
#pragma unroll
    for (int px = 0; px < 4; px++)
#pragma unroll
        for (int j = 0; j < 8; j++) acc[px][j] = bz[j];
#pragma unroll
    for (int ci = 0; ci < 2; ci++)
#pragma unroll
        for (int ky = 0; ky < 3; ky++)
#pragma unroll
            for (int kx = 0; kx < 3; kx++) {
                int q = ci * 9 + ky * 3 + kx;
                const float4* wp = (const float4*)&ws[q * 64 + cog * 8];
                float4 wa = wp[0], wb = wp[1];
                float w8[8] = {wa.x, wa.y, wa.z, wa.w, wb.x, wb.y, wb.z, wb.w};
#pragma unroll
                for (int px = 0; px < 4; px++) {
                    float v = iv[ci][ky][kx + px];
#pragma unroll
                    for (int j = 0; j < 8; j++) acc[px][j] += v * w8[j];
                }
            }
#pragma unroll
    for (int px = 0; px < 4; px++) {
        size_t p = (size_t)b * HW + (size_t)y * WW + (px0 + px);
        __half2 h4[4];
#pragma unroll
        for (int j = 0; j < 8; j += 2)
            h4[j >> 1] = __floats2half2_rn(fmaxf(acc[px][j], 0.f), fmaxf(acc[px][j + 1], 0.f));
        *(uint4*)(g_h1n + p * 64 + cog * 8) = *(const uint4*)h4;
    }
}

// ---------------- conv2 (R7 version): per-tap B staging, 42KB static smem ----------------
__global__ __launch_bounds__(128) void conv2_mma(const float* __restrict__ bias) {
    __shared__ uint4 s_a[4 * 66 * 8];
    __shared__ uint4 s_b[512];
    int x0 = blockIdx.x * 64, y0 = blockIdx.y * 2, b = blockIdx.z;
    int tid = threadIdx.x, wid = tid >> 5, lane = tid & 31;
    int g = lane >> 2, t = lane & 3;
    for (int idx = tid; idx < 2112; idx += 128) {
        int r = idx / 528, rem = idx % 528, p = rem >> 3, cc = rem & 7;
        int gx = x0 - 1 + p, yy = y0 - 1 + r;
        uint4 v = make_uint4(0, 0, 0, 0);
        if ((unsigned)gx < WW && (unsigned)yy < HH)
            v = *(const uint4*)(g_h1n + ((size_t)(b * HH + yy) * WW + gx) * 64 + cc * 8);
        s_a[(r * 66 + p) * 8 + (cc ^ (p & 7))] = v;
    }
    uint32_t sa = (uint32_t)__cvta_generic_to_shared(s_a);
    uint32_t sb = (uint32_t)__cvta_generic_to_shared(s_b);
    int lrow = lane & 7, msel = lane >> 3;
    int a_pofs = ((msel & 1) << 3) + lrow;
    int a_hi = msel >> 1;
    int b_hi = (lane >> 3) & 1;
    float acc[2][8][4];
#pragma unroll
    for (int r = 0; r < 2; r++)
#pragma unroll
        for (int i = 0; i < 8; i++)
#pragma unroll
            for (int j = 0; j < 4; j++) acc[r][i][j] = 0.f;

    for (int ky = 0; ky < 3; ky++)
        for (int kx = 0; kx < 3; kx++) {
            int tap = ky * 3 + kx;
            __syncthreads();
            for (int idx = tid; idx < 512; idx += 128) {
                int co = idx >> 3, cc = idx & 7;
                s_b[co * 8 + (cc ^ (co & 7))] =
                    *(const uint4*)(g_w2t + tap * 4096 + co * 64 + cc * 8);
            }
            __syncthreads();
            int p = wid * 16 + kx + a_pofs;
            int psw = p & 7;
            int arow0 = (ky * 66 + p) * 8, arow1 = arow0 + 528;
#pragma unroll
            for (int kk = 0; kk < 4; kk++) {
                unsigned a0[4], a1[4];
                int chunk = 2 * kk + a_hi;
                ldsm_x4(a0, sa + (arow0 + (chunk ^ psw)) * 16);
                ldsm_x4(a1, sa + (arow1 + (chunk ^ psw)) * 16);
                int bch = 2 * kk + b_hi;
#pragma unroll
                for (int nt = 0; nt < 8; nt++) {
                    unsigned b0, b1;
                    ldsm_x2(b0, b1, sb + (nt * 64 + lrow * 8 + (bch ^ lrow)) * 16);
                    mma_f16(acc[0][nt], a0[0], a0[1], a0[2], a0[3], b0, b1);
                    mma_f16(acc[1][nt], a1[0], a1[1], a1[2], a1[3], b0, b1);
                }
            }
        }
    int px1 = x0 + wid * 16 + g;
#pragma unroll
    for (int r = 0; r < 2; r++) {
        int y = y0 + r;
        __half* o1 = g_h2n + ((size_t)(b * HH + y) * WW + px1) * 64;
        __half* o2 = o1 + 8 * 64;
#pragma unroll
        for (int nt = 0; nt < 8; nt++) {
            int n = nt * 8 + 2 * t;
            float b0 = __ldg(bias + n), b1 = __ldg(bias + n + 1);
            *(__half2*)(o1 + n) = __floats2half2_rn(fmaxf(acc[r][nt][0] + b0, 0.f), fmaxf(acc[r][nt][1] + b1, 0.f));
            *(__half2*)(o2 + n) = __floats2half2_rn(fmaxf(acc[r][nt][2] + b0, 0.f), fmaxf(acc[r][nt][3] + b1, 0.f));
        }
    }
}

// ---------------- conv3: 64->2 mma fp16, smem+ldmatrix, M=32/warp ----------------
__global__ __launch_bounds__(128) void conv3_mma(const float* __restrict__ bias) {
    __shared__ uint4 s_a[4 * 66 * 8];
    __shared__ uint4 s_b3[576];
    int x0 = blockIdx.x * 64, y0 = blockIdx.y * 2, b = blockIdx.z;
    int tid = threadIdx.x, wid = tid >> 5, lane = tid & 31;
    int g = lane >> 2, t = lane & 3;
    for (int idx = tid; idx < 2112; idx += 128) {
        int r = idx / 528, rem = idx % 528, p = rem >> 3, cc = rem & 7;
        int gx = x0 - 1 + p, yy = y0 - 1 + r;
        uint4 v = make_uint4(0, 0, 0, 0);
        if ((unsigned)gx < WW && (unsigned)yy < HH)
            v = *(const uint4*)(g_h2n + ((size_t)(b * HH + yy) * WW + gx) * 64 + cc * 8);
        s_a[(r * 66 + p) * 8 + (cc ^ (p & 7))] = v;
    }
    for (int idx = tid; idx < 576; idx += 128) {
        int tap = idx / 64, rem = idx % 64, co = rem >> 3, cc = rem & 7;
        s_b3[tap * 64 + co * 8 + (cc ^ co)] =
            *(const uint4*)(g_w3t + tap * 512 + co * 64 + cc * 8);
    }
    __syncthreads();
    uint32_t sa = (uint32_t)__cvta_generic_to_shared(s_a);
    uint32_t sb = (uint32_t)__cvta_generic_to_shared(s_b3);
    int lrow = lane & 7, msel = lane >> 3;
    int a_pofs = ((msel & 1) << 3) + lrow;
    int a_hi = msel >> 1;
    int b_hi = (lane >> 3) & 1;
    float acc[2][4];
#pragma unroll
    for (int r = 0; r < 2; r++)
#pragma unroll
        for (int j = 0; j < 4; j++) acc[r][j] = 0.f;
    for (int ky = 0; ky < 3; ky++)
        for (int kx = 0; kx < 3; kx++) {
            int tap = ky * 3 + kx;
            int p = wid * 16 + kx + a_pofs;
            int psw = p & 7;
            int arow0 = (ky * 66 + p) * 8, arow1 = arow0 + 528;
#pragma unroll
            for (int kk = 0; kk < 4; kk++) {
                unsigned a0[4], a1[4];
                int chunk = 2 * kk + a_hi;
                ldsm_x4(a0, sa + (arow0 + (chunk ^ psw)) * 16);
                ldsm_x4(a1, sa + (arow1 + (chunk ^ psw)) * 16);
                unsigned b0, b1;
                int bch = 2 * kk + b_hi;
                ldsm_x2(b0, b1, sb + (tap * 64 + lrow * 8 + (bch ^ lrow)) * 16);
                mma_f16(acc[0], a0[0], a0[1], a0[2], a0[3], b0, b1);
                mma_f16(acc[1], a1[0], a1[1], a1[2], a1[3], b0, b1);
            }
        }
    if (t == 0) {
        float b0 = __ldg(bias + 0), b1 = __ldg(bias + 1);
        int px1 = x0 + wid * 16 + g, px2 = px1 + 8;
#pragma unroll
        for (int r = 0; r < 2; r++) {
            int base = (y0 + r) * WW;
            g_tmp2[(b * 2 + 0) * HW + base + px1] = acc[r][0] + b0;
            g_tmp2[(b * 2 + 1) * HW + base + px1] = acc[r][1] + b1;
            g_tmp2[(b * 2 + 0) * HW + base + px2] = acc[r][2] + b0;
            g_tmp2[(b * 2 + 1) * HW + base + px2] = acc[r][3] + b1;
        }
    }
}

// ---------------- GCN: s^T = (feat @ W1)^T, bf16, coalesced via smem transpose ----------------
__global__ __launch_bounds__(128) void gcn_s_k(const float* __restrict__ in,
                                               const float* __restrict__ W1) {
    __shared__ float w[36 * 64];
    __shared__ __nv_bfloat16 tb[16][136];
    for (int i = threadIdx.x; i < 2304; i += 128) w[i] = W1[i];
    __syncthreads();
    int idx = blockIdx.x * 128 + threadIdx.x;
    int n = idx & 4095, b = (idx >> 12) & 3, c = idx >> 14;
    int n0 = (blockIdx.x * 128) & 4095;
    int gy = n >> 6, gx = n & 63;
    const float* base = in + (b * 2 + c) * HW + (gy * 6) * WW + gx * 6;
    float f[36];
#pragma unroll
    for (int py = 0; py < 6; py++)
#pragma unroll
        for (int px = 0; px < 6; px++) f[py * 6 + px] = __ldg(base + py * WW + px);
    float acc[64];
#pragma unroll
    for (int o = 0; o < 64; o++) acc[o] = 0.f;
#pragma unroll
    for (int ff = 0; ff < 36; ff++) {
        float fv = f[ff];
        const float* wr = &w[ff * 64];
#pragma unroll
        for (int o = 0; o < 64; o++) acc[o] += fv * wr[o];
    }
    int nl = threadIdx.x;
    size_t orow = (size_t)(c * 256 + b * 64);
    for (int ch = 0; ch < 4; ch++) {
        __syncthreads();
#pragma unroll
        for (int o = 0; o < 16; o++) tb[o][nl] = __float2bfloat16(acc[ch * 16 + o]);
        __syncthreads();
        int r = nl >> 3, cw = (nl & 7) * 16;
        const uint4* src = (const uint4*)&tb[r][cw];
        uint4 v0 = src[0], v1 = src[1];
        uint4* dst = (uint4*)(g_st + (orow + ch * 16 + r) * NN + n0 + cw);
        dst[0] = v0; dst[1] = v1;
    }
}

// ---------------- GCN: s3^T = (g @ W3)^T, bf16, coalesced via smem transpose ----------------
__global__ __launch_bounds__(128) void gcn_s3_k(const float* __restrict__ W3) {
    __shared__ float w[64 * 36];
    __shared__ __nv_bfloat16 tb[36][136];
    for (int i = threadIdx.x; i < 2304; i += 128) w[i] = W3[i];
    __syncthreads();
    int idx = blockIdx.x * 128 + threadIdx.x;
    int n = idx & 4095, b = (idx >> 12) & 3, c = idx >> 14;
    int n0 = (blockIdx.x * 128) & 4095;
    const float* gb = g_g + (size_t)(c * NN + n) * 256 + b * 64;
    float acc[36];
#pragma unroll
    for (int o = 0; o < 36; o++) acc[o] = 0.f;
#pragma unroll
    for (int k = 0; k < 64; k += 4) {
        float4 g4 = *(const float4*)(gb + k);
        float gv[4] = {g4.x, g4.y, g4.z, g4.w};
#pragma unroll
        for (int kk = 0; kk < 4; kk++) {
            const float* wr = &w[(k + kk) * 36];
            float gvv = gv[kk];
#pragma unroll
            for (int o = 0; o < 36; o++) acc[o] += gvv * wr[o];
        }
    }
    int nl = threadIdx.x;
#pragma unroll
    for (int o = 0; o < 36; o++) tb[o][nl] = __float2bfloat16(acc[o]);
    __syncthreads();
    size_t orow = (size_t)(c * 144 + b * 36);
    for (int rr = nl; rr < 288; rr += 128) {
        int r = rr >> 3, cw = (rr & 7) * 16;
        const uint4* src = (const uint4*)&tb[r][cw];
        uint4 v0 = src[0], v1 = src[1];
        uint4* dst = (uint4*)(g_s3t + (orow + r) * NN + n0 + cw);
        dst[0] = v0; dst[1] = v1;
    }
}

// ---------------- adj GEMM: cp.async double-buffered smem pipeline ----------------
// 256 thr = 8 warps (4M x 2N); block tile M=128, N=64, K=32/stage.
__global__ __launch_bounds__(256) void gemm2_k(int which, int Nvalid) {
    __shared__ uint4 sA[2][512];   // [buf][r(128) * 4 chunks swz]  8KB/stage
    __shared__ uint4 sB[2][256];   // [buf][n(64)  * 4 chunks swz]  4KB/stage
    int c = blockIdx.z;
    const __nv_bfloat16* A = g_adjb + (size_t)c * NN * NN;
    const __nv_bfloat16* Bm; float* C; int Ncols;
    if (which == 0) { Bm = g_st  + (size_t)c * 256 * NN; C = g_g  + (size_t)c * NN * 256; Ncols = 256; }
    else            { Bm = g_s3t + (size_t)c * 144 * NN; C = g_t3 + (size_t)c * NN * 144; Ncols = 144; }
    int n0 = blockIdx.x * 64, m0 = blockIdx.y * 128;
    int tid = threadIdx.x, wid = tid >> 5, lane = tid & 31;
    int g = lane >> 2, t = lane & 3;
    int wm = (wid >> 1) * 32, wn = (wid & 1) * 32;
    uint32_t sab = (uint32_t)__cvta_generic_to_shared(sA);
    uint32_t sbb = (uint32_t)__cvta_generic_to_shared(sB);

    // fragment smem addressing (precomputed)
    int arow[2], aswz[2];
#pragma unroll
    for (int f = 0; f < 2; f++) {
        arow[f] = wm + f * 16 + (lane & 7) + ((lane >> 3) & 1) * 8;
        aswz[f] = (arow[f] >> 1) & 3;
    }
    int akc = (lane >> 4) & 1;
    int brow[2], bswz[2];
#pragma unroll
    for (int p = 0; p < 2; p++) {
        brow[p] = wn + p * 16 + (lane & 7) + ((lane >> 4) << 3);
        bswz[p] = (brow[p] >> 1) & 3;
    }
    int bkc = (lane >> 3) & 1;

    float acc[2][4][4];
#pragma unroll
    for (int f = 0; f < 2; f++)
#pragma unroll
        for (int p = 0; p < 4; p++)
#pragma unroll
            for (int j = 0; j < 4; j++) acc[f][p][j] = 0.f;

    auto stage = [&](int buf, int k0) {
#pragma unroll
        for (int idx = tid; idx < 768; idx += 256) {
            if (idx < 512) {
                int r = idx >> 2, cc = idx & 3;
                uint32_t dst = sab + (buf * 512 + r * 4 + (cc ^ ((r >> 1) & 3))) * 16;
                CP_ASYNC16(dst, A + (size_t)(m0 + r) * NN + k0 + cc * 8);
            } else {
                int j = idx - 512;
                int r = j >> 2, cc = j & 3;
                int row = n0 + r; if (row >= Nvalid) row = Nvalid - 1;
                uint32_t dst = sbb + (buf * 256 + r * 4 + (cc ^ ((r >> 1) & 3))) * 16;
                CP_ASYNC16(dst, Bm + (size_t)row * NN + k0 + cc * 8);
            }
        }
        CP_COMMIT();
    };

    stage(0, 0);
    const int NIT = NN / 32;   // 128
    for (int i = 0; i < NIT; i++) {
        CP_WAIT0();
        __syncthreads();
        if (i + 1 < NIT) stage((i + 1) & 1, (i + 1) * 32);
        int buf = i & 1;
        uint32_t sa0 = sab + buf * 512 * 16;
        uint32_t sb0 = sbb + buf * 256 * 16;
#pragma unroll
        for (int s = 0; s < 2; s++) {
            unsigned a[2][4];
#pragma unroll
            for (int f = 0; f < 2; f++)
                ldsm_x4(a[f], sa0 + (arow[f] * 4 + ((2 * s + akc) ^ aswz[f])) * 16);
#pragma unroll
            for (int p = 0; p < 2; p++) {
                unsigned br[4];
                ldsm_x4(br, sb0 + (brow[p] * 4 + ((2 * s + bkc) ^ bswz[p])) * 16);
#pragma unroll
                for (int f = 0; f < 2; f++) {
                    mma_bf16(acc[f][2 * p],     a[f][0], a[f][1], a[f][2], a[f][3], br[0], br[1]);
                    mma_bf16(acc[f][2 * p + 1], a[f][0], a[f][1], a[f][2], a[f][3], br[2], br[3]);
                }
            }
        }
        __syncthreads();
    }
#pragma unroll
    for (int f = 0; f < 2; f++) {
        int ra = m0 + wm + f * 16 + g, rb = ra + 8;
#pragma unroll
        for (int p = 0; p < 4; p++) {
            int n = n0 + wn + p * 8 + 2 * t;
            if (n >= Nvalid) continue;
            float v0 = acc[f][p][0], v1 = acc[f][p][1], v2 = acc[f][p][2], v3 = acc[f][p][3];
            if (which == 0) { v0 = fmaxf(v0, 0.f); v1 = fmaxf(v1, 0.f); v2 = fmaxf(v2, 0.f); v3 = fmaxf(v3, 0.f); }
            *(float2*)(C + (size_t)ra * Ncols + n) = make_float2(v0, v1);
            *(float2*)(C + (size_t)rb * Ncols + n) = make_float2(v2, v3);
        }
    }
}

// ---------------- combine: out = in + (1-arf)*tmp2 + arf*tmp3 ----------------
__global__ __launch_bounds__(256) void combine_k(const float* __restrict__ in,
                                                 const float* __restrict__ arf) {
    int g = blockIdx.x * 256 + threadIdx.x;
    int p = g % HW, b = g / HW;
    int x = p % WW, y = p / WW;
    float a = __ldg(arf);
    int gy = y / 6, py = y - gy * 6, gx = x / 6, px = x - gx * 6;
    int n = gy * 64 + gx, f = py * 6 + px;
#pragma unroll
    for (int c = 0; c < 2; c++) {
        float t3v = g_t3[(size_t)(c * NN + n) * 144 + b * 36 + f];
        int li = (b * 2 + c) * HW + p;
        g_oimg[li] = in[li] + (1.f - a) * g_tmp2[li] + a * t3v;
    }
}

__device__ __forceinline__ float2 cadd(float2 a, float2 b) { return make_float2(a.x + b.x, a.y + b.y); }
__device__ __forceinline__ float2 csub(float2 a, float2 b) { return make_float2(a.x - b.x, a.y - b.y); }

// ---------------- fwd row FFT; fused z=(-1)^(x+y)*oimg*csm at load ----------------
__global__ __launch_bounds__(192) void fft_row_fwd_k(const float* __restrict__ csr,
                                                     const float* __restrict__ csi) {
    __shared__ float2 sb[384];
    int line = blockIdx.x;
    float2* base = g_k + (size_t)line * 384;
    int tid = threadIdx.x;
    {
        int img = line / HH, y = line % HH;
        int b = img & 3, c = img >> 2;
        const float* o0 = g_oimg + (size_t)(b * 2 + 0) * HW + y * WW;
        const float* o1 = g_oimg + (size_t)(b * 2 + 1) * HW + y * WW;
        const float* cr = csr + (size_t)(b * CCH + c) * HW + y * WW;
        const float* ci = csi + (size_t)(b * CCH + c) * HW + y * WW;
        for (int i = tid; i < 384; i += 192) {
            float orr = o0[i], oii = o1[i];
            float crv = __ldg(cr + i), civ = __ldg(ci + i);
            float sgn = ((i + y) & 1) ? -1.f : 1.f;
            float2 z = make_float2(sgn * (orr * crv - oii * civ), sgn * (orr * civ + oii * crv));
            int r = i % 3, q = i / 3;
            sb[r * 128 + q] = z;
        }
    }
    __syncthreads();
    int r = tid >> 6, bf = tid & 63, off = r << 7;
#pragma unroll
    for (int len = 128; len >= 2; len >>= 1) {
        int h = len >> 1;
        int grp = bf / h, t = bf - grp * h;
        int i1 = off + grp * len + t;
        float2 u = sb[i1], v = sb[i1 + h];
        sb[i1] = cadd(u, v);
        float2 d = csub(u, v);
        float2 w = g_tw128[t * (128 / len)];
        sb[i1 + h] = make_float2(d.x * w.x - d.y * w.y, d.x * w.y + d.y * w.x);
        __syncthreads();
    }
    for (int k = tid; k < 384; k += 192) {
        int k0 = k & 127;
        int rv = __brev((unsigned)k0) >> 25;
        float2 y0 = sb[rv], y1 = sb[128 + rv], y2 = sb[256 + rv];
        float2 c1 = g_tw384[k], c2 = g_tw384[(2 * k) % 384];
        float xr = y0.x + c1.x * y1.x - c1.y * y1.y + c2.x * y2.x - c2.y * y2.y;
        float xi = y0.y + c1.x * y1.y + c1.y * y1.x + c2.x * y2.y + c2.y * y2.x;
        base[k] = make_float2(xr, xi);
    }
}

// ---------------- FUSED column pass: fwd FFT -> DC -> inverse FFT ----------------
__global__ __launch_bounds__(192) void fft_col_fused_k(const int* __restrict__ mask,
                                                       const float* __restrict__ tkr,
                                                       const float* __restrict__ tki) {
    __shared__ float2 sb[8 * 384];
    int img = blockIdx.x / 48, cg = blockIdx.x % 48;
    float2* base = g_k + (size_t)img * HW + cg * 8;
    int tid = threadIdx.x;
    for (int i = tid; i < 3072; i += 192) {
        int col = i & 7, yy = i >> 3;
        float2 Z = base[(size_t)yy * 384 + col];
        sb[col * 384 + (yy % 3) * 128 + yy / 3] = Z;
    }
    __syncthreads();
#pragma unroll
    for (int len = 128; len >= 2; len >>= 1) {
        int h = len >> 1;
        for (int widx = tid; widx < 1536; widx += 192) {
            int seg = widx >> 6, bf = widx & 63;
            int boff = (seg / 3) * 384 + (seg % 3) * 128;
            int grp = bf / h, t = bf - grp * h;
            int i1 = boff + grp * len + t;
            float2 u = sb[i1], v = sb[i1 + h];
            sb[i1] = cadd(u, v);
            float2 d = csub(u, v);
            float2 w = g_tw128[t * (128 / len)];
            sb[i1 + h] = make_float2(d.x * w.x - d.y * w.y, d.x * w.y + d.y * w.x);
        }
        __syncthreads();
    }
    float2 val[16];
    for (int ii = 0; ii < 16; ii++) {
        int i = tid + ii * 192;
        int col = i & 7, k = i >> 3;
        int k0 = k & 127;
        int rv = __brev((unsigned)k0) >> 25;
        int cb = col * 384;
        float2 y0 = sb[cb + rv], y1 = sb[cb + 128 + rv], y2 = sb[cb + 256 + rv];
        float2 c1 = g_tw384[k], c2 = g_tw384[(2 * k) % 384];
        float xr = y0.x + c1.x * y1.x - c1.y * y1.y + c2.x * y2.x - c2.y * y2.y;
        float xi = y0.y + c1.x * y1.y + c1.y * y1.x + c2.x * y2.y + c2.y * y2.x;
        int gx = cg * 8 + col;
        int p = k * 384 + gx;
        float mv = (float)__ldg(mask + p);
        float sgn = ((gx + k) & 1) ? -1.f : 1.f;
        float coef = 384.f * 0.999999f * mv * sgn;
        float om = 1.f - mv;
        size_t gidx = (size_t)img * HW + p;
        val[ii] = make_float2(om * xr + coef * __ldg(tkr + gidx),
                              om * xi + coef * __ldg(tki + gidx));
    }
    __syncthreads();
    for (int ii = 0; ii < 16; ii++) {
        int i = tid + ii * 192;
        int col = i & 7, k = i >> 3;
        sb[col * 384 + (k % 3) * 128 + k / 3] = val[ii];
    }
    __syncthreads();
#pragma unroll
    for (int len = 128; len >= 2; len >>= 1) {
        int h = len >> 1;
        for (int widx = tid; widx < 1536; widx += 192) {
            int seg = widx >> 6, bf = widx & 63;
            int boff = (seg / 3) * 384 + (seg % 3) * 128;
            int grp = bf / h, t = bf - grp * h;
            int i1 = boff + grp * len + t;
            float2 u = sb[i1], v = sb[i1 + h];
            sb[i1] = cadd(u, v);
            float2 d = csub(u, v);
            float2 w = g_tw128[t * (128 / len)];
            sb[i1 + h] = make_float2(d.x * w.x + d.y * w.y, -d.x * w.y + d.y * w.x);
        }
        __syncthreads();
    }
    for (int i = tid; i < 3072; i += 192) {
        int col = i & 7, k = i >> 3;
        int k0 = k & 127;
        int rv = __brev((unsigned)k0) >> 25;
        int cb = col * 384;
        float2 y0 = sb[cb + rv], y1 = sb[cb + 128 + rv], y2 = sb[cb + 256 + rv];
        float2 c1 = g_tw384[k], c2 = g_tw384[(2 * k) % 384];
        float s1 = -c1.y, s2 = -c2.y;
        float xr = (y0.x + c1.x * y1.x - s1 * y1.y + c2.x * y2.x - s2 * y2.y) * (1.f / 384.f);
        float xi = (y0.y + c1.x * y1.y + s1 * y1.x + c2.x * y2.y + s2 * y2.x) * (1.f / 384.f);
        base[(size_t)k * 384 + col] = make_float2(xr, xi);
    }
}

// ---------------- fused inverse row FFT (12 coils) + coil combine ----------------
__global__ __launch_bounds__(384) void invrow_final_k(const float* __restrict__ csr,
                                                      const float* __restrict__ csi,
                                                      float* __restrict__ out) {
    __shared__ float2 sb[12][384];
    int y = blockIdx.x % HH, b = blockIdx.x / HH;
    int tid = threadIdx.x;
    int r0 = tid % 3, q0 = tid / 3;
#pragma unroll
    for (int c = 0; c < CCH; c++) {
        float2 z = g_k[((size_t)(c * BSZ + b)) * HW + (size_t)y * 384 + tid];
        sb[c][r0 * 128 + q0] = z;
    }
    __syncthreads();
#pragma unroll
    for (int len = 128; len >= 2; len >>= 1) {
        int h = len >> 1;
        for (int widx = tid; widx < 2304; widx += 384) {
            int line = widx / 192, bf = widx % 192;
            int seg = bf >> 6, b6 = bf & 63;
            int grp = b6 / h, t = b6 - grp * h;
            int i1 = seg * 128 + grp * len + t;
            float2 u = sb[line][i1], v = sb[line][i1 + h];
            sb[line][i1] = cadd(u, v);
            float2 d = csub(u, v);
            float2 w = g_tw128[t * (128 / len)];
            sb[line][i1 + h] = make_float2(d.x * w.x + d.y * w.y, -d.x * w.y + d.y * w.x);
        }
        __syncthreads();
    }
    int k = tid;
    int k0 = k & 127;
    int rv = __brev((unsigned)k0) >> 25;
    float2 c1 = g_tw384[k], c2 = g_tw384[(2 * k) % 384];
    float s1 = -c1.y, s2 = -c2.y;
    float rr = 0.f, ri = 0.f;
    const float* crb = csr + (size_t)b * CCH * HW + (size_t)y * WW + k;
    const float* cib = csi + (size_t)b * CCH * HW + (size_t)y * WW + k;
#pragma unroll
    for (int c = 0; c < CCH; c++) {
        float2 y0 = sb[c][rv], y1 = sb[c][128 + rv], y2 = sb[c][256 + rv];
        float xr = (y0.x + c1.x * y1.x - s1 * y1.y + c2.x * y2.x - s2 * y2.y) * (1.f / 384.f);
        float xi = (y0.y + c1.x * y1.y + s1 * y1.x + c2.x * y2.y + s2 * y2.x) * (1.f / 384.f);
        float cr = __ldg(crb + (size_t)c * HW);
        float ci = __ldg(cib + (size_t)c * HW);
        rr += xr * cr + xi * ci;
        ri += xi * cr - xr * ci;
    }
    float sgn = ((k + y) & 1) ? -1.f : 1.f;
    out[(size_t)(b * 2 + 0) * HW + (size_t)y * WW + k] = sgn * rr;
    out[(size_t)(b * 2 + 1) * HW + (size_t)y * WW + k] = sgn * ri;
}

// ---------------- launch ----------------
extern "C" void kernel_launch(void* const* d_in, const int* in_sizes, int n_in,
                              void* d_out, int out_size) {
    (void)in_sizes; (void)n_in; (void)out_size;
    const float* input = (const float*)d_in[0];
    const float* adj   = (const float*)d_in[1];
    const int*   mask  = (const int*)  d_in[2];
    const float* csr   = (const float*)d_in[3];
    const float* csi   = (const float*)d_in[4];
    const float* tkr   = (const float*)d_in[5];
    const float* tki   = (const float*)d_in[6];
    const float* W1    = (const float*)d_in[7];
    const float* W3    = (const float*)d_in[8];
    const float* arf   = (const float*)d_in[9];
    const float* cw1   = (const float*)d_in[10];
    const float* cb1   = (const float*)d_in[11];
    const float* cw2   = (const float*)d_in[12];
    const float* cb2   = (const float*)d_in[13];
    const float* cw3   = (const float*)d_in[14];
    const float* cb3   = (const float*)d_in[15];
    float* out = (float*)d_out;

    // Order chosen so gemm2_k(which=0) is launch index 3 (the ncu-captured slot).
    prep_w_k<<<144, 256>>>(cw2, cw3);                        // 0
    gcn_s_k<<<256, 128>>>(input, W1);                        // 1
    adj_cvt_k<<<32768, 256>>>(adj);                          // 2
    gemm2_k<<<dim3(4, 32, 2), 256>>>(0, 256);                // 3  <-- profiled
    conv1_k<<<4608, 256>>>(input, cw1, cb1);                 // 4
    conv2_mma<<<dim3(6, 192, 4), 128>>>(cb2);                // 5
    conv3_mma<<<dim3(6, 192, 4), 128>>>(cb3);                // 6
    gcn_s3_k<<<256, 128>>>(W3);                              // 7
    gemm2_k<<<dim3(3, 32, 2), 256>>>(1, 144);                // 8

    // combine + FFT chain
    combine_k<<<2304, 256>>>(input, arf);
    init_tw_k<<<1, 384>>>();
    fft_row_fwd_k<<<48 * 384, 192>>>(csr, csi);
    fft_col_fused_k<<<48 * 48, 192>>>(mask, tkr, tki);
    invrow_final_k<<<4 * 384, 384>>>(csr, csi, out);
}

// round 11
// speedup vs baseline: 1.3649x; 1.0541x over previous
#include <cuda_runtime.h>
#include <cuda_fp16.h>
#include <cuda_bf16.h>
#include <math.h>
#include <stdint.h>
#include <stddef.h>

#define BSZ 4
#define CCH 12
#define HH 384
#define WW 384
#define HW (HH*WW)
#define NN 4096

// ---------------- static device scratch (no allocs allowed) ----------------
__device__ __half         g_h1n[(size_t)BSZ*HW*64];   // conv1 out, NHWC fp16
__device__ __half         g_h2n[(size_t)BSZ*HW*64];   // conv2 out, NHWC fp16
__device__ __nv_bfloat16  g_adjb[(size_t)2*NN*NN];    // adj bf16
__device__ __half         g_w2t[9*64*64];             // conv2 w [tap][co][ci]
__device__ __half         g_w3t[9*8*64];              // conv3 w [tap][o pad8][ci]
__device__ __nv_bfloat16  g_st [(size_t)2*256*NN];    // s^T  [c][b*64+o][m]
__device__ __nv_bfloat16  g_s3t[(size_t)2*144*NN];    // s3^T [c][b*36+o][m]
__device__ float          g_g  [(size_t)2*NN*256];    // relu(adj@s) [c][m][256]
__device__ float          g_t3 [(size_t)2*NN*144];    // adj@s3 [c][m][144]
__device__ float          g_tmp2[BSZ*2*HW];
__device__ float          g_oimg[BSZ*2*HW];
__device__ float2         g_k[(size_t)CCH*BSZ*HW];
__device__ float2         g_tw128[64];
__device__ float2         g_tw384[384];

// ---------------- mma / ldmatrix / cp.async wrappers ----------------
__device__ __forceinline__ void mma_f16(float c[4], unsigned a0, unsigned a1,
                                        unsigned a2, unsigned a3,
                                        unsigned b0, unsigned b1) {
    asm volatile("mma.sync.aligned.m16n8k16.row.col.f32.f16.f16.f32 "
        "{%0,%1,%2,%3}, {%4,%5,%6,%7}, {%8,%9}, {%0,%1,%2,%3};"
        : "+f"(c[0]), "+f"(c[1]), "+f"(c[2]), "+f"(c[3])
        : "r"(a0), "r"(a1), "r"(a2), "r"(a3), "r"(b0), "r"(b1));
}
__device__ __forceinline__ void mma_bf16(float c[4], unsigned a0, unsigned a1,
                                         unsigned a2, unsigned a3,
                                         unsigned b0, unsigned b1) {
    asm volatile("mma.sync.aligned.m16n8k16.row.col.f32.bf16.bf16.f32 "
        "{%0,%1,%2,%3}, {%4,%5,%6,%7}, {%8,%9}, {%0,%1,%2,%3};"
        : "+f"(c[0]), "+f"(c[1]), "+f"(c[2]), "+f"(c[3])
        : "r"(a0), "r"(a1), "r"(a2), "r"(a3), "r"(b0), "r"(b1));
}
__device__ __forceinline__ void ldsm_x4(unsigned r[4], uint32_t a) {
    asm volatile("ldmatrix.sync.aligned.m8n8.x4.shared.b16 {%0,%1,%2,%3}, [%4];"
        : "=r"(r[0]), "=r"(r[1]), "=r"(r[2]), "=r"(r[3]) : "r"(a));
}
__device__ __forceinline__ void ldsm_x2(unsigned& r0, unsigned& r1, uint32_t a) {
    asm volatile("ldmatrix.sync.aligned.m8n8.x2.shared.b16 {%0,%1}, [%2];"
        : "=r"(r0), "=r"(r1) : "r"(a));
}
#define CP_ASYNC16(dst, src) \
    asm volatile("cp.async.cg.shared.global [%0], [%1], 16;" :: "r"(dst), "l"(src))
#define CP_COMMIT()  asm volatile("cp.async.commit_group;")
#define CP_WAIT0()   asm volatile("cp.async.wait_group 0;")
#define CP_WAIT1()   asm volatile("cp.async.wait_group 1;")

// ---------------- init ----------------
__global__ void init_tw_k() {
    int t = threadIdx.x;
    if (t < 64) { float s, c; sincospif(-(float)t / 64.f, &s, &c);  g_tw128[t] = make_float2(c, s); }
    {            float s, c; sincospif(-(float)t / 192.f, &s, &c); g_tw384[t] = make_float2(c, s); }
}
__global__ void prep_w_k(const float* __restrict__ cw2, const float* __restrict__ cw3) {
    int i = blockIdx.x * 256 + threadIdx.x;
    if (i < 9 * 64 * 64) {
        int tap = i / 4096, r = i % 4096, co = r >> 6, ci = r & 63;
        g_w2t[i] = __float2half(cw2[(co * 64 + ci) * 9 + tap]);
    }
    if (i < 9 * 8 * 64) {
        int tap = i / 512, r = i % 512, o = r >> 6, ci = r & 63;
        g_w3t[i] = __float2half((o < 2) ? cw3[(o * 64 + ci) * 9 + tap] : 0.f);
    }
}
__global__ __launch_bounds__(256) void adj_cvt_k(const float* __restrict__ adj) {
    size_t i = ((size_t)blockIdx.x * 256 + threadIdx.x) * 4;
    float4 v = *(const float4*)(adj + i);
    __nv_bfloat162* o = (__nv_bfloat162*)(g_adjb + i);
    o[0] = __floats2bfloat162_rn(v.x, v.y);
    o[1] = __floats2bfloat162_rn(v.z, v.w);
}

// ---------------- conv1: 2 -> 64, relu; 4 px x 8 ch per thread ----------------
__global__ __launch_bounds__(256) void conv1_k(const float* __restrict__ in,
                                               const float* __restrict__ w,
                                               const float* __restrict__ bias) {
    __shared__ float ws[18 * 64];
    for (int i = threadIdx.x; i < 1152; i += 256) {
        int co = i / 18, q = i % 18;
        ws[q * 64 + co] = w[i];
    }
    __syncthreads();
    int tid = threadIdx.x;
    int cog = tid & 7;
    int pq  = tid >> 3;
    int chunk = blockIdx.x % 3;
    int rowid = blockIdx.x / 3;
    int y = rowid % HH, b = rowid / HH;
    int px0 = chunk * 128 + pq * 4;
    float iv[2][3][6];
#pragma unroll
    for (int ci = 0; ci < 2; ci++) {
        const float* base = in + (b * 2 + ci) * HW;
#pragma unroll
        for (int ry = 0; ry < 3; ry++) {
            int yy = y + ry - 1; bool yok = (unsigned)yy < HH;
#pragma unroll
            for (int cx = 0; cx < 6; cx++) {
                int xx = px0 + cx - 1;
                iv[ci][ry][cx] = (yok && (unsigned)xx < WW) ? __ldg(base + yy * WW + xx) : 0.f;
            }
        }
    }
    float acc[4][8];
    float bz[8];
#pragma unroll
    for (int j = 0; j < 8; j++) bz[j] = __ldg(bias + cog * 8 + j);
#pragma unroll
    for (int px = 0; px < 4; px++)
#pragma unroll
        for (int j = 0; j < 8; j++) acc[px][j] = bz[j];
#pragma unroll
    for (int ci = 0; ci < 2; ci++)
#pragma unroll
        for (int ky = 0; ky < 3; ky++)
#pragma unroll
            for (int kx = 0; kx < 3; kx++) {
                int q = ci * 9 + ky * 3 + kx;
                const float4* wp = (const float4*)&ws[q * 64 + cog * 8];
                float4 wa = wp[0], wb = wp[1];
                float w8[8] = {wa.x, wa.y, wa.z, wa.w, wb.x, wb.y, wb.z, wb.w};
#pragma unroll
                for (int px = 0; px < 4; px++) {
                    float v = iv[ci][ky][kx + px];
#pragma unroll
                    for (int j = 0; j < 8; j++) acc[px][j] += v * w8[j];
                }
            }
#pragma unroll
    for (int px = 0; px < 4; px++) {
        size_t p = (size_t)b * HW + (size_t)y * WW + (px0 + px);
        __half2 h4[4];
#pragma unroll
        for (int j = 0; j < 8; j += 2)
            h4[j >> 1] = __floats2half2_rn(fmaxf(acc[px][j], 0.f), fmaxf(acc[px][j + 1], 0.f));
        *(uint4*)(g_h1n + p * 64 + cog * 8) = *(const uint4*)h4;
    }
}

// ---------------- conv2: 64->64 mma fp16; double-buffered cp.async B, x4 B loads ----------------
// grid (6, 192, 4), 128 thr = 4 warps; 50.2KB dynamic smem -> 4 blocks/SM
__global__ __launch_bounds__(128) void conv2_mma(const float* __restrict__ bias) {
    extern __shared__ uint4 dsm2[];
    uint4* s_a  = dsm2;          // [row 4][px 66][chunk 8 swz] = 2112 uint4 (33.8KB)
    uint4* s_b2 = dsm2 + 2112;   // [buf 2][co 64][chunk 8 swz] = 1024 uint4 (16KB)
    int x0 = blockIdx.x * 64, y0 = blockIdx.y * 2, b = blockIdx.z;
    int tid = threadIdx.x, wid = tid >> 5, lane = tid & 31;
    int g = lane >> 2, t = lane & 3;
    uint32_t sbq = (uint32_t)__cvta_generic_to_shared(s_b2);
    // prefetch B tap 0 (async)
#pragma unroll
    for (int j = 0; j < 4; j++) {
        int idx = tid + j * 128;
        int co = idx >> 3, cc = idx & 7;
        CP_ASYNC16(sbq + (co * 8 + (cc ^ (co & 7))) * 16, g_w2t + co * 64 + cc * 8);
    }
    CP_COMMIT();
    // stage A tile (rows y0-1..y0+2, px x0-1..x0+64), halo zero
    for (int idx = tid; idx < 2112; idx += 128) {
        int r = idx / 528, rem = idx % 528, p = rem >> 3, cc = rem & 7;
        int gx = x0 - 1 + p, yy = y0 - 1 + r;
        uint4 v = make_uint4(0, 0, 0, 0);
        if ((unsigned)gx < WW && (unsigned)yy < HH)
            v = *(const uint4*)(g_h1n + ((size_t)(b * HH + yy) * WW + gx) * 64 + cc * 8);
        s_a[(r * 66 + p) * 8 + (cc ^ (p & 7))] = v;
    }
    uint32_t sa = (uint32_t)__cvta_generic_to_shared(s_a);
    int lrow = lane & 7, msel = lane >> 3;
    int a_pofs = ((msel & 1) << 3) + lrow;
    int a_hi = msel >> 1;
    int lq = lane >> 3;
    float acc[2][8][4];
#pragma unroll
    for (int r = 0; r < 2; r++)
#pragma unroll
        for (int i = 0; i < 8; i++)
#pragma unroll
            for (int j = 0; j < 4; j++) acc[r][i][j] = 0.f;
    __syncthreads();   // A staged; B tap0 handled via wait_group below

    for (int tap = 0; tap < 9; tap++) {
        if (tap < 8) {   // prefetch next tap's B
            int buf = (tap + 1) & 1;
#pragma unroll
            for (int j = 0; j < 4; j++) {
                int idx = tid + j * 128;
                int co = idx >> 3, cc = idx & 7;
                CP_ASYNC16(sbq + (buf * 512 + co * 8 + (cc ^ (co & 7))) * 16,
                           g_w2t + (tap + 1) * 4096 + co * 64 + cc * 8);
            }
            CP_COMMIT();
            CP_WAIT1();     // current tap's group done; next stays in flight
        } else {
            CP_WAIT0();     // last tap: drain
        }
        __syncthreads();
        int ky = tap / 3, kx = tap % 3;
        int p = wid * 16 + kx + a_pofs;
        int psw = p & 7;
        int arow0 = (ky * 66 + p) * 8, arow1 = arow0 + 528;
        uint32_t sbt = sbq + (tap & 1) * 512 * 16;
#pragma unroll
        for (int kk = 0; kk < 4; kk++) {
            unsigned a0[4], a1[4];
            int chunk = 2 * kk + a_hi;
            ldsm_x4(a0, sa + (arow0 + (chunk ^ psw)) * 16);
            ldsm_x4(a1, sa + (arow1 + (chunk ^ psw)) * 16);
#pragma unroll
            for (int ntp = 0; ntp < 4; ntp++) {
                int co_b = (2 * ntp + (lq >> 1)) * 8 + lrow;
                int bch = 2 * kk + (lq & 1);
                unsigned br[4];
                ldsm_x4(br, sbt + (co_b * 8 + (bch ^ lrow)) * 16);
                mma_f16(acc[0][2 * ntp],     a0[0], a0[1], a0[2], a0[3], br[0], br[1]);
                mma_f16(acc[0][2 * ntp + 1], a0[0], a0[1], a0[2], a0[3], br[2], br[3]);
                mma_f16(acc[1][2 * ntp],     a1[0], a1[1], a1[2], a1[3], br[0], br[1]);
                mma_f16(acc[1][2 * ntp + 1], a1[0], a1[1], a1[2], a1[3], br[2], br[3]);
            }
        }
        __syncthreads();   // compute done before next prefetch overwrites other buf
    }
    int px1 = x0 + wid * 16 + g;
#pragma unroll
    for (int r = 0; r < 2; r++) {
        int y = y0 + r;
        __half* o1 = g_h2n + ((size_t)(b * HH + y) * WW + px1) * 64;
        __half* o2 = o1 + 8 * 64;
#pragma unroll
        for (int nt = 0; nt < 8; nt++) {
            int n = nt * 8 + 2 * t;
            float b0 = __ldg(bias + n), b1 = __ldg(bias + n + 1);
            *(__half2*)(o1 + n) = __floats2half2_rn(fmaxf(acc[r][nt][0] + b0, 0.f), fmaxf(acc[r][nt][1] + b1, 0.f));
            *(__half2*)(o2 + n) = __floats2half2_rn(fmaxf(acc[r][nt][2] + b0, 0.f), fmaxf(acc[r][nt][3] + b1, 0.f));
        }
    }
}

// ---------------- conv3: 64->2 mma fp16, smem+ldmatrix, M=32/warp ----------------
__global__ __launch_bounds__(128) void conv3_mma(const float* __restrict__ bias) {
    __shared__ uint4 s_a[4 * 66 * 8];
    __shared__ uint4 s_b3[576];
    int x0 = blockIdx.x * 64, y0 = blockIdx.y * 2, b = blockIdx.z;
    int tid = threadIdx.x, wid = tid >> 5, lane = tid & 31;
    int g = lane >> 2, t = lane & 3;
    for (int idx = tid; idx < 2112; idx += 128) {
        int r = idx / 528, rem = idx % 528, p = rem >> 3, cc = rem & 7;
        int gx = x0 - 1 + p, yy = y0 - 1 + r;
        uint4 v = make_uint4(0, 0, 0, 0);
        if ((unsigned)gx < WW && (unsigned)yy < HH)
            v = *(const uint4*)(g_h2n + ((size_t)(b * HH + yy) * WW + gx) * 64 + cc * 8);
        s_a[(r * 66 + p) * 8 + (cc ^ (p & 7))] = v;
    }
    for (int idx = tid; idx < 576; idx += 128) {
        int tap = idx / 64, rem = idx % 64, co = rem >> 3, cc = rem & 7;
        s_b3[tap * 64 + co * 8 + (cc ^ co)] =
            *(const uint4*)(g_w3t + tap * 512 + co * 64 + cc * 8);
    }
    __syncthreads();
    uint32_t sa = (uint32_t)__cvta_generic_to_shared(s_a);
    uint32_t sb = (uint32_t)__cvta_generic_to_shared(s_b3);
    int lrow = lane & 7, msel = lane >> 3;
    int a_pofs = ((msel & 1) << 3) + lrow;
    int a_hi = msel >> 1;
    int b_hi = (lane >> 3) & 1;
    float acc[2][4];
#pragma unroll
    for (int r = 0; r < 2; r++)
#pragma unroll
        for (int j = 0; j < 4; j++) acc[r][j] = 0.f;
    for (int ky = 0; ky < 3; ky++)
        for (int kx = 0; kx < 3; kx++) {
            int tap = ky * 3 + kx;
            int p = wid * 16 + kx + a_pofs;
            int psw = p & 7;
            int arow0 = (ky * 66 + p) * 8, arow1 = arow0 + 528;
#pragma unroll
            for (int kk = 0; kk < 4; kk++) {
                unsigned a0[4], a1[4];
                int chunk = 2 * kk + a_hi;
                ldsm_x4(a0, sa + (arow0 + (chunk ^ psw)) * 16);
                ldsm_x4(a1, sa + (arow1 + (chunk ^ psw)) * 16);
                unsigned b0, b1;
                int bch = 2 * kk + b_hi;
                ldsm_x2(b0, b1, sb + (tap * 64 + lrow * 8 + (bch ^ lrow)) * 16);
                mma_f16(acc[0], a0[0], a0[1], a0[2], a0[3], b0, b1);
                mma_f16(acc[1], a1[0], a1[1], a1[2], a1[3], b0, b1);
            }
        }
    if (t == 0) {
        float b0 = __ldg(bias + 0), b1 = __ldg(bias + 1);
        int px1 = x0 + wid * 16 + g, px2 = px1 + 8;
#pragma unroll
        for (int r = 0; r < 2; r++) {
            int base = (y0 + r) * WW;
            g_tmp2[(b * 2 + 0) * HW + base + px1] = acc[r][0] + b0;
            g_tmp2[(b * 2 + 1) * HW + base + px1] = acc[r][1] + b1;
            g_tmp2[(b * 2 + 0) * HW + base + px2] = acc[r][2] + b0;
            g_tmp2[(b * 2 + 1) * HW + base + px2] = acc[r][3] + b1;
        }
    }
}

// ---------------- GCN: s^T = (feat @ W1)^T, bf16, coalesced via smem transpose ----------------
__global__ __launch_bounds__(128) void gcn_s_k(const float* __restrict__ in,
                                               const float* __restrict__ W1) {
    __shared__ float w[36 * 64];
    __shared__ __nv_bfloat16 tb[16][136];
    for (int i = threadIdx.x; i < 2304; i += 128) w[i] = W1[i];
    __syncthreads();
    int idx = blockIdx.x * 128 + threadIdx.x;
    int n = idx & 4095, b = (idx >> 12) & 3, c = idx >> 14;
    int n0 = (blockIdx.x * 128) & 4095;
    int gy = n >> 6, gx = n & 63;
    const float* base = in + (b * 2 + c) * HW + (gy * 6) * WW + gx * 6;
    float f[36];
#pragma unroll
    for (int py = 0; py < 6; py++)
#pragma unroll
        for (int px = 0; px < 6; px++) f[py * 6 + px] = __ldg(base + py * WW + px);
    float acc[64];
#pragma unroll
    for (int o = 0; o < 64; o++) acc[o] = 0.f;
#pragma unroll
    for (int ff = 0; ff < 36; ff++) {
        float fv = f[ff];
        const float* wr = &w[ff * 64];
#pragma unroll
        for (int o = 0; o < 64; o++) acc[o] += fv * wr[o];
    }
    int nl = threadIdx.x;
    size_t orow = (size_t)(c * 256 + b * 64);
    for (int ch = 0; ch < 4; ch++) {
        __syncthreads();
#pragma unroll
        for (int o = 0; o < 16; o++) tb[o][nl] = __float2bfloat16(acc[ch * 16 + o]);
        __syncthreads();
        int r = nl >> 3, cw = (nl & 7) * 16;
        const uint4* src = (const uint4*)&tb[r][cw];
        uint4 v0 = src[0], v1 = src[1];
        uint4* dst = (uint4*)(g_st + (orow + ch * 16 + r) * NN + n0 + cw);
        dst[0] = v0; dst[1] = v1;
    }
}

// ---------------- GCN: s3^T = (g @ W3)^T, bf16, coalesced via smem transpose ----------------
__global__ __launch_bounds__(128) void gcn_s3_k(const float* __restrict__ W3) {
    __shared__ float w[64 * 36];
    __shared__ __nv_bfloat16 tb[36][136];
    for (int i = threadIdx.x; i < 2304; i += 128) w[i] = W3[i];
    __syncthreads();
    int idx = blockIdx.x * 128 + threadIdx.x;
    int n = idx & 4095, b = (idx >> 12) & 3, c = idx >> 14;
    int n0 = (blockIdx.x * 128) & 4095;
    const float* gb = g_g + (size_t)(c * NN + n) * 256 + b * 64;
    float acc[36];
#pragma unroll
    for (int o = 0; o < 36; o++) acc[o] = 0.f;
#pragma unroll
    for (int k = 0; k < 64; k += 4) {
        float4 g4 = *(const float4*)(gb + k);
        float gv[4] = {g4.x, g4.y, g4.z, g4.w};
#pragma unroll
        for (int kk = 0; kk < 4; kk++) {
            const float* wr = &w[(k + kk) * 36];
            float gvv = gv[kk];
#pragma unroll
            for (int o = 0; o < 36; o++) acc[o] += gvv * wr[o];
        }
    }
    int nl = threadIdx.x;
#pragma unroll
    for (int o = 0; o < 36; o++) tb[o][nl] = __float2bfloat16(acc[o]);
    __syncthreads();
    size_t orow = (size_t)(c * 144 + b * 36);
    for (int rr = nl; rr < 288; rr += 128) {
        int r = rr >> 3, cw = (rr & 7) * 16;
        const uint4* src = (const uint4*)&tb[r][cw];
        uint4 v0 = src[0], v1 = src[1];
        uint4* dst = (uint4*)(g_s3t + (orow + r) * NN + n0 + cw);
        dst[0] = v0; dst[1] = v1;
    }
}

// ---------------- adj GEMM: 3-stage cp.async pipeline, one sync/iter ----------------
// 256 thr = 8 warps (4M x 2N); block tile M=128, N=64, K=32/stage.
__global__ __launch_bounds__(256) void gemm2_k(int which, int Nvalid) {
    __shared__ uint4 sA[3][512];   // 24KB
    __shared__ uint4 sB[3][256];   // 12KB
    int c = blockIdx.z;
    const __nv_bfloat16* A = g_adjb + (size_t)c * NN * NN;
    const __nv_bfloat16* Bm; float* C; int Ncols;
    if (which == 0) { Bm = g_st  + (size_t)c * 256 * NN; C = g_g  + (size_t)c * NN * 256; Ncols = 256; }
    else            { Bm = g_s3t + (size_t)c * 144 * NN; C = g_t3 + (size_t)c * NN * 144; Ncols = 144; }
    int n0 = blockIdx.x * 64, m0 = blockIdx.y * 128;
    int tid = threadIdx.x, wid = tid >> 5, lane = tid & 31;
    int g = lane >> 2, t = lane & 3;
    int wm = (wid >> 1) * 32, wn = (wid & 1) * 32;
    uint32_t sab = (uint32_t)__cvta_generic_to_shared(sA);
    uint32_t sbb = (uint32_t)__cvta_generic_to_shared(sB);

    int arow[2], aswz[2];
#pragma unroll
    for (int f = 0; f < 2; f++) {
        arow[f] = wm + f * 16 + (lane & 7) + ((lane >> 3) & 1) * 8;
        aswz[f] = (arow[f] >> 1) & 3;
    }
    int akc = (lane >> 4) & 1;
    int brow[2], bswz[2];
#pragma unroll
    for (int p = 0; p < 2; p++) {
        brow[p] = wn + p * 16 + (lane & 7) + ((lane >> 4) << 3);
        bswz[p] = (brow[p] >> 1) & 3;
    }
    int bkc = (lane >> 3) & 1;

    float acc[2][4][4];
#pragma unroll
    for (int f = 0; f < 2; f++)
#pragma unroll
        for (int p = 0; p < 4; p++)
#pragma unroll
            for (int j = 0; j < 4; j++) acc[f][p][j] = 0.f;

    auto stage = [&](int buf, int k0) {
#pragma unroll
        for (int idx = tid; idx < 768; idx += 256) {
            if (idx < 512) {
                int r = idx >> 2, cc = idx & 3;
                uint32_t dst = sab + (buf * 512 + r * 4 + (cc ^ ((r >> 1) & 3))) * 16;
                CP_ASYNC16(dst, A + (size_t)(m0 + r) * NN + k0 + cc * 8);
            } else {
                int j = idx - 512;
                int r = j >> 2, cc = j & 3;
                int row = n0 + r; if (row >= Nvalid) row = Nvalid - 1;
                uint32_t dst = sbb + (buf * 256 + r * 4 + (cc ^ ((r >> 1) & 3))) * 16;
                CP_ASYNC16(dst, Bm + (size_t)row * NN + k0 + cc * 8);
            }
        }
        CP_COMMIT();
    };

    const int NIT = NN / 32;   // 128
    stage(0, 0);
    stage(1, 32);
    for (int i = 0; i < NIT; i++) {
        if (i + 1 < NIT) CP_WAIT1(); else CP_WAIT0();
        __syncthreads();
        if (i + 2 < NIT) stage((i + 2) % 3, (i + 2) * 32);
        int buf = i % 3;
        uint32_t sa0 = sab + buf * 512 * 16;
        uint32_t sb0 = sbb + buf * 256 * 16;
#pragma unroll
        for (int s = 0; s < 2; s++) {
            unsigned a[2][4];
#pragma unroll
            for (int f = 0; f < 2; f++)
                ldsm_x4(a[f], sa0 + (arow[f] * 4 + ((2 * s + akc) ^ aswz[f])) * 16);
#pragma unroll
            for (int p = 0; p < 2; p++) {
                unsigned br[4];
                ldsm_x4(br, sb0 + (brow[p] * 4 + ((2 * s + bkc) ^ bswz[p])) * 16);
#pragma unroll
                for (int f = 0; f < 2; f++) {
                    mma_bf16(acc[f][2 * p],     a[f][0], a[f][1], a[f][2], a[f][3], br[0], br[1]);
                    mma_bf16(acc[f][2 * p + 1], a[f][0], a[f][1], a[f][2], a[f][3], br[2], br[3]);
                }
            }
        }
    }
#pragma unroll
    for (int f = 0; f < 2; f++) {
        int ra = m0 + wm + f * 16 + g, rb = ra + 8;
#pragma unroll
        for (int p = 0; p < 4; p++) {
            int n = n0 + wn + p * 8 + 2 * t;
            if (n >= Nvalid) continue;
            float v0 = acc[f][p][0], v1 = acc[f][p][1], v2 = acc[f][p][2], v3 = acc[f][p][3];
            if (which == 0) { v0 = fmaxf(v0, 0.f); v1 = fmaxf(v1, 0.f); v2 = fmaxf(v2, 0.f); v3 = fmaxf(v3, 0.f); }
            *(float2*)(C + (size_t)ra * Ncols + n) = make_float2(v0, v1);
            *(float2*)(C + (size_t)rb * Ncols + n) = make_float2(v2, v3);
        }
    }
}

// ---------------- combine: out = in + (1-arf)*tmp2 + arf*tmp3 ----------------
__global__ __launch_bounds__(256) void combine_k(const float* __restrict__ in,
                                                 const float* __restrict__ arf) {
    int g = blockIdx.x * 256 + threadIdx.x;
    int p = g % HW, b = g / HW;
    int x = p % WW, y = p / WW;
    float a = __ldg(arf);
    int gy = y / 6, py = y - gy * 6, gx = x / 6, px = x - gx * 6;
    int n = gy * 64 + gx, f = py * 6 + px;
#pragma unroll
    for (int c = 0; c < 2; c++) {
        float t3v = g_t3[(size_t)(c * NN + n) * 144 + b * 36 + f];
        int li = (b * 2 + c) * HW + p;
        g_oimg[li] = in[li] + (1.f - a) * g_tmp2[li] + a * t3v;
    }
}

__device__ __forceinline__ float2 cadd(float2 a, float2 b) { return make_float2(a.x + b.x, a.y + b.y); }
__device__ __forceinline__ float2 csub(float2 a, float2 b) { return make_float2(a.x - b.x, a.y - b.y); }

// ---------------- fwd row FFT; fused z=(-1)^(x+y)*oimg*csm at load ----------------
__global__ __launch_bounds__(192) void fft_row_fwd_k(const float* __restrict__ csr,
                                                     const float* __restrict__ csi) {
    __shared__ float2 sb[384];
    int line = blockIdx.x;
    float2* base = g_k + (size_t)line * 384;
    int tid = threadIdx.x;
    {
        int img = line / HH, y = line % HH;
        int b = img & 3, c = img >> 2;
        const float* o0 = g_oimg + (size_t)(b * 2 + 0) * HW + y * WW;
        const float* o1 = g_oimg + (size_t)(b * 2 + 1) * HW + y * WW;
        const float* cr = csr + (size_t)(b * CCH + c) * HW + y * WW;
        const float* ci = csi + (size_t)(b * CCH + c) * HW + y * WW;
        for (int i = tid; i < 384; i += 192) {
            float orr = o0[i], oii = o1[i];
            float crv = __ldg(cr + i), civ = __ldg(ci + i);
            float sgn = ((i + y) & 1) ? -1.f : 1.f;
            float2 z = make_float2(sgn * (orr * crv - oii * civ), sgn * (orr * civ + oii * crv));
            int r = i % 3, q = i / 3;
            sb[r * 128 + q] = z;
        }
    }
    __syncthreads();
    int r = tid >> 6, bf = tid & 63, off = r << 7;
#pragma unroll
    for (int len = 128; len >= 2; len >>= 1) {
        int h = len >> 1;
        int grp = bf / h, t = bf - grp * h;
        int i1 = off + grp * len + t;
        float2 u = sb[i1], v = sb[i1 + h];
        sb[i1] = cadd(u, v);
        float2 d = csub(u, v);
        float2 w = g_tw128[t * (128 / len)];
        sb[i1 + h] = make_float2(d.x * w.x - d.y * w.y, d.x * w.y + d.y * w.x);
        __syncthreads();
    }
    for (int k = tid; k < 384; k += 192) {
        int k0 = k & 127;
        int rv = __brev((unsigned)k0) >> 25;
        float2 y0 = sb[rv], y1 = sb[128 + rv], y2 = sb[256 + rv];
        float2 c1 = g_tw384[k], c2 = g_tw384[(2 * k) % 384];
        float xr = y0.x + c1.x * y1.x - c1.y * y1.y + c2.x * y2.x - c2.y * y2.y;
        float xi = y0.y + c1.x * y1.y + c1.y * y1.x + c2.x * y2.y + c2.y * y2.x;
        base[k] = make_float2(xr, xi);
    }
}

// ---------------- FUSED column pass: fwd FFT -> DC -> inverse FFT ----------------
__global__ __launch_bounds__(192) void fft_col_fused_k(const int* __restrict__ mask,
                                                       const float* __restrict__ tkr,
                                                       const float* __restrict__ tki) {
    __shared__ float2 sb[8 * 384];
    int img = blockIdx.x / 48, cg = blockIdx.x % 48;
    float2* base = g_k + (size_t)img * HW + cg * 8;
    int tid = threadIdx.x;
    for (int i = tid; i < 3072; i += 192) {
        int col = i & 7, yy = i >> 3;
        float2 Z = base[(size_t)yy * 384 + col];
        sb[col * 384 + (yy % 3) * 128 + yy / 3] = Z;
    }
    __syncthreads();
#pragma unroll
    for (int len = 128; len >= 2; len >>= 1) {
        int h = len >> 1;
        for (int widx = tid; widx < 1536; widx += 192) {
            int seg = widx >> 6, bf = widx & 63;
            int boff = (seg / 3) * 384 + (seg % 3) * 128;
            int grp = bf / h, t = bf - grp * h;
            int i1 = boff + grp * len + t;
            float2 u = sb[i1], v = sb[i1 + h];
            sb[i1] = cadd(u, v);
            float2 d = csub(u, v);
            float2 w = g_tw128[t * (128 / len)];
            sb[i1 + h] = make_float2(d.x * w.x - d.y * w.y, d.x * w.y + d.y * w.x);
        }
        __syncthreads();
    }
    float2 val[16];
    for (int ii = 0; ii < 16; ii++) {
        int i = tid + ii * 192;
        int col = i & 7, k = i >> 3;
        int k0 = k & 127;
        int rv = __brev((unsigned)k0) >> 25;
        int cb = col * 384;
        float2 y0 = sb[cb + rv], y1 = sb[cb + 128 + rv], y2 = sb[cb + 256 + rv];
        float2 c1 = g_tw384[k], c2 = g_tw384[(2 * k) % 384];
        float xr = y0.x + c1.x * y1.x - c1.y * y1.y + c2.x * y2.x - c2.y * y2.y;
        float xi = y0.y + c1.x * y1.y + c1.y * y1.x + c2.x * y2.y + c2.y * y2.x;
        int gx = cg * 8 + col;
        int p = k * 384 + gx;
        float mv = (float)__ldg(mask + p);
        float sgn = ((gx + k) & 1) ? -1.f : 1.f;
        float coef = 384.f * 0.999999f * mv * sgn;
        float om = 1.f - mv;
        size_t gidx = (size_t)img * HW + p;
        val[ii] = make_float2(om * xr + coef * __ldg(tkr + gidx),
                              om * xi + coef * __ldg(tki + gidx));
    }
    __syncthreads();
    for (int ii = 0; ii < 16; ii++) {
        int i = tid + ii * 192;
        int col = i & 7, k = i >> 3;
        sb[col * 384 + (k % 3) * 128 + k / 3] = val[ii];
    }
    __syncthreads();
#pragma unroll
    for (int len = 128; len >= 2; len >>= 1) {
        int h = len >> 1;
        for (int widx = tid; widx < 1536; widx += 192) {
            int seg = widx >> 6, bf = widx & 63;
            int boff = (seg / 3) * 384 + (seg % 3) * 128;
            int grp = bf / h, t = bf - grp * h;
            int i1 = boff + grp * len + t;
            float2 u = sb[i1], v = sb[i1 + h];
            sb[i1] = cadd(u, v);
            float2 d = csub(u, v);
            float2 w = g_tw128[t * (128 / len)];
            sb[i1 + h] = make_float2(d.x * w.x + d.y * w.y, -d.x * w.y + d.y * w.x);
        }
        __syncthreads();
    }
    for (int i = tid; i < 3072; i += 192) {
        int col = i & 7, k = i >> 3;
        int k0 = k & 127;
        int rv = __brev((unsigned)k0) >> 25;
        int cb = col * 384;
        float2 y0 = sb[cb + rv], y1 = sb[cb + 128 + rv], y2 = sb[cb + 256 + rv];
        float2 c1 = g_tw384[k], c2 = g_tw384[(2 * k) % 384];
        float s1 = -c1.y, s2 = -c2.y;
        float xr = (y0.x + c1.x * y1.x - s1 * y1.y + c2.x * y2.x - s2 * y2.y) * (1.f / 384.f);
        float xi = (y0.y + c1.x * y1.y + s1 * y1.x + c2.x * y2.y + s2 * y2.x) * (1.f / 384.f);
        base[(size_t)k * 384 + col] = make_float2(xr, xi);
    }
}

// ---------------- fused inverse row FFT (12 coils) + coil combine ----------------
__global__ __launch_bounds__(384) void invrow_final_k(const float* __restrict__ csr,
                                                      const float* __restrict__ csi,
                                                      float* __restrict__ out) {
    __shared__ float2 sb[12][384];
    int y = blockIdx.x % HH, b = blockIdx.x / HH;
    int tid = threadIdx.x;
    int r0 = tid % 3, q0 = tid / 3;
#pragma unroll
    for (int c = 0; c < CCH; c++) {
        float2 z = g_k[((size_t)(c * BSZ + b)) * HW + (size_t)y * 384 + tid];
        sb[c][r0 * 128 + q0] = z;
    }
    __syncthreads();
#pragma unroll
    for (int len = 128; len >= 2; len >>= 1) {
        int h = len >> 1;
        for (int widx = tid; widx < 2304; widx += 384) {
            int line = widx / 192, bf = widx % 192;
            int seg = bf >> 6, b6 = bf & 63;
            int grp = b6 / h, t = b6 - grp * h;
            int i1 = seg * 128 + grp * len + t;
            float2 u = sb[line][i1], v = sb[line][i1 + h];
            sb[line][i1] = cadd(u, v);
            float2 d = csub(u, v);
            float2 w = g_tw128[t * (128 / len)];
            sb[line][i1 + h] = make_float2(d.x * w.x + d.y * w.y, -d.x * w.y + d.y * w.x);
        }
        __syncthreads();
    }
    int k = tid;
    int k0 = k & 127;
    int rv = __brev((unsigned)k0) >> 25;
    float2 c1 = g_tw384[k], c2 = g_tw384[(2 * k) % 384];
    float s1 = -c1.y, s2 = -c2.y;
    float rr = 0.f, ri = 0.f;
    const float* crb = csr + (size_t)b * CCH * HW + (size_t)y * WW + k;
    const float* cib = csi + (size_t)b * CCH * HW + (size_t)y * WW + k;
#pragma unroll
    for (int c = 0; c < CCH; c++) {
        float2 y0 = sb[c][rv], y1 = sb[c][128 + rv], y2 = sb[c][256 + rv];
        float xr = (y0.x + c1.x * y1.x - s1 * y1.y + c2.x * y2.x - s2 * y2.y) * (1.f / 384.f);
        float xi = (y0.y + c1.x * y1.y + s1 * y1.x + c2.x * y2.y + s2 * y2.x) * (1.f / 384.f);
        float cr = __ldg(crb + (size_t)c * HW);
        float ci = __ldg(cib + (size_t)c * HW);
        rr += xr * cr + xi * ci;
        ri += xi * cr - xr * ci;
    }
    float sgn = ((k + y) & 1) ? -1.f : 1.f;
    out[(size_t)(b * 2 + 0) * HW + (size_t)y * WW + k] = sgn * rr;
    out[(size_t)(b * 2 + 1) * HW + (size_t)y * WW + k] = sgn * ri;
}

// ---------------- launch ----------------
extern "C" void kernel_launch(void* const* d_in, const int* in_sizes, int n_in,
                              void* d_out, int out_size) {
    (void)in_sizes; (void)n_in; (void)out_size;
    const float* input = (const float*)d_in[0];
    const float* adj   = (const float*)d_in[1];
    const int*   mask  = (const int*)  d_in[2];
    const float* csr   = (const float*)d_in[3];
    const float* csi   = (const float*)d_in[4];
    const float* tkr   = (const float*)d_in[5];
    const float* tki   = (const float*)d_in[6];
    const float* W1    = (const float*)d_in[7];
    const float* W3    = (const float*)d_in[8];
    const float* arf   = (const float*)d_in[9];
    const float* cw1   = (const float*)d_in[10];
    const float* cb1   = (const float*)d_in[11];
    const float* cw2   = (const float*)d_in[12];
    const float* cb2   = (const float*)d_in[13];
    const float* cw3   = (const float*)d_in[14];
    const float* cb3   = (const float*)d_in[15];
    float* out = (float*)d_out;

    const int CONV2_SMEM = (2112 + 1024) * 16;   // 50176 B
    cudaFuncSetAttribute(conv2_mma, cudaFuncAttributeMaxDynamicSharedMemorySize, CONV2_SMEM);

    // Order chosen so conv2_mma is launch index 3 (the ncu-captured slot).
    prep_w_k<<<144, 256>>>(cw2, cw3);                        // 0
    conv1_k<<<4608, 256>>>(input, cw1, cb1);                 // 1
    gcn_s_k<<<256, 128>>>(input, W1);                        // 2
    conv2_mma<<<dim3(6, 192, 4), 128, CONV2_SMEM>>>(cb2);    // 3  <-- profiled
    adj_cvt_k<<<32768, 256>>>(adj);                          // 4
    gemm2_k<<<dim3(4, 32, 2), 256>>>(0, 256);                // 5
    conv3_mma<<<dim3(6, 192, 4), 128>>>(cb3);                // 6
    gcn_s3_k<<<256, 128>>>(W3);                              // 7
    gemm2_k<<<dim3(3, 32, 2), 256>>>(1, 144);                // 8

    // combine + FFT chain
    combine_k<<<2304, 256>>>(input, arf);
    init_tw_k<<<1, 384>>>();
    fft_row_fwd_k<<<48 * 384, 192>>>(csr, csi);
    fft_col_fused_k<<<48 * 48, 192>>>(mask, tkr, tki);
    invrow_final_k<<<4 * 384, 384>>>(csr, csi, out);
}

// round 12
// speedup vs baseline: 1.4978x; 1.0974x over previous
#include <cuda_runtime.h>
#include <cuda_fp16.h>
#include <cuda_bf16.h>
#include <math.h>
#include <stdint.h>
#include <stddef.h>

#define BSZ 4
#define CCH 12
#define HH 384
#define WW 384
#define HW (HH*WW)
#define NN 4096

// ---------------- static device scratch (no allocs allowed) ----------------
__device__ __half         g_h1n[(size_t)BSZ*HW*64];   // conv1 out, NHWC fp16
__device__ __half         g_h2n[(size_t)BSZ*HW*64];   // conv2 out, NHWC fp16
__device__ __nv_bfloat16  g_adjb[(size_t)2*NN*NN];    // adj bf16
__device__ __half         g_w2t[9*64*64];             // conv2 w [tap][co][ci]
__device__ __half         g_w3t[9*8*64];              // conv3 w [tap][o pad8][ci]
__device__ __nv_bfloat16  g_st [(size_t)2*256*NN];    // s^T  [c][b*64+o][m]
__device__ __nv_bfloat16  g_s3t[(size_t)2*144*NN];    // s3^T [c][b*36+o][m]
__device__ float          g_g  [(size_t)2*NN*256];    // relu(adj@s) [c][m][256]
__device__ float          g_t3 [(size_t)2*NN*144];    // adj@s3 [c][m][144]
__device__ float          g_tmp2[BSZ*2*HW];
__device__ float2         g_k[(size_t)CCH*BSZ*HW];
__device__ float2         g_tw128[64];
__device__ float2         g_tw384[384];

// ---------------- mma / ldmatrix / cp.async wrappers ----------------
__device__ __forceinline__ void mma_f16(float c[4], unsigned a0, unsigned a1,
                                        unsigned a2, unsigned a3,
                                        unsigned b0, unsigned b1) {
    asm volatile("mma.sync.aligned.m16n8k16.row.col.f32.f16.f16.f32 "
        "{%0,%1,%2,%3}, {%4,%5,%6,%7}, {%8,%9}, {%0,%1,%2,%3};"
        : "+f"(c[0]), "+f"(c[1]), "+f"(c[2]), "+f"(c[3])
        : "r"(a0), "r"(a1), "r"(a2), "r"(a3), "r"(b0), "r"(b1));
}
__device__ __forceinline__ void mma_bf16(float c[4], unsigned a0, unsigned a1,
                                         unsigned a2, unsigned a3,
                                         unsigned b0, unsigned b1) {
    asm volatile("mma.sync.aligned.m16n8k16.row.col.f32.bf16.bf16.f32 "
        "{%0,%1,%2,%3}, {%4,%5,%6,%7}, {%8,%9}, {%0,%1,%2,%3};"
        : "+f"(c[0]), "+f"(c[1]), "+f"(c[2]), "+f"(c[3])
        : "r"(a0), "r"(a1), "r"(a2), "r"(a3), "r"(b0), "r"(b1));
}
__device__ __forceinline__ void ldsm_x4(unsigned r[4], uint32_t a) {
    asm volatile("ldmatrix.sync.aligned.m8n8.x4.shared.b16 {%0,%1,%2,%3}, [%4];"
        : "=r"(r[0]), "=r"(r[1]), "=r"(r[2]), "=r"(r[3]) : "r"(a));
}
__device__ __forceinline__ void ldsm_x2(unsigned& r0, unsigned& r1, uint32_t a) {
    asm volatile("ldmatrix.sync.aligned.m8n8.x2.shared.b16 {%0,%1}, [%2];"
        : "=r"(r0), "=r"(r1) : "r"(a));
}
#define CP_ASYNC16(dst, src) \
    asm volatile("cp.async.cg.shared.global [%0], [%1], 16;" :: "r"(dst), "l"(src))
#define CP_ASYNC16Z(dst, src, sz) \
    asm volatile("cp.async.cg.shared.global [%0], [%1], 16, %2;" :: "r"(dst), "l"(src), "r"(sz))
#define CP_COMMIT()  asm volatile("cp.async.commit_group;")
#define CP_WAIT0()   asm volatile("cp.async.wait_group 0;")
#define CP_WAIT1()   asm volatile("cp.async.wait_group 1;")

// ---------------- init ----------------
__global__ void init_tw_k() {
    int t = threadIdx.x;
    if (t < 64) { float s, c; sincospif(-(float)t / 64.f, &s, &c);  g_tw128[t] = make_float2(c, s); }
    {            float s, c; sincospif(-(float)t / 192.f, &s, &c); g_tw384[t] = make_float2(c, s); }
}
__global__ void prep_w_k(const float* __restrict__ cw2, const float* __restrict__ cw3) {
    int i = blockIdx.x * 256 + threadIdx.x;
    if (i < 9 * 64 * 64) {
        int tap = i / 4096, r = i % 4096, co = r >> 6, ci = r & 63;
        g_w2t[i] = __float2half(cw2[(co * 64 + ci) * 9 + tap]);
    }
    if (i < 9 * 8 * 64) {
        int tap = i / 512, r = i % 512, o = r >> 6, ci = r & 63;
        g_w3t[i] = __float2half((o < 2) ? cw3[(o * 64 + ci) * 9 + tap] : 0.f);
    }
}
__global__ __launch_bounds__(256) void adj_cvt_k(const float* __restrict__ adj) {
    size_t i = ((size_t)blockIdx.x * 256 + threadIdx.x) * 4;
    float4 v = *(const float4*)(adj + i);
    __nv_bfloat162* o = (__nv_bfloat162*)(g_adjb + i);
    o[0] = __floats2bfloat162_rn(v.x, v.y);
    o[1] = __floats2bfloat162_rn(v.z, v.w);
}

// ---------------- conv1: 2 -> 64, relu; 4 px x 8 ch per thread ----------------
__global__ __launch_bounds__(256) void conv1_k(const float* __restrict__ in,
                                               const float* __restrict__ w,
                                               const float* __restrict__ bias) {
    __shared__ float ws[18 * 64];
    for (int i = threadIdx.x; i < 1152; i += 256) {
        int co = i / 18, q = i % 18;
        ws[q * 64 + co] = w[i];
    }
    __syncthreads();
    int tid = threadIdx.x;
    int cog = tid & 7;
    int pq  = tid >> 3;
    int chunk = blockIdx.x % 3;
    int rowid = blockIdx.x / 3;
    int y = rowid % HH, b = rowid / HH;
    int px0 = chunk * 128 + pq * 4;
    float iv[2][3][6];
#pragma unroll
    for (int ci = 0; ci < 2; ci++) {
        const float* base = in + (b * 2 + ci) * HW;
#pragma unroll
        for (int ry = 0; ry < 3; ry++) {
            int yy = y + ry - 1; bool yok = (unsigned)yy < HH;
#pragma unroll
            for (int cx = 0; cx < 6; cx++) {
                int xx = px0 + cx - 1;
                iv[ci][ry][cx] = (yok && (unsigned)xx < WW) ? __ldg(base + yy * WW + xx) : 0.f;
            }
        }
    }
    float acc[4][8];
    float bz[8];
#pragma unroll
    for (int j = 0; j < 8; j++) bz[j] = __ldg(bias + cog * 8 + j);
#pragma unroll
    for (int px = 0; px < 4; px++)
#pragma unroll
        for (int j = 0; j < 8; j++) acc[px][j] = bz[j];
#pragma unroll
    for (int ci = 0; ci < 2; ci++)
#pragma unroll
        for (int ky = 0; ky < 3; ky++)
#pragma unroll
            for (int kx = 0; kx < 3; kx++) {
                int q = ci * 9 + ky * 3 + kx;
                const float4* wp = (const float4*)&ws[q * 64 + cog * 8];
                float4 wa = wp[0], wb = wp[1];
                float w8[8] = {wa.x, wa.y, wa.z, wa.w, wb.x, wb.y, wb.z, wb.w};
#pragma unroll
                for (int px = 0; px < 4; px++) {
                    float v = iv[ci][ky][kx + px];
#pragma unroll
                    for (int j = 0; j < 8; j++) acc[px][j] += v * w8[j];
                }
            }
#pragma unroll
    for (int px = 0; px < 4; px++) {
        size_t p = (size_t)b * HW + (size_t)y * WW + (px0 + px);
        __half2 h4[4];
#pragma unroll
        for (int j = 0; j < 8; j += 2)
            h4[j >> 1] = __floats2half2_rn(fmaxf(acc[px][j], 0.f), fmaxf(acc[px][j + 1], 0.f));
        *(uint4*)(g_h1n + p * 64 + cog * 8) = *(const uint4*)h4;
    }
}

// ---------------- conv2: 64->64 mma fp16; cp.async A + double-buffered B ----------------
// grid (6, 192, 4), 128 thr = 4 warps; 50.2KB dynamic smem
__global__ __launch_bounds__(128) void conv2_mma(const float* __restrict__ bias) {
    extern __shared__ uint4 dsm2[];
    uint4* s_a  = dsm2;          // [row 4][px 66][chunk 8 swz] = 2112 uint4
    uint4* s_b2 = dsm2 + 2112;   // [buf 2][co 64][chunk 8 swz] = 1024 uint4
    int x0 = blockIdx.x * 64, y0 = blockIdx.y * 2, b = blockIdx.z;
    int tid = threadIdx.x, wid = tid >> 5, lane = tid & 31;
    int g = lane >> 2, t = lane & 3;
    uint32_t sbq = (uint32_t)__cvta_generic_to_shared(s_b2);
    uint32_t sa = (uint32_t)__cvta_generic_to_shared(s_a);
    // prefetch B tap 0 (group 0)
#pragma unroll
    for (int j = 0; j < 4; j++) {
        int idx = tid + j * 128;
        int co = idx >> 3, cc = idx & 7;
        CP_ASYNC16(sbq + (co * 8 + (cc ^ (co & 7))) * 16, g_w2t + co * 64 + cc * 8);
    }
    CP_COMMIT();
    // stage A tile via cp.async, halo zero-filled (group 1)
    for (int idx = tid; idx < 2112; idx += 128) {
        int r = idx / 528, rem = idx % 528, p = rem >> 3, cc = rem & 7;
        int gx = x0 - 1 + p, yy = y0 - 1 + r;
        bool ok = ((unsigned)gx < WW) && ((unsigned)yy < HH);
        const __half* src = g_h1n + ((size_t)(b * HH + (ok ? yy : 0)) * WW + (ok ? gx : 0)) * 64 + cc * 8;
        CP_ASYNC16Z(sa + ((r * 66 + p) * 8 + (cc ^ (p & 7))) * 16, src, ok ? 16 : 0);
    }
    CP_COMMIT();
    int lrow = lane & 7, msel = lane >> 3;
    int a_pofs = ((msel & 1) << 3) + lrow;
    int a_hi = msel >> 1;
    int lq = lane >> 3;
    float acc[2][8][4];
#pragma unroll
    for (int r = 0; r < 2; r++)
#pragma unroll
        for (int i = 0; i < 8; i++)
#pragma unroll
            for (int j = 0; j < 4; j++) acc[r][i][j] = 0.f;

    for (int tap = 0; tap < 9; tap++) {
        if (tap < 8) {   // prefetch next tap's B
            int buf = (tap + 1) & 1;
#pragma unroll
            for (int j = 0; j < 4; j++) {
                int idx = tid + j * 128;
                int co = idx >> 3, cc = idx & 7;
                CP_ASYNC16(sbq + (buf * 512 + co * 8 + (cc ^ (co & 7))) * 16,
                           g_w2t + (tap + 1) * 4096 + co * 64 + cc * 8);
            }
            CP_COMMIT();
            CP_WAIT1();     // A + current tap's B done; next tap in flight
        } else {
            CP_WAIT0();
        }
        __syncthreads();
        int ky = tap / 3, kx = tap % 3;
        int p = wid * 16 + kx + a_pofs;
        int psw = p & 7;
        int arow0 = (ky * 66 + p) * 8, arow1 = arow0 + 528;
        uint32_t sbt = sbq + (tap & 1) * 512 * 16;
#pragma unroll
        for (int kk = 0; kk < 4; kk++) {
            unsigned a0[4], a1[4];
            int chunk = 2 * kk + a_hi;
            ldsm_x4(a0, sa + (arow0 + (chunk ^ psw)) * 16);
            ldsm_x4(a1, sa + (arow1 + (chunk ^ psw)) * 16);
#pragma unroll
            for (int ntp = 0; ntp < 4; ntp++) {
                int co_b = (2 * ntp + (lq >> 1)) * 8 + lrow;
                int bch = 2 * kk + (lq & 1);
                unsigned br[4];
                ldsm_x4(br, sbt + (co_b * 8 + (bch ^ lrow)) * 16);
                mma_f16(acc[0][2 * ntp],     a0[0], a0[1], a0[2], a0[3], br[0], br[1]);
                mma_f16(acc[0][2 * ntp + 1], a0[0], a0[1], a0[2], a0[3], br[2], br[3]);
                mma_f16(acc[1][2 * ntp],     a1[0], a1[1], a1[2], a1[3], br[0], br[1]);
                mma_f16(acc[1][2 * ntp + 1], a1[0], a1[1], a1[2], a1[3], br[2], br[3]);
            }
        }
        __syncthreads();   // compute done before next prefetch overwrites other buf
    }
    int px1 = x0 + wid * 16 + g;
#pragma unroll
    for (int r = 0; r < 2; r++) {
        int y = y0 + r;
        __half* o1 = g_h2n + ((size_t)(b * HH + y) * WW + px1) * 64;
        __half* o2 = o1 + 8 * 64;
#pragma unroll
        for (int nt = 0; nt < 8; nt++) {
            int n = nt * 8 + 2 * t;
            float b0 = __ldg(bias + n), b1 = __ldg(bias + n + 1);
            *(__half2*)(o1 + n) = __floats2half2_rn(fmaxf(acc[r][nt][0] + b0, 0.f), fmaxf(acc[r][nt][1] + b1, 0.f));
            *(__half2*)(o2 + n) = __floats2half2_rn(fmaxf(acc[r][nt][2] + b0, 0.f), fmaxf(acc[r][nt][3] + b1, 0.f));
        }
    }
}

// ---------------- conv3: 64->2 mma fp16; 4 rows/block, cp.async staging ----------------
// grid (6, 96, 4), 128 thr; dynamic smem (3168+576)*16 = 58.5KB
__global__ __launch_bounds__(128) void conv3_mma(const float* __restrict__ bias) {
    extern __shared__ uint4 dsm3[];
    uint4* s_a  = dsm3;           // [row 6][px 66][chunk 8 swz] = 3168 uint4
    uint4* s_b3 = dsm3 + 3168;    // [tap 9][o 8][chunk 8 swz] = 576 uint4
    int x0 = blockIdx.x * 64, y0 = blockIdx.y * 4, b = blockIdx.z;
    int tid = threadIdx.x, wid = tid >> 5, lane = tid & 31;
    int g = lane >> 2, t = lane & 3;
    uint32_t sa = (uint32_t)__cvta_generic_to_shared(s_a);
    uint32_t sb = (uint32_t)__cvta_generic_to_shared(s_b3);
    for (int idx = tid; idx < 3168; idx += 128) {
        int r = idx / 528, rem = idx % 528, p = rem >> 3, cc = rem & 7;
        int gx = x0 - 1 + p, yy = y0 - 1 + r;
        bool ok = ((unsigned)gx < WW) && ((unsigned)yy < HH);
        const __half* src = g_h2n + ((size_t)(b * HH + (ok ? yy : 0)) * WW + (ok ? gx : 0)) * 64 + cc * 8;
        CP_ASYNC16Z(sa + ((r * 66 + p) * 8 + (cc ^ (p & 7))) * 16, src, ok ? 16 : 0);
    }
    for (int idx = tid; idx < 576; idx += 128) {
        int tap = idx / 64, rem = idx % 64, co = rem >> 3, cc = rem & 7;
        CP_ASYNC16(sb + (tap * 64 + co * 8 + (cc ^ co)) * 16,
                   g_w3t + tap * 512 + co * 64 + cc * 8);
    }
    CP_COMMIT();
    CP_WAIT0();
    __syncthreads();
    int lrow = lane & 7, msel = lane >> 3;
    int a_pofs = ((msel & 1) << 3) + lrow;
    int a_hi = msel >> 1;
    int b_hi = (lane >> 3) & 1;
    float acc[2][2][4];
#pragma unroll
    for (int rp = 0; rp < 2; rp++)
#pragma unroll
        for (int r = 0; r < 2; r++)
#pragma unroll
            for (int j = 0; j < 4; j++) acc[rp][r][j] = 0.f;
#pragma unroll
    for (int rp = 0; rp < 2; rp++)
        for (int ky = 0; ky < 3; ky++)
            for (int kx = 0; kx < 3; kx++) {
                int tap = ky * 3 + kx;
                int p = wid * 16 + kx + a_pofs;
                int psw = p & 7;
                int arow0 = ((2 * rp + ky) * 66 + p) * 8, arow1 = arow0 + 528;
#pragma unroll
                for (int kk = 0; kk < 4; kk++) {
                    unsigned a0[4], a1[4];
                    int chunk = 2 * kk + a_hi;
                    ldsm_x4(a0, sa + (arow0 + (chunk ^ psw)) * 16);
                    ldsm_x4(a1, sa + (arow1 + (chunk ^ psw)) * 16);
                    unsigned b0, b1;
                    int bch = 2 * kk + b_hi;
                    ldsm_x2(b0, b1, sb + (tap * 64 + lrow * 8 + (bch ^ lrow)) * 16);
                    mma_f16(acc[rp][0], a0[0], a0[1], a0[2], a0[3], b0, b1);
                    mma_f16(acc[rp][1], a1[0], a1[1], a1[2], a1[3], b0, b1);
                }
            }
    if (t == 0) {
        float b0 = __ldg(bias + 0), b1 = __ldg(bias + 1);
        int px1 = x0 + wid * 16 + g, px2 = px1 + 8;
#pragma unroll
        for (int rp = 0; rp < 2; rp++)
#pragma unroll
            for (int r = 0; r < 2; r++) {
                int base = (y0 + 2 * rp + r) * WW;
                g_tmp2[(b * 2 + 0) * HW + base + px1] = acc[rp][r][0] + b0;
                g_tmp2[(b * 2 + 1) * HW + base + px1] = acc[rp][r][1] + b1;
                g_tmp2[(b * 2 + 0) * HW + base + px2] = acc[rp][r][2] + b0;
                g_tmp2[(b * 2 + 1) * HW + base + px2] = acc[rp][r][3] + b1;
            }
    }
}

// ---------------- GCN: s^T = (feat @ W1)^T, bf16, coalesced via smem transpose ----------------
__global__ __launch_bounds__(128) void gcn_s_k(const float* __restrict__ in,
                                               const float* __restrict__ W1) {
    __shared__ float w[36 * 64];
    __shared__ __nv_bfloat16 tb[16][136];
    for (int i = threadIdx.x; i < 2304; i += 128) w[i] = W1[i];
    __syncthreads();
    int idx = blockIdx.x * 128 + threadIdx.x;
    int n = idx & 4095, b = (idx >> 12) & 3, c = idx >> 14;
    int n0 = (blockIdx.x * 128) & 4095;
    int gy = n >> 6, gx = n & 63;
    const float* base = in + (b * 2 + c) * HW + (gy * 6) * WW + gx * 6;
    float f[36];
#pragma unroll
    for (int py = 0; py < 6; py++)
#pragma unroll
        for (int px = 0; px < 6; px++) f[py * 6 + px] = __ldg(base + py * WW + px);
    float acc[64];
#pragma unroll
    for (int o = 0; o < 64; o++) acc[o] = 0.f;
#pragma unroll
    for (int ff = 0; ff < 36; ff++) {
        float fv = f[ff];
        const float* wr = &w[ff * 64];
#pragma unroll
        for (int o = 0; o < 64; o++) acc[o] += fv * wr[o];
    }
    int nl = threadIdx.x;
    size_t orow = (size_t)(c * 256 + b * 64);
    for (int ch = 0; ch < 4; ch++) {
        __syncthreads();
#pragma unroll
        for (int o = 0; o < 16; o++) tb[o][nl] = __float2bfloat16(acc[ch * 16 + o]);
        __syncthreads();
        int r = nl >> 3, cw = (nl & 7) * 16;
        const uint4* src = (const uint4*)&tb[r][cw];
        uint4 v0 = src[0], v1 = src[1];
        uint4* dst = (uint4*)(g_st + (orow + ch * 16 + r) * NN + n0 + cw);
        dst[0] = v0; dst[1] = v1;
    }
}

// ---------------- GCN: s3^T = (g @ W3)^T, bf16, coalesced via smem transpose ----------------
__global__ __launch_bounds__(128) void gcn_s3_k(const float* __restrict__ W3) {
    __shared__ float w[64 * 36];
    __shared__ __nv_bfloat16 tb[36][136];
    for (int i = threadIdx.x; i < 2304; i += 128) w[i] = W3[i];
    __syncthreads();
    int idx = blockIdx.x * 128 + threadIdx.x;
    int n = idx & 4095, b = (idx >> 12) & 3, c = idx >> 14;
    int n0 = (blockIdx.x * 128) & 4095;
    const float* gb = g_g + (size_t)(c * NN + n) * 256 + b * 64;
    float acc[36];
#pragma unroll
    for (int o = 0; o < 36; o++) acc[o] = 0.f;
#pragma unroll
    for (int k = 0; k < 64; k += 4) {
        float4 g4 = *(const float4*)(gb + k);
        float gv[4] = {g4.x, g4.y, g4.z, g4.w};
#pragma unroll
        for (int kk = 0; kk < 4; kk++) {
            const float* wr = &w[(k + kk) * 36];
            float gvv = gv[kk];
#pragma unroll
            for (int o = 0; o < 36; o++) acc[o] += gvv * wr[o];
        }
    }
    int nl = threadIdx.x;
#pragma unroll
    for (int o = 0; o < 36; o++) tb[o][nl] = __float2bfloat16(acc[o]);
    __syncthreads();
    size_t orow = (size_t)(c * 144 + b * 36);
    for (int rr = nl; rr < 288; rr += 128) {
        int r = rr >> 3, cw = (rr & 7) * 16;
        const uint4* src = (const uint4*)&tb[r][cw];
        uint4 v0 = src[0], v1 = src[1];
        uint4* dst = (uint4*)(g_s3t + (orow + r) * NN + n0 + cw);
        dst[0] = v0; dst[1] = v1;
    }
}

// ---------------- adj GEMM: 3-stage cp.async pipeline (R10, unchanged) ----------------
__global__ __launch_bounds__(256) void gemm2_k(int which, int Nvalid) {
    __shared__ uint4 sA[3][512];
    __shared__ uint4 sB[3][256];
    int c = blockIdx.z;
    const __nv_bfloat16* A = g_adjb + (size_t)c * NN * NN;
    const __nv_bfloat16* Bm; float* C; int Ncols;
    if (which == 0) { Bm = g_st  + (size_t)c * 256 * NN; C = g_g  + (size_t)c * NN * 256; Ncols = 256; }
    else            { Bm = g_s3t + (size_t)c * 144 * NN; C = g_t3 + (size_t)c * NN * 144; Ncols = 144; }
    int n0 = blockIdx.x * 64, m0 = blockIdx.y * 128;
    int tid = threadIdx.x, wid = tid >> 5, lane = tid & 31;
    int g = lane >> 2, t = lane & 3;
    int wm = (wid >> 1) * 32, wn = (wid & 1) * 32;
    uint32_t sab = (uint32_t)__cvta_generic_to_shared(sA);
    uint32_t sbb = (uint32_t)__cvta_generic_to_shared(sB);

    int arow[2], aswz[2];
#pragma unroll
    for (int f = 0; f < 2; f++) {
        arow[f] = wm + f * 16 + (lane & 7) + ((lane >> 3) & 1) * 8;
        aswz[f] = (arow[f] >> 1) & 3;
    }
    int akc = (lane >> 4) & 1;
    int brow[2], bswz[2];
#pragma unroll
    for (int p = 0; p < 2; p++) {
        brow[p] = wn + p * 16 + (lane & 7) + ((lane >> 4) << 3);
        bswz[p] = (brow[p] >> 1) & 3;
    }
    int bkc = (lane >> 3) & 1;

    float acc[2][4][4];
#pragma unroll
    for (int f = 0; f < 2; f++)
#pragma unroll
        for (int p = 0; p < 4; p++)
#pragma unroll
            for (int j = 0; j < 4; j++) acc[f][p][j] = 0.f;

    auto stage = [&](int buf, int k0) {
#pragma unroll
        for (int idx = tid; idx < 768; idx += 256) {
            if (idx < 512) {
                int r = idx >> 2, cc = idx & 3;
                uint32_t dst = sab + (buf * 512 + r * 4 + (cc ^ ((r >> 1) & 3))) * 16;
                CP_ASYNC16(dst, A + (size_t)(m0 + r) * NN + k0 + cc * 8);
            } else {
                int j = idx - 512;
                int r = j >> 2, cc = j & 3;
                int row = n0 + r; if (row >= Nvalid) row = Nvalid - 1;
                uint32_t dst = sbb + (buf * 256 + r * 4 + (cc ^ ((r >> 1) & 3))) * 16;
                CP_ASYNC16(dst, Bm + (size_t)row * NN + k0 + cc * 8);
            }
        }
        CP_COMMIT();
    };

    const int NIT = NN / 32;
    stage(0, 0);
    stage(1, 32);
    for (int i = 0; i < NIT; i++) {
        if (i + 1 < NIT) CP_WAIT1(); else CP_WAIT0();
        __syncthreads();
        if (i + 2 < NIT) stage((i + 2) % 3, (i + 2) * 32);
        int buf = i % 3;
        uint32_t sa0 = sab + buf * 512 * 16;
        uint32_t sb0 = sbb + buf * 256 * 16;
#pragma unroll
        for (int s = 0; s < 2; s++) {
            unsigned a[2][4];
#pragma unroll
            for (int f = 0; f < 2; f++)
                ldsm_x4(a[f], sa0 + (arow[f] * 4 + ((2 * s + akc) ^ aswz[f])) * 16);
#pragma unroll
            for (int p = 0; p < 2; p++) {
                unsigned br[4];
                ldsm_x4(br, sb0 + (brow[p] * 4 + ((2 * s + bkc) ^ bswz[p])) * 16);
#pragma unroll
                for (int f = 0; f < 2; f++) {
                    mma_bf16(acc[f][2 * p],     a[f][0], a[f][1], a[f][2], a[f][3], br[0], br[1]);
                    mma_bf16(acc[f][2 * p + 1], a[f][0], a[f][1], a[f][2], a[f][3], br[2], br[3]);
                }
            }
        }
    }
#pragma unroll
    for (int f = 0; f < 2; f++) {
        int ra = m0 + wm + f * 16 + g, rb = ra + 8;
#pragma unroll
        for (int p = 0; p < 4; p++) {
            int n = n0 + wn + p * 8 + 2 * t;
            if (n >= Nvalid) continue;
            float v0 = acc[f][p][0], v1 = acc[f][p][1], v2 = acc[f][p][2], v3 = acc[f][p][3];
            if (which == 0) { v0 = fmaxf(v0, 0.f); v1 = fmaxf(v1, 0.f); v2 = fmaxf(v2, 0.f); v3 = fmaxf(v3, 0.f); }
            *(float2*)(C + (size_t)ra * Ncols + n) = make_float2(v0, v1);
            *(float2*)(C + (size_t)rb * Ncols + n) = make_float2(v2, v3);
        }
    }
}

__device__ __forceinline__ float2 cadd(float2 a, float2 b) { return make_float2(a.x + b.x, a.y + b.y); }
__device__ __forceinline__ float2 csub(float2 a, float2 b) { return make_float2(a.x - b.x, a.y - b.y); }

// ---------------- fwd row FFT, 12 coils/block; combine fused at load ----------------
// grid 4*384 (b,y), 384 thr. z = (-1)^(x+y)*(in+(1-a)*tmp2+a*t3)*csm computed in-kernel.
__global__ __launch_bounds__(384) void fwdrow12_k(const float* __restrict__ in,
                                                  const float* __restrict__ arf,
                                                  const float* __restrict__ csr,
                                                  const float* __restrict__ csi) {
    __shared__ float2 sb[12][384];
    int y = blockIdx.x % HH, b = blockIdx.x / HH;
    int tid = threadIdx.x;
    float a = __ldg(arf);
    int gy = y / 6, py = y - gy * 6;
    int gx = tid / 6, px = tid - gx * 6;
    int nnode = gy * 64 + gx, f = py * 6 + px;
    float orr, oii;
    {
        int li0 = (b * 2 + 0) * HW + y * WW + tid;
        int li1 = li0 + HW;
        float t30 = g_t3[(size_t)(0 * NN + nnode) * 144 + b * 36 + f];
        float t31 = g_t3[(size_t)(1 * NN + nnode) * 144 + b * 36 + f];
        orr = in[li0] + (1.f - a) * g_tmp2[li0] + a * t30;
        oii = in[li1] + (1.f - a) * g_tmp2[li1] + a * t31;
    }
    float sgn = ((tid + y) & 1) ? -1.f : 1.f;
    float zr = sgn * orr, zi = sgn * oii;
    int r0 = tid % 3, q0 = tid / 3;
    const float* crb = csr + (size_t)b * CCH * HW + (size_t)y * WW + tid;
    const float* cib = csi + (size_t)b * CCH * HW + (size_t)y * WW + tid;
#pragma unroll
    for (int c = 0; c < CCH; c++) {
        float crv = __ldg(crb + (size_t)c * HW), civ = __ldg(cib + (size_t)c * HW);
        sb[c][r0 * 128 + q0] = make_float2(zr * crv - zi * civ, zr * civ + zi * crv);
    }
    __syncthreads();
#pragma unroll
    for (int len = 128; len >= 2; len >>= 1) {
        int h = len >> 1;
        for (int widx = tid; widx < 2304; widx += 384) {
            int line = widx / 192, bf = widx % 192;
            int seg = bf >> 6, b6 = bf & 63;
            int grp = b6 / h, t = b6 - grp * h;
            int i1 = seg * 128 + grp * len + t;
            float2 u = sb[line][i1], v = sb[line][i1 + h];
            sb[line][i1] = cadd(u, v);
            float2 d = csub(u, v);
            float2 w = g_tw128[t * (128 / len)];
            sb[line][i1 + h] = make_float2(d.x * w.x - d.y * w.y, d.x * w.y + d.y * w.x);
        }
        __syncthreads();
    }
    int k = tid, k0 = k & 127;
    int rv = __brev((unsigned)k0) >> 25;
    float2 c1 = g_tw384[k], c2 = g_tw384[(2 * k) % 384];
#pragma unroll
    for (int c = 0; c < CCH; c++) {
        float2 y0v = sb[c][rv], y1 = sb[c][128 + rv], y2 = sb[c][256 + rv];
        float xr = y0v.x + c1.x * y1.x - c1.y * y1.y + c2.x * y2.x - c2.y * y2.y;
        float xi = y0v.y + c1.x * y1.y + c1.y * y1.x + c2.x * y2.y + c2.y * y2.x;
        g_k[((size_t)(c * BSZ + b)) * HW + (size_t)y * 384 + k] = make_float2(xr, xi);
    }
}

// ---------------- FUSED column pass: fwd FFT -> DC -> inverse FFT ----------------
__global__ __launch_bounds__(192) void fft_col_fused_k(const int* __restrict__ mask,
                                                       const float* __restrict__ tkr,
                                                       const float* __restrict__ tki) {
    __shared__ float2 sb[8 * 384];
    int img = blockIdx.x / 48, cg = blockIdx.x % 48;
    float2* base = g_k + (size_t)img * HW + cg * 8;
    int tid = threadIdx.x;
    for (int i = tid; i < 3072; i += 192) {
        int col = i & 7, yy = i >> 3;
        float2 Z = base[(size_t)yy * 384 + col];
        sb[col * 384 + (yy % 3) * 128 + yy / 3] = Z;
    }
    __syncthreads();
#pragma unroll
    for (int len = 128; len >= 2; len >>= 1) {
        int h = len >> 1;
        for (int widx = tid; widx < 1536; widx += 192) {
            int seg = widx >> 6, bf = widx & 63;
            int boff = (seg / 3) * 384 + (seg % 3) * 128;
            int grp = bf / h, t = bf - grp * h;
            int i1 = boff + grp * len + t;
            float2 u = sb[i1], v = sb[i1 + h];
            sb[i1] = cadd(u, v);
            float2 d = csub(u, v);
            float2 w = g_tw128[t * (128 / len)];
            sb[i1 + h] = make_float2(d.x * w.x - d.y * w.y, d.x * w.y + d.y * w.x);
        }
        __syncthreads();
    }
    float2 val[16];
    for (int ii = 0; ii < 16; ii++) {
        int i = tid + ii * 192;
        int col = i & 7, k = i >> 3;
        int k0 = k & 127;
        int rv = __brev((unsigned)k0) >> 25;
        int cb = col * 384;
        float2 y0 = sb[cb + rv], y1 = sb[cb + 128 + rv], y2 = sb[cb + 256 + rv];
        float2 c1 = g_tw384[k], c2 = g_tw384[(2 * k) % 384];
        float xr = y0.x + c1.x * y1.x - c1.y * y1.y + c2.x * y2.x - c2.y * y2.y;
        float xi = y0.y + c1.x * y1.y + c1.y * y1.x + c2.x * y2.y + c2.y * y2.x;
        int gx = cg * 8 + col;
        int p = k * 384 + gx;
        float mv = (float)__ldg(mask + p);
        float sgn = ((gx + k) & 1) ? -1.f : 1.f;
        float coef = 384.f * 0.999999f * mv * sgn;
        float om = 1.f - mv;
        size_t gidx = (size_t)img * HW + p;
        val[ii] = make_float2(om * xr + coef * __ldg(tkr + gidx),
                              om * xi + coef * __ldg(tki + gidx));
    }
    __syncthreads();
    for (int ii = 0; ii < 16; ii++) {
        int i = tid + ii * 192;
        int col = i & 7, k = i >> 3;
        sb[col * 384 + (k % 3) * 128 + k / 3] = val[ii];
    }
    __syncthreads();
#pragma unroll
    for (int len = 128; len >= 2; len >>= 1) {
        int h = len >> 1;
        for (int widx = tid; widx < 1536; widx += 192) {
            int seg = widx >> 6, bf = widx & 63;
            int boff = (seg / 3) * 384 + (seg % 3) * 128;
            int grp = bf / h, t = bf - grp * h;
            int i1 = boff + grp * len + t;
            float2 u = sb[i1], v = sb[i1 + h];
            sb[i1] = cadd(u, v);
            float2 d = csub(u, v);
            float2 w = g_tw128[t * (128 / len)];
            sb[i1 + h] = make_float2(d.x * w.x + d.y * w.y, -d.x * w.y + d.y * w.x);
        }
        __syncthreads();
    }
    for (int i = tid; i < 3072; i += 192) {
        int col = i & 7, k = i >> 3;
        int k0 = k & 127;
        int rv = __brev((unsigned)k0) >> 25;
        int cb = col * 384;
        float2 y0 = sb[cb + rv], y1 = sb[cb + 128 + rv], y2 = sb[cb + 256 + rv];
        float2 c1 = g_tw384[k], c2 = g_tw384[(2 * k) % 384];
        float s1 = -c1.y, s2 = -c2.y;
        float xr = (y0.x + c1.x * y1.x - s1 * y1.y + c2.x * y2.x - s2 * y2.y) * (1.f / 384.f);
        float xi = (y0.y + c1.x * y1.y + s1 * y1.x + c2.x * y2.y + s2 * y2.x) * (1.f / 384.f);
        base[(size_t)k * 384 + col] = make_float2(xr, xi);
    }
}

// ---------------- fused inverse row FFT (12 coils) + coil combine ----------------
__global__ __launch_bounds__(384) void invrow_final_k(const float* __restrict__ csr,
                                                      const float* __restrict__ csi,
                                                      float* __restrict__ out) {
    __shared__ float2 sb[12][384];
    int y = blockIdx.x % HH, b = blockIdx.x / HH;
    int tid = threadIdx.x;
    int r0 = tid % 3, q0 = tid / 3;
#pragma unroll
    for (int c = 0; c < CCH; c++) {
        float2 z = g_k[((size_t)(c * BSZ + b)) * HW + (size_t)y * 384 + tid];
        sb[c][r0 * 128 + q0] = z;
    }
    __syncthreads();
#pragma unroll
    for (int len = 128; len >= 2; len >>= 1) {
        int h = len >> 1;
        for (int widx = tid; widx < 2304; widx += 384) {
            int line = widx / 192, bf = widx % 192;
            int seg = bf >> 6, b6 = bf & 63;
            int grp = b6 / h, t = b6 - grp * h;
            int i1 = seg * 128 + grp * len + t;
            float2 u = sb[line][i1], v = sb[line][i1 + h];
            sb[line][i1] = cadd(u, v);
            float2 d = csub(u, v);
            float2 w = g_tw128[t * (128 / len)];
            sb[line][i1 + h] = make_float2(d.x * w.x + d.y * w.y, -d.x * w.y + d.y * w.x);
        }
        __syncthreads();
    }
    int k = tid;
    int k0 = k & 127;
    int rv = __brev((unsigned)k0) >> 25;
    float2 c1 = g_tw384[k], c2 = g_tw384[(2 * k) % 384];
    float s1 = -c1.y, s2 = -c2.y;
    float rr = 0.f, ri = 0.f;
    const float* crb = csr + (size_t)b * CCH * HW + (size_t)y * WW + k;
    const float* cib = csi + (size_t)b * CCH * HW + (size_t)y * WW + k;
#pragma unroll
    for (int c = 0; c < CCH; c++) {
        float2 y0 = sb[c][rv], y1 = sb[c][128 + rv], y2 = sb[c][256 + rv];
        float xr = (y0.x + c1.x * y1.x - s1 * y1.y + c2.x * y2.x - s2 * y2.y) * (1.f / 384.f);
        float xi = (y0.y + c1.x * y1.y + s1 * y1.x + c2.x * y2.y + s2 * y2.x) * (1.f / 384.f);
        float cr = __ldg(crb + (size_t)c * HW);
        float ci = __ldg(cib + (size_t)c * HW);
        rr += xr * cr + xi * ci;
        ri += xi * cr - xr * ci;
    }
    float sgn = ((k + y) & 1) ? -1.f : 1.f;
    out[(size_t)(b * 2 + 0) * HW + (size_t)y * WW + k] = sgn * rr;
    out[(size_t)(b * 2 + 1) * HW + (size_t)y * WW + k] = sgn * ri;
}

// ---------------- launch ----------------
extern "C" void kernel_launch(void* const* d_in, const int* in_sizes, int n_in,
                              void* d_out, int out_size) {
    (void)in_sizes; (void)n_in; (void)out_size;
    const float* input = (const float*)d_in[0];
    const float* adj   = (const float*)d_in[1];
    const int*   mask  = (const int*)  d_in[2];
    const float* csr   = (const float*)d_in[3];
    const float* csi   = (const float*)d_in[4];
    const float* tkr   = (const float*)d_in[5];
    const float* tki   = (const float*)d_in[6];
    const float* W1    = (const float*)d_in[7];
    const float* W3    = (const float*)d_in[8];
    const float* arf   = (const float*)d_in[9];
    const float* cw1   = (const float*)d_in[10];
    const float* cb1   = (const float*)d_in[11];
    const float* cw2   = (const float*)d_in[12];
    const float* cb2   = (const float*)d_in[13];
    const float* cw3   = (const float*)d_in[14];
    const float* cb3   = (const float*)d_in[15];
    float* out = (float*)d_out;

    const int CONV2_SMEM = (2112 + 1024) * 16;   // 50176 B
    const int CONV3_SMEM = (3168 + 576) * 16;    // 59904 B
    cudaFuncSetAttribute(conv2_mma, cudaFuncAttributeMaxDynamicSharedMemorySize, CONV2_SMEM);
    cudaFuncSetAttribute(conv3_mma, cudaFuncAttributeMaxDynamicSharedMemorySize, CONV3_SMEM);

    // Order chosen so conv3_mma is launch index 3 (the ncu-captured slot).
    prep_w_k<<<144, 256>>>(cw2, cw3);                        // 0
    conv1_k<<<4608, 256>>>(input, cw1, cb1);                 // 1
    conv2_mma<<<dim3(6, 192, 4), 128, CONV2_SMEM>>>(cb2);    // 2
    conv3_mma<<<dim3(6, 96, 4), 128, CONV3_SMEM>>>(cb3);     // 3  <-- profiled
    gcn_s_k<<<256, 128>>>(input, W1);                        // 4
    adj_cvt_k<<<32768, 256>>>(adj);                          // 5
    gemm2_k<<<dim3(4, 32, 2), 256>>>(0, 256);                // 6
    gcn_s3_k<<<256, 128>>>(W3);                              // 7
    gemm2_k<<<dim3(3, 32, 2), 256>>>(1, 144);                // 8

    // FFT chain (combine fused into fwdrow12)
    init_tw_k<<<1, 384>>>();
    fwdrow12_k<<<4 * 384, 384>>>(input, arf, csr, csi);
    fft_col_fused_k<<<48 * 48, 192>>>(mask, tkr, tki);
    invrow_final_k<<<4 * 384, 384>>>(csr, csi, out);
}

// round 13
// speedup vs baseline: 1.5311x; 1.0222x over previous
#include <cuda_runtime.h>
#include <cuda_fp16.h>
#include <cuda_bf16.h>
#include <math.h>
#include <stdint.h>
#include <stddef.h>

#define BSZ 4
#define CCH 12
#define HH 384
#define WW 384
#define HW (HH*WW)
#define NN 4096

// ---------------- static device scratch (no allocs allowed) ----------------
__device__ __half         g_h1n[(size_t)BSZ*HW*64];   // conv1 out, NHWC fp16
__device__ __half         g_h2n[(size_t)BSZ*HW*64];   // conv2 out, NHWC fp16
__device__ __nv_bfloat16  g_adjb[(size_t)2*NN*NN];    // adj bf16
__device__ __half         g_w2t[9*64*64];             // conv2 w [tap][co][ci]
__device__ __half         g_w3t[9*8*64];              // conv3 w [tap][o pad8][ci]
__device__ __nv_bfloat16  g_st [(size_t)2*256*NN];    // s^T  [c][b*64+o][m]
__device__ __nv_bfloat16  g_s3t[(size_t)2*144*NN];    // s3^T [c][b*36+o][m]
__device__ float          g_t3 [(size_t)2*NN*144];    // adj@s3 [c][m][144]
__device__ float          g_tmp2[BSZ*2*HW];
__device__ float2         g_k[(size_t)CCH*BSZ*HW];
__device__ float2         g_tw128[64];
__device__ float2         g_tw384[384];

// ---------------- mma / ldmatrix / cp.async wrappers ----------------
__device__ __forceinline__ void mma_f16(float c[4], unsigned a0, unsigned a1,
                                        unsigned a2, unsigned a3,
                                        unsigned b0, unsigned b1) {
    asm volatile("mma.sync.aligned.m16n8k16.row.col.f32.f16.f16.f32 "
        "{%0,%1,%2,%3}, {%4,%5,%6,%7}, {%8,%9}, {%0,%1,%2,%3};"
        : "+f"(c[0]), "+f"(c[1]), "+f"(c[2]), "+f"(c[3])
        : "r"(a0), "r"(a1), "r"(a2), "r"(a3), "r"(b0), "r"(b1));
}
__device__ __forceinline__ void mma_bf16(float c[4], unsigned a0, unsigned a1,
                                         unsigned a2, unsigned a3,
                                         unsigned b0, unsigned b1) {
    asm volatile("mma.sync.aligned.m16n8k16.row.col.f32.bf16.bf16.f32 "
        "{%0,%1,%2,%3}, {%4,%5,%6,%7}, {%8,%9}, {%0,%1,%2,%3};"
        : "+f"(c[0]), "+f"(c[1]), "+f"(c[2]), "+f"(c[3])
        : "r"(a0), "r"(a1), "r"(a2), "r"(a3), "r"(b0), "r"(b1));
}
__device__ __forceinline__ void ldsm_x4(unsigned r[4], uint32_t a) {
    asm volatile("ldmatrix.sync.aligned.m8n8.x4.shared.b16 {%0,%1,%2,%3}, [%4];"
        : "=r"(r[0]), "=r"(r[1]), "=r"(r[2]), "=r"(r[3]) : "r"(a));
}
__device__ __forceinline__ void ldsm_x2(unsigned& r0, unsigned& r1, uint32_t a) {
    asm volatile("ldmatrix.sync.aligned.m8n8.x2.shared.b16 {%0,%1}, [%2];"
        : "=r"(r0), "=r"(r1) : "r"(a));
}
#define CP_ASYNC16(dst, src) \
    asm volatile("cp.async.cg.shared.global [%0], [%1], 16;" :: "r"(dst), "l"(src))
#define CP_ASYNC16Z(dst, src, sz) \
    asm volatile("cp.async.cg.shared.global [%0], [%1], 16, %2;" :: "r"(dst), "l"(src), "r"(sz))
#define CP_COMMIT()  asm volatile("cp.async.commit_group;")
#define CP_WAIT0()   asm volatile("cp.async.wait_group 0;")
#define CP_WAIT1()   asm volatile("cp.async.wait_group 1;")

// ---------------- init ----------------
__global__ void init_tw_k() {
    int t = threadIdx.x;
    if (t < 64) { float s, c; sincospif(-(float)t / 64.f, &s, &c);  g_tw128[t] = make_float2(c, s); }
    {            float s, c; sincospif(-(float)t / 192.f, &s, &c); g_tw384[t] = make_float2(c, s); }
}
__global__ void prep_w_k(const float* __restrict__ cw2, const float* __restrict__ cw3) {
    int i = blockIdx.x * 256 + threadIdx.x;
    if (i < 9 * 64 * 64) {
        int tap = i / 4096, r = i % 4096, co = r >> 6, ci = r & 63;
        g_w2t[i] = __float2half(cw2[(co * 64 + ci) * 9 + tap]);
    }
    if (i < 9 * 8 * 64) {
        int tap = i / 512, r = i % 512, o = r >> 6, ci = r & 63;
        g_w3t[i] = __float2half((o < 2) ? cw3[(o * 64 + ci) * 9 + tap] : 0.f);
    }
}
__global__ __launch_bounds__(256) void adj_cvt_k(const float* __restrict__ adj) {
    size_t i = ((size_t)blockIdx.x * 256 + threadIdx.x) * 4;
    float4 v = *(const float4*)(adj + i);
    __nv_bfloat162* o = (__nv_bfloat162*)(g_adjb + i);
    o[0] = __floats2bfloat162_rn(v.x, v.y);
    o[1] = __floats2bfloat162_rn(v.z, v.w);
}

// ---------------- conv1: 2 -> 64, relu; smem-staged input, 4 px x 8 ch/thread ----------------
__global__ __launch_bounds__(256) void conv1_k(const float* __restrict__ in,
                                               const float* __restrict__ w,
                                               const float* __restrict__ bias) {
    __shared__ float ws[18 * 64];        // [q=ci*9+tap][co]
    __shared__ float sIn[2][3][132];     // [ci][row][130 px padded]
    for (int i = threadIdx.x; i < 1152; i += 256) {
        int co = i / 18, q = i % 18;
        ws[q * 64 + co] = w[i];
    }
    int tid = threadIdx.x;
    int cog = tid & 7;
    int pq  = tid >> 3;
    int chunk = blockIdx.x % 3;
    int rowid = blockIdx.x / 3;
    int y = rowid % HH, b = rowid / HH;
    int px_base = chunk * 128;
    int px0 = px_base + pq * 4;
    // stage input rows y-1..y+1, px px_base-1 .. px_base+129 (zero halo)
    for (int i = tid; i < 792; i += 256) {
        int ci = i / 396, rem = i % 396, r = rem / 132, xx = rem % 132;
        int gxx = px_base - 1 + xx;
        int yy = y + r - 1;
        float v = 0.f;
        if (xx < 131 && (unsigned)gxx < WW && (unsigned)yy < HH)
            v = __ldg(in + (b * 2 + ci) * HW + yy * WW + gxx);
        sIn[ci][r][xx] = v;
    }
    __syncthreads();
    float iv[2][3][6];
#pragma unroll
    for (int ci = 0; ci < 2; ci++)
#pragma unroll
        for (int ry = 0; ry < 3; ry++)
#pragma unroll
            for (int cx = 0; cx < 6; cx++)
                iv[ci][ry][cx] = sIn[ci][ry][pq * 4 + cx];
    float acc[4][8];
    float bz[8];
#pragma unroll
    for (int j = 0; j < 8; j++) bz[j] = __ldg(bias + cog * 8 + j);
#pragma unroll
    for (int px = 0; px < 4; px++)
#pragma unroll
        for (int j = 0; j < 8; j++) acc[px][j] = bz[j];
#pragma unroll
    for (int ci = 0; ci < 2; ci++)
#pragma unroll
        for (int ky = 0; ky < 3; ky++)
#pragma unroll
            for (int kx = 0; kx < 3; kx++) {
                int q = ci * 9 + ky * 3 + kx;
                const float4* wp = (const float4*)&ws[q * 64 + cog * 8];
                float4 wa = wp[0], wb = wp[1];
                float w8[8] = {wa.x, wa.y, wa.z, wa.w, wb.x, wb.y, wb.z, wb.w};
#pragma unroll
                for (int px = 0; px < 4; px++) {
                    float v = iv[ci][ky][kx + px];
#pragma unroll
                    for (int j = 0; j < 8; j++) acc[px][j] += v * w8[j];
                }
            }
#pragma unroll
    for (int px = 0; px < 4; px++) {
        size_t p = (size_t)b * HW + (size_t)y * WW + (px0 + px);
        __half2 h4[4];
#pragma unroll
        for (int j = 0; j < 8; j += 2)
            h4[j >> 1] = __floats2half2_rn(fmaxf(acc[px][j], 0.f), fmaxf(acc[px][j + 1], 0.f));
        *(uint4*)(g_h1n + p * 64 + cog * 8) = *(const uint4*)h4;
    }
}

// ---------------- conv2: 64->64 mma fp16; cp.async A + double-buffered B ----------------
__global__ __launch_bounds__(128) void conv2_mma(const float* __restrict__ bias) {
    extern __shared__ uint4 dsm2[];
    uint4* s_a  = dsm2;          // 2112 uint4
    uint4* s_b2 = dsm2 + 2112;   // 1024 uint4
    int x0 = blockIdx.x * 64, y0 = blockIdx.y * 2, b = blockIdx.z;
    int tid = threadIdx.x, wid = tid >> 5, lane = tid & 31;
    int g = lane >> 2, t = lane & 3;
    uint32_t sbq = (uint32_t)__cvta_generic_to_shared(s_b2);
    uint32_t sa = (uint32_t)__cvta_generic_to_shared(s_a);
#pragma unroll
    for (int j = 0; j < 4; j++) {
        int idx = tid + j * 128;
        int co = idx >> 3, cc = idx & 7;
        CP_ASYNC16(sbq + (co * 8 + (cc ^ (co & 7))) * 16, g_w2t + co * 64 + cc * 8);
    }
    CP_COMMIT();
    for (int idx = tid; idx < 2112; idx += 128) {
        int r = idx / 528, rem = idx % 528, p = rem >> 3, cc = rem & 7;
        int gx = x0 - 1 + p, yy = y0 - 1 + r;
        bool ok = ((unsigned)gx < WW) && ((unsigned)yy < HH);
        const __half* src = g_h1n + ((size_t)(b * HH + (ok ? yy : 0)) * WW + (ok ? gx : 0)) * 64 + cc * 8;
        CP_ASYNC16Z(sa + ((r * 66 + p) * 8 + (cc ^ (p & 7))) * 16, src, ok ? 16 : 0);
    }
    CP_COMMIT();
    int lrow = lane & 7, msel = lane >> 3;
    int a_pofs = ((msel & 1) << 3) + lrow;
    int a_hi = msel >> 1;
    int lq = lane >> 3;
    float acc[2][8][4];
#pragma unroll
    for (int r = 0; r < 2; r++)
#pragma unroll
        for (int i = 0; i < 8; i++)
#pragma unroll
            for (int j = 0; j < 4; j++) acc[r][i][j] = 0.f;

    for (int tap = 0; tap < 9; tap++) {
        if (tap < 8) {
            int buf = (tap + 1) & 1;
#pragma unroll
            for (int j = 0; j < 4; j++) {
                int idx = tid + j * 128;
                int co = idx >> 3, cc = idx & 7;
                CP_ASYNC16(sbq + (buf * 512 + co * 8 + (cc ^ (co & 7))) * 16,
                           g_w2t + (tap + 1) * 4096 + co * 64 + cc * 8);
            }
            CP_COMMIT();
            CP_WAIT1();
        } else {
            CP_WAIT0();
        }
        __syncthreads();
        int ky = tap / 3, kx = tap % 3;
        int p = wid * 16 + kx + a_pofs;
        int psw = p & 7;
        int arow0 = (ky * 66 + p) * 8, arow1 = arow0 + 528;
        uint32_t sbt = sbq + (tap & 1) * 512 * 16;
#pragma unroll
        for (int kk = 0; kk < 4; kk++) {
            unsigned a0[4], a1[4];
            int chunk = 2 * kk + a_hi;
            ldsm_x4(a0, sa + (arow0 + (chunk ^ psw)) * 16);
            ldsm_x4(a1, sa + (arow1 + (chunk ^ psw)) * 16);
#pragma unroll
            for (int ntp = 0; ntp < 4; ntp++) {
                int co_b = (2 * ntp + (lq >> 1)) * 8 + lrow;
                int bch = 2 * kk + (lq & 1);
                unsigned br[4];
                ldsm_x4(br, sbt + (co_b * 8 + (bch ^ lrow)) * 16);
                mma_f16(acc[0][2 * ntp],     a0[0], a0[1], a0[2], a0[3], br[0], br[1]);
                mma_f16(acc[0][2 * ntp + 1], a0[0], a0[1], a0[2], a0[3], br[2], br[3]);
                mma_f16(acc[1][2 * ntp],     a1[0], a1[1], a1[2], a1[3], br[0], br[1]);
                mma_f16(acc[1][2 * ntp + 1], a1[0], a1[1], a1[2], a1[3], br[2], br[3]);
            }
        }
        __syncthreads();
    }
    int px1 = x0 + wid * 16 + g;
#pragma unroll
    for (int r = 0; r < 2; r++) {
        int y = y0 + r;
        __half* o1 = g_h2n + ((size_t)(b * HH + y) * WW + px1) * 64;
        __half* o2 = o1 + 8 * 64;
#pragma unroll
        for (int nt = 0; nt < 8; nt++) {
            int n = nt * 8 + 2 * t;
            float b0 = __ldg(bias + n), b1 = __ldg(bias + n + 1);
            *(__half2*)(o1 + n) = __floats2half2_rn(fmaxf(acc[r][nt][0] + b0, 0.f), fmaxf(acc[r][nt][1] + b1, 0.f));
            *(__half2*)(o2 + n) = __floats2half2_rn(fmaxf(acc[r][nt][2] + b0, 0.f), fmaxf(acc[r][nt][3] + b1, 0.f));
        }
    }
}

// ---------------- conv3: 64->2 mma fp16; 4 rows/block, cp.async staging ----------------
__global__ __launch_bounds__(128) void conv3_mma(const float* __restrict__ bias) {
    extern __shared__ uint4 dsm3[];
    uint4* s_a  = dsm3;           // 3168 uint4
    uint4* s_b3 = dsm3 + 3168;    // 576 uint4
    int x0 = blockIdx.x * 64, y0 = blockIdx.y * 4, b = blockIdx.z;
    int tid = threadIdx.x, wid = tid >> 5, lane = tid & 31;
    int g = lane >> 2, t = lane & 3;
    uint32_t sa = (uint32_t)__cvta_generic_to_shared(s_a);
    uint32_t sb = (uint32_t)__cvta_generic_to_shared(s_b3);
    for (int idx = tid; idx < 3168; idx += 128) {
        int r = idx / 528, rem = idx % 528, p = rem >> 3, cc = rem & 7;
        int gx = x0 - 1 + p, yy = y0 - 1 + r;
        bool ok = ((unsigned)gx < WW) && ((unsigned)yy < HH);
        const __half* src = g_h2n + ((size_t)(b * HH + (ok ? yy : 0)) * WW + (ok ? gx : 0)) * 64 + cc * 8;
        CP_ASYNC16Z(sa + ((r * 66 + p) * 8 + (cc ^ (p & 7))) * 16, src, ok ? 16 : 0);
    }
    for (int idx = tid; idx < 576; idx += 128) {
        int tap = idx / 64, rem = idx % 64, co = rem >> 3, cc = rem & 7;
        CP_ASYNC16(sb + (tap * 64 + co * 8 + (cc ^ co)) * 16,
                   g_w3t + tap * 512 + co * 64 + cc * 8);
    }
    CP_COMMIT();
    CP_WAIT0();
    __syncthreads();
    int lrow = lane & 7, msel = lane >> 3;
    int a_pofs = ((msel & 1) << 3) + lrow;
    int a_hi = msel >> 1;
    int b_hi = (lane >> 3) & 1;
    float acc[2][2][4];
#pragma unroll
    for (int rp = 0; rp < 2; rp++)
#pragma unroll
        for (int r = 0; r < 2; r++)
#pragma unroll
            for (int j = 0; j < 4; j++) acc[rp][r][j] = 0.f;
#pragma unroll
    for (int rp = 0; rp < 2; rp++)
        for (int ky = 0; ky < 3; ky++)
            for (int kx = 0; kx < 3; kx++) {
                int tap = ky * 3 + kx;
                int p = wid * 16 + kx + a_pofs;
                int psw = p & 7;
                int arow0 = ((2 * rp + ky) * 66 + p) * 8, arow1 = arow0 + 528;
#pragma unroll
                for (int kk = 0; kk < 4; kk++) {
                    unsigned a0[4], a1[4];
                    int chunk = 2 * kk + a_hi;
                    ldsm_x4(a0, sa + (arow0 + (chunk ^ psw)) * 16);
                    ldsm_x4(a1, sa + (arow1 + (chunk ^ psw)) * 16);
                    unsigned b0, b1;
                    int bch = 2 * kk + b_hi;
                    ldsm_x2(b0, b1, sb + (tap * 64 + lrow * 8 + (bch ^ lrow)) * 16);
                    mma_f16(acc[rp][0], a0[0], a0[1], a0[2], a0[3], b0, b1);
                    mma_f16(acc[rp][1], a1[0], a1[1], a1[2], a1[3], b0, b1);
                }
            }
    if (t == 0) {
        float b0 = __ldg(bias + 0), b1 = __ldg(bias + 1);
        int px1 = x0 + wid * 16 + g, px2 = px1 + 8;
#pragma unroll
        for (int rp = 0; rp < 2; rp++)
#pragma unroll
            for (int r = 0; r < 2; r++) {
                int base = (y0 + 2 * rp + r) * WW;
                g_tmp2[(b * 2 + 0) * HW + base + px1] = acc[rp][r][0] + b0;
                g_tmp2[(b * 2 + 1) * HW + base + px1] = acc[rp][r][1] + b1;
                g_tmp2[(b * 2 + 0) * HW + base + px2] = acc[rp][r][2] + b0;
                g_tmp2[(b * 2 + 1) * HW + base + px2] = acc[rp][r][3] + b1;
            }
    }
}

// ---------------- GCN: s^T = (feat @ W1)^T, bf16, coalesced via smem transpose ----------------
__global__ __launch_bounds__(128) void gcn_s_k(const float* __restrict__ in,
                                               const float* __restrict__ W1) {
    __shared__ float w[36 * 64];
    __shared__ __nv_bfloat16 tb[16][136];
    for (int i = threadIdx.x; i < 2304; i += 128) w[i] = W1[i];
    __syncthreads();
    int idx = blockIdx.x * 128 + threadIdx.x;
    int n = idx & 4095, b = (idx >> 12) & 3, c = idx >> 14;
    int n0 = (blockIdx.x * 128) & 4095;
    int gy = n >> 6, gx = n & 63;
    const float* base = in + (b * 2 + c) * HW + (gy * 6) * WW + gx * 6;
    float f[36];
#pragma unroll
    for (int py = 0; py < 6; py++)
#pragma unroll
        for (int px = 0; px < 6; px++) f[py * 6 + px] = __ldg(base + py * WW + px);
    float acc[64];
#pragma unroll
    for (int o = 0; o < 64; o++) acc[o] = 0.f;
#pragma unroll
    for (int ff = 0; ff < 36; ff++) {
        float fv = f[ff];
        const float* wr = &w[ff * 64];
#pragma unroll
        for (int o = 0; o < 64; o++) acc[o] += fv * wr[o];
    }
    int nl = threadIdx.x;
    size_t orow = (size_t)(c * 256 + b * 64);
    for (int ch = 0; ch < 4; ch++) {
        __syncthreads();
#pragma unroll
        for (int o = 0; o < 16; o++) tb[o][nl] = __float2bfloat16(acc[ch * 16 + o]);
        __syncthreads();
        int r = nl >> 3, cw = (nl & 7) * 16;
        const uint4* src = (const uint4*)&tb[r][cw];
        uint4 v0 = src[0], v1 = src[1];
        uint4* dst = (uint4*)(g_st + (orow + ch * 16 + r) * NN + n0 + cw);
        dst[0] = v0; dst[1] = v1;
    }
}

// ---------------- adj GEMM: 3-stage cp.async pipeline; which=0 fuses relu+W3 proj ----------------
__global__ __launch_bounds__(256) void gemm2_k(int which, int Nvalid, const float* __restrict__ W3) {
    __shared__ uint4 smem_u[3 * 512 + 3 * 256];   // 36KB; reused as g-tile in epilogue
    uint4* sA = smem_u;
    uint4* sB = smem_u + 3 * 512;
    int c = blockIdx.z;
    const __nv_bfloat16* A = g_adjb + (size_t)c * NN * NN;
    const __nv_bfloat16* Bm; float* C; int Ncols;
    if (which == 0) { Bm = g_st  + (size_t)c * 256 * NN; C = nullptr;            Ncols = 256; }
    else            { Bm = g_s3t + (size_t)c * 144 * NN; C = g_t3 + (size_t)c * NN * 144; Ncols = 144; }
    int n0 = blockIdx.x * 64, m0 = blockIdx.y * 128;
    int tid = threadIdx.x, wid = tid >> 5, lane = tid & 31;
    int g = lane >> 2, t = lane & 3;
    int wm = (wid >> 1) * 32, wn = (wid & 1) * 32;
    uint32_t sab = (uint32_t)__cvta_generic_to_shared(sA);
    uint32_t sbb = (uint32_t)__cvta_generic_to_shared(sB);

    int arow[2], aswz[2];
#pragma unroll
    for (int f = 0; f < 2; f++) {
        arow[f] = wm + f * 16 + (lane & 7) + ((lane >> 3) & 1) * 8;
        aswz[f] = (arow[f] >> 1) & 3;
    }
    int akc = (lane >> 4) & 1;
    int brow[2], bswz[2];
#pragma unroll
    for (int p = 0; p < 2; p++) {
        brow[p] = wn + p * 16 + (lane & 7) + ((lane >> 4) << 3);
        bswz[p] = (brow[p] >> 1) & 3;
    }
    int bkc = (lane >> 3) & 1;

    float acc[2][4][4];
#pragma unroll
    for (int f = 0; f < 2; f++)
#pragma unroll
        for (int p = 0; p < 4; p++)
#pragma unroll
            for (int j = 0; j < 4; j++) acc[f][p][j] = 0.f;

    auto stage = [&](int buf, int k0) {
#pragma unroll
        for (int idx = tid; idx < 768; idx += 256) {
            if (idx < 512) {
                int r = idx >> 2, cc = idx & 3;
                uint32_t dst = sab + (buf * 512 + r * 4 + (cc ^ ((r >> 1) & 3))) * 16;
                CP_ASYNC16(dst, A + (size_t)(m0 + r) * NN + k0 + cc * 8);
            } else {
                int j = idx - 512;
                int r = j >> 2, cc = j & 3;
                int row = n0 + r; if (row >= Nvalid) row = Nvalid - 1;
                uint32_t dst = sbb + (buf * 256 + r * 4 + (cc ^ ((r >> 1) & 3))) * 16;
                CP_ASYNC16(dst, Bm + (size_t)row * NN + k0 + cc * 8);
            }
        }
        CP_COMMIT();
    };

    const int NIT = NN / 32;
    stage(0, 0);
    stage(1, 32);
    for (int i = 0; i < NIT; i++) {
        if (i + 1 < NIT) CP_WAIT1(); else CP_WAIT0();
        __syncthreads();
        if (i + 2 < NIT) stage((i + 2) % 3, (i + 2) * 32);
        int buf = i % 3;
        uint32_t sa0 = sab + buf * 512 * 16;
        uint32_t sb0 = sbb + buf * 256 * 16;
#pragma unroll
        for (int s = 0; s < 2; s++) {
            unsigned a[2][4];
#pragma unroll
            for (int f = 0; f < 2; f++)
                ldsm_x4(a[f], sa0 + (arow[f] * 4 + ((2 * s + akc) ^ aswz[f])) * 16);
#pragma unroll
            for (int p = 0; p < 2; p++) {
                unsigned br[4];
                ldsm_x4(br, sb0 + (brow[p] * 4 + ((2 * s + bkc) ^ bswz[p])) * 16);
#pragma unroll
                for (int f = 0; f < 2; f++) {
                    mma_bf16(acc[f][2 * p],     a[f][0], a[f][1], a[f][2], a[f][3], br[0], br[1]);
                    mma_bf16(acc[f][2 * p + 1], a[f][0], a[f][1], a[f][2], a[f][3], br[2], br[3]);
                }
            }
        }
    }
    if (which == 1) {
#pragma unroll
        for (int f = 0; f < 2; f++) {
            int ra = m0 + wm + f * 16 + g, rb = ra + 8;
#pragma unroll
            for (int p = 0; p < 4; p++) {
                int n = n0 + wn + p * 8 + 2 * t;
                if (n >= Nvalid) continue;
                *(float2*)(C + (size_t)ra * Ncols + n) = make_float2(acc[f][p][0], acc[f][p][1]);
                *(float2*)(C + (size_t)rb * Ncols + n) = make_float2(acc[f][p][2], acc[f][p][3]);
            }
        }
        return;
    }
    // ---- which == 0 epilogue: g = relu(acc) -> s3 = g @ W3 -> s3t bf16 ----
    __syncthreads();                        // all ldsm done before smem reuse
    float* gs = (float*)smem_u;             // [128][68] padded
#pragma unroll
    for (int f = 0; f < 2; f++) {
        int ral = wm + f * 16 + g, rbl = ral + 8;
#pragma unroll
        for (int p = 0; p < 4; p++) {
            int nl = wn + p * 8 + 2 * t;
            gs[ral * 68 + nl]     = fmaxf(acc[f][p][0], 0.f);
            gs[ral * 68 + nl + 1] = fmaxf(acc[f][p][1], 0.f);
            gs[rbl * 68 + nl]     = fmaxf(acc[f][p][2], 0.f);
            gs[rbl * 68 + nl + 1] = fmaxf(acc[f][p][3], 0.f);
        }
    }
    __syncthreads();
    int r = tid >> 1, half = tid & 1;
    float accs[18];
#pragma unroll
    for (int o = 0; o < 18; o++) accs[o] = 0.f;
    for (int k = 0; k < 64; k++) {
        float gv = gs[r * 68 + k];
        const float* wr = W3 + k * 36 + half * 18;
#pragma unroll
        for (int o = 0; o < 18; o++) accs[o] += gv * __ldg(wr + o);
    }
    int b = blockIdx.x;                     // n-tile == batch (n0 = b*64)
    size_t rowb = (size_t)(c * 144 + b * 36 + half * 18);
#pragma unroll
    for (int o = 0; o < 18; o++)
        g_s3t[(rowb + o) * NN + m0 + r] = __float2bfloat16(accs[o]);
}

__device__ __forceinline__ float2 cadd(float2 a, float2 b) { return make_float2(a.x + b.x, a.y + b.y); }
__device__ __forceinline__ float2 csub(float2 a, float2 b) { return make_float2(a.x - b.x, a.y - b.y); }

// ---------------- fwd row FFT, 12 coils/block; combine fused at load ----------------
__global__ __launch_bounds__(384) void fwdrow12_k(const float* __restrict__ in,
                                                  const float* __restrict__ arf,
                                                  const float* __restrict__ csr,
                                                  const float* __restrict__ csi) {
    __shared__ float2 sb[12][384];
    int y = blockIdx.x % HH, b = blockIdx.x / HH;
    int tid = threadIdx.x;
    float a = __ldg(arf);
    int gy = y / 6, py = y - gy * 6;
    int gx = tid / 6, px = tid - gx * 6;
    int nnode = gy * 64 + gx, f = py * 6 + px;
    float orr, oii;
    {
        int li0 = (b * 2 + 0) * HW + y * WW + tid;
        int li1 = li0 + HW;
        float t30 = g_t3[(size_t)(0 * NN + nnode) * 144 + b * 36 + f];
        float t31 = g_t3[(size_t)(1 * NN + nnode) * 144 + b * 36 + f];
        orr = in[li0] + (1.f - a) * g_tmp2[li0] + a * t30;
        oii = in[li1] + (1.f - a) * g_tmp2[li1] + a * t31;
    }
    float sgn = ((tid + y) & 1) ? -1.f : 1.f;
    float zr = sgn * orr, zi = sgn * oii;
    int r0 = tid % 3, q0 = tid / 3;
    const float* crb = csr + (size_t)b * CCH * HW + (size_t)y * WW + tid;
    const float* cib = csi + (size_t)b * CCH * HW + (size_t)y * WW + tid;
#pragma unroll
    for (int c = 0; c < CCH; c++) {
        float crv = __ldg(crb + (size_t)c * HW), civ = __ldg(cib + (size_t)c * HW);
        sb[c][r0 * 128 + q0] = make_float2(zr * crv - zi * civ, zr * civ + zi * crv);
    }
    __syncthreads();
#pragma unroll
    for (int len = 128; len >= 2; len >>= 1) {
        int h = len >> 1;
        for (int widx = tid; widx < 2304; widx += 384) {
            int line = widx / 192, bf = widx % 192;
            int seg = bf >> 6, b6 = bf & 63;
            int grp = b6 / h, t = b6 - grp * h;
            int i1 = seg * 128 + grp * len + t;
            float2 u = sb[line][i1], v = sb[line][i1 + h];
            sb[line][i1] = cadd(u, v);
            float2 d = csub(u, v);
            float2 w = g_tw128[t * (128 / len)];
            sb[line][i1 + h] = make_float2(d.x * w.x - d.y * w.y, d.x * w.y + d.y * w.x);
        }
        __syncthreads();
    }
    int k = tid, k0 = k & 127;
    int rv = __brev((unsigned)k0) >> 25;
    float2 c1 = g_tw384[k], c2 = g_tw384[(2 * k) % 384];
#pragma unroll
    for (int c = 0; c < CCH; c++) {
        float2 y0v = sb[c][rv], y1 = sb[c][128 + rv], y2 = sb[c][256 + rv];
        float xr = y0v.x + c1.x * y1.x - c1.y * y1.y + c2.x * y2.x - c2.y * y2.y;
        float xi = y0v.y + c1.x * y1.y + c1.y * y1.x + c2.x * y2.y + c2.y * y2.x;
        g_k[((size_t)(c * BSZ + b)) * HW + (size_t)y * 384 + k] = make_float2(xr, xi);
    }
}

// ---------------- FUSED column pass: fwd FFT -> DC -> inverse FFT ----------------
__global__ __launch_bounds__(192) void fft_col_fused_k(const int* __restrict__ mask,
                                                       const float* __restrict__ tkr,
                                                       const float* __restrict__ tki) {
    __shared__ float2 sb[8 * 384];
    int img = blockIdx.x / 48, cg = blockIdx.x % 48;
    float2* base = g_k + (size_t)img * HW + cg * 8;
    int tid = threadIdx.x;
    for (int i = tid; i < 3072; i += 192) {
        int col = i & 7, yy = i >> 3;
        float2 Z = base[(size_t)yy * 384 + col];
        sb[col * 384 + (yy % 3) * 128 + yy / 3] = Z;
    }
    __syncthreads();
#pragma unroll
    for (int len = 128; len >= 2; len >>= 1) {
        int h = len >> 1;
        for (int widx = tid; widx < 1536; widx += 192) {
            int seg = widx >> 6, bf = widx & 63;
            int boff = (seg / 3) * 384 + (seg % 3) * 128;
            int grp = bf / h, t = bf - grp * h;
            int i1 = boff + grp * len + t;
            float2 u = sb[i1], v = sb[i1 + h];
            sb[i1] = cadd(u, v);
            float2 d = csub(u, v);
            float2 w = g_tw128[t * (128 / len)];
            sb[i1 + h] = make_float2(d.x * w.x - d.y * w.y, d.x * w.y + d.y * w.x);
        }
        __syncthreads();
    }
    float2 val[16];
    for (int ii = 0; ii < 16; ii++) {
        int i = tid + ii * 192;
        int col = i & 7, k = i >> 3;
        int k0 = k & 127;
        int rv = __brev((unsigned)k0) >> 25;
        int cb = col * 384;
        float2 y0 = sb[cb + rv], y1 = sb[cb + 128 + rv], y2 = sb[cb + 256 + rv];
        float2 c1 = g_tw384[k], c2 = g_tw384[(2 * k) % 384];
        float xr = y0.x + c1.x * y1.x - c1.y * y1.y + c2.x * y2.x - c2.y * y2.y;
        float xi = y0.y + c1.x * y1.y + c1.y * y1.x + c2.x * y2.y + c2.y * y2.x;
        int gx = cg * 8 + col;
        int p = k * 384 + gx;
        float mv = (float)__ldg(mask + p);
        float sgn = ((gx + k) & 1) ? -1.f : 1.f;
        float coef = 384.f * 0.999999f * mv * sgn;
        float om = 1.f - mv;
        size_t gidx = (size_t)img * HW + p;
        val[ii] = make_float2(om * xr + coef * __ldg(tkr + gidx),
                              om * xi + coef * __ldg(tki + gidx));
    }
    __syncthreads();
    for (int ii = 0; ii < 16; ii++) {
        int i = tid + ii * 192;
        int col = i & 7, k = i >> 3;
        sb[col * 384 + (k % 3) * 128 + k / 3] = val[ii];
    }
    __syncthreads();
#pragma unroll
    for (int len = 128; len >= 2; len >>= 1) {
        int h = len >> 1;
        for (int widx = tid; widx < 1536; widx += 192) {
            int seg = widx >> 6, bf = widx & 63;
            int boff = (seg / 3) * 384 + (seg % 3) * 128;
            int grp = bf / h, t = bf - grp * h;
            int i1 = boff + grp * len + t;
            float2 u = sb[i1], v = sb[i1 + h];
            sb[i1] = cadd(u, v);
            float2 d = csub(u, v);
            float2 w = g_tw128[t * (128 / len)];
            sb[i1 + h] = make_float2(d.x * w.x + d.y * w.y, -d.x * w.y + d.y * w.x);
        }
        __syncthreads();
    }
    for (int i = tid; i < 3072; i += 192) {
        int col = i & 7, k = i >> 3;
        int k0 = k & 127;
        int rv = __brev((unsigned)k0) >> 25;
        int cb = col * 384;
        float2 y0 = sb[cb + rv], y1 = sb[cb + 128 + rv], y2 = sb[cb + 256 + rv];
        float2 c1 = g_tw384[k], c2 = g_tw384[(2 * k) % 384];
        float s1 = -c1.y, s2 = -c2.y;
        float xr = (y0.x + c1.x * y1.x - s1 * y1.y + c2.x * y2.x - s2 * y2.y) * (1.f / 384.f);
        float xi = (y0.y + c1.x * y1.y + s1 * y1.x + c2.x * y2.y + s2 * y2.x) * (1.f / 384.f);
        base[(size_t)k * 384 + col] = make_float2(xr, xi);
    }
}

// ---------------- fused inverse row FFT (12 coils) + coil combine ----------------
__global__ __launch_bounds__(384) void invrow_final_k(const float* __restrict__ csr,
                                                      const float* __restrict__ csi,
                                                      float* __restrict__ out) {
    __shared__ float2 sb[12][384];
    int y = blockIdx.x % HH, b = blockIdx.x / HH;
    int tid = threadIdx.x;
    int r0 = tid % 3, q0 = tid / 3;
#pragma unroll
    for (int c = 0; c < CCH; c++) {
        float2 z = g_k[((size_t)(c * BSZ + b)) * HW + (size_t)y * 384 + tid];
        sb[c][r0 * 128 + q0] = z;
    }
    __syncthreads();
#pragma unroll
    for (int len = 128; len >= 2; len >>= 1) {
        int h = len >> 1;
        for (int widx = tid; widx < 2304; widx += 384) {
            int line = widx / 192, bf = widx % 192;
            int seg = bf >> 6, b6 = bf & 63;
            int grp = b6 / h, t = b6 - grp * h;
            int i1 = seg * 128 + grp * len + t;
            float2 u = sb[line][i1], v = sb[line][i1 + h];
            sb[line][i1] = cadd(u, v);
            float2 d = csub(u, v);
            float2 w = g_tw128[t * (128 / len)];
            sb[line][i1 + h] = make_float2(d.x * w.x + d.y * w.y, -d.x * w.y + d.y * w.x);
        }
        __syncthreads();
    }
    int k = tid;
    int k0 = k & 127;
    int rv = __brev((unsigned)k0) >> 25;
    float2 c1 = g_tw384[k], c2 = g_tw384[(2 * k) % 384];
    float s1 = -c1.y, s2 = -c2.y;
    float rr = 0.f, ri = 0.f;
    const float* crb = csr + (size_t)b * CCH * HW + (size_t)y * WW + k;
    const float* cib = csi + (size_t)b * CCH * HW + (size_t)y * WW + k;
#pragma unroll
    for (int c = 0; c < CCH; c++) {
        float2 y0 = sb[c][rv], y1 = sb[c][128 + rv], y2 = sb[c][256 + rv];
        float xr = (y0.x + c1.x * y1.x - s1 * y1.y + c2.x * y2.x - s2 * y2.y) * (1.f / 384.f);
        float xi = (y0.y + c1.x * y1.y + s1 * y1.x + c2.x * y2.y + s2 * y2.x) * (1.f / 384.f);
        float cr = __ldg(crb + (size_t)c * HW);
        float ci = __ldg(cib + (size_t)c * HW);
        rr += xr * cr + xi * ci;
        ri += xi * cr - xr * ci;
    }
    float sgn = ((k + y) & 1) ? -1.f : 1.f;
    out[(size_t)(b * 2 + 0) * HW + (size_t)y * WW + k] = sgn * rr;
    out[(size_t)(b * 2 + 1) * HW + (size_t)y * WW + k] = sgn * ri;
}

// ---------------- launch ----------------
extern "C" void kernel_launch(void* const* d_in, const int* in_sizes, int n_in,
                              void* d_out, int out_size) {
    (void)in_sizes; (void)n_in; (void)out_size;
    const float* input = (const float*)d_in[0];
    const float* adj   = (const float*)d_in[1];
    const int*   mask  = (const int*)  d_in[2];
    const float* csr   = (const float*)d_in[3];
    const float* csi   = (const float*)d_in[4];
    const float* tkr   = (const float*)d_in[5];
    const float* tki   = (const float*)d_in[6];
    const float* W1    = (const float*)d_in[7];
    const float* W3    = (const float*)d_in[8];
    const float* arf   = (const float*)d_in[9];
    const float* cw1   = (const float*)d_in[10];
    const float* cb1   = (const float*)d_in[11];
    const float* cw2   = (const float*)d_in[12];
    const float* cb2   = (const float*)d_in[13];
    const float* cw3   = (const float*)d_in[14];
    const float* cb3   = (const float*)d_in[15];
    float* out = (float*)d_out;

    const int CONV2_SMEM = (2112 + 1024) * 16;   // 50176 B
    const int CONV3_SMEM = (3168 + 576) * 16;    // 59904 B
    cudaFuncSetAttribute(conv2_mma, cudaFuncAttributeMaxDynamicSharedMemorySize, CONV2_SMEM);
    cudaFuncSetAttribute(conv3_mma, cudaFuncAttributeMaxDynamicSharedMemorySize, CONV3_SMEM);

    // Order chosen so conv1_k is launch index 3 (the ncu-captured slot).
    prep_w_k<<<144, 256>>>(cw2, cw3);                        // 0
    gcn_s_k<<<256, 128>>>(input, W1);                        // 1
    adj_cvt_k<<<32768, 256>>>(adj);                          // 2
    conv1_k<<<4608, 256>>>(input, cw1, cb1);                 // 3  <-- profiled
    conv2_mma<<<dim3(6, 192, 4), 128, CONV2_SMEM>>>(cb2);    // 4
    conv3_mma<<<dim3(6, 96, 4), 128, CONV3_SMEM>>>(cb3);     // 5
    gemm2_k<<<dim3(4, 32, 2), 256>>>(0, 256, W3);            // 6: g=relu(adj@s), fused s3 proj
    gemm2_k<<<dim3(3, 32, 2), 256>>>(1, 144, nullptr);       // 7: t3 = adj @ s3

    // FFT chain
    init_tw_k<<<1, 384>>>();
    fwdrow12_k<<<4 * 384, 384>>>(input, arf, csr, csi);
    fft_col_fused_k<<<48 * 48, 192>>>(mask, tkr, tki);
    invrow_final_k<<<4 * 384, 384>>>(csr, csi, out);
}

// round 15
// speedup vs baseline: 1.5343x; 1.0021x over previous
#include <cuda_runtime.h>
#include <cuda_fp16.h>
#include <cuda_bf16.h>
#include <math.h>
#include <stdint.h>
#include <stddef.h>

#define BSZ 4
#define CCH 12
#define HH 384
#define WW 384
#define HW (HH*WW)
#define NN 4096

// ---------------- static device scratch (no allocs allowed) ----------------
__device__ __half         g_h1n[(size_t)BSZ*HW*64];   // conv1 out, NHWC fp16
__device__ __half         g_h2n[(size_t)BSZ*HW*64];   // conv2 out, NHWC fp16
__device__ __nv_bfloat16  g_adjb[(size_t)2*NN*NN];    // adj bf16
__device__ __half         g_w2t[9*64*64];             // conv2 w [tap][co][ci]
__device__ __half         g_w3t[9*8*64];              // conv3 w [tap][o pad8][ci]
__device__ __nv_bfloat16  g_st [(size_t)2*256*NN];    // s^T  [c][b*64+o][m]
__device__ __nv_bfloat16  g_s3t[(size_t)2*144*NN];    // s3^T [c][b*36+o][m]
__device__ float          g_t3 [(size_t)2*NN*144];    // adj@s3 [c][m][144]
__device__ float          g_tmp2[BSZ*2*HW];
__device__ __half2        g_k[(size_t)CCH*BSZ*HW];    // k-space, fp16 complex (28MB)
__device__ float2         g_tw128[64];
__device__ float2         g_tw384[384];

// ---------------- mma / ldmatrix / cp.async wrappers ----------------
__device__ __forceinline__ void mma_f16(float c[4], unsigned a0, unsigned a1,
                                        unsigned a2, unsigned a3,
                                        unsigned b0, unsigned b1) {
    asm volatile("mma.sync.aligned.m16n8k16.row.col.f32.f16.f16.f32 "
        "{%0,%1,%2,%3}, {%4,%5,%6,%7}, {%8,%9}, {%0,%1,%2,%3};"
        : "+f"(c[0]), "+f"(c[1]), "+f"(c[2]), "+f"(c[3])
        : "r"(a0), "r"(a1), "r"(a2), "r"(a3), "r"(b0), "r"(b1));
}
__device__ __forceinline__ void mma_bf16(float c[4], unsigned a0, unsigned a1,
                                         unsigned a2, unsigned a3,
                                         unsigned b0, unsigned b1) {
    asm volatile("mma.sync.aligned.m16n8k16.row.col.f32.bf16.bf16.f32 "
        "{%0,%1,%2,%3}, {%4,%5,%6,%7}, {%8,%9}, {%0,%1,%2,%3};"
        : "+f"(c[0]), "+f"(c[1]), "+f"(c[2]), "+f"(c[3])
        : "r"(a0), "r"(a1), "r"(a2), "r"(a3), "r"(b0), "r"(b1));
}
__device__ __forceinline__ void ldsm_x4(unsigned r[4], uint32_t a) {
    asm volatile("ldmatrix.sync.aligned.m8n8.x4.shared.b16 {%0,%1,%2,%3}, [%4];"
        : "=r"(r[0]), "=r"(r[1]), "=r"(r[2]), "=r"(r[3]) : "r"(a));
}
__device__ __forceinline__ void ldsm_x2(unsigned& r0, unsigned& r1, uint32_t a) {
    asm volatile("ldmatrix.sync.aligned.m8n8.x2.shared.b16 {%0,%1}, [%2];"
        : "=r"(r0), "=r"(r1) : "r"(a));
}
#define CP_ASYNC16(dst, src) \
    asm volatile("cp.async.cg.shared.global [%0], [%1], 16;" :: "r"(dst), "l"(src))
#define CP_ASYNC16Z(dst, src, sz) \
    asm volatile("cp.async.cg.shared.global [%0], [%1], 16, %2;" :: "r"(dst), "l"(src), "r"(sz))
#define CP_COMMIT()  asm volatile("cp.async.commit_group;")
#define CP_WAIT0()   asm volatile("cp.async.wait_group 0;")
#define CP_WAIT1()   asm volatile("cp.async.wait_group 1;")

// ---------------- init: weights repack + twiddles (merged) ----------------
__global__ void prep_w_k(const float* __restrict__ cw2, const float* __restrict__ cw3) {
    if (blockIdx.x == 0) {
        int t = threadIdx.x;
        if (t < 64) { float s, c; sincospif(-(float)t / 64.f, &s, &c); g_tw128[t] = make_float2(c, s); }
        for (int u = t; u < 384; u += 256) {
            float s, c; sincospif(-(float)u / 192.f, &s, &c);
            g_tw384[u] = make_float2(c, s);
        }
    }
    int i = blockIdx.x * 256 + threadIdx.x;
    if (i < 9 * 64 * 64) {
        int tap = i / 4096, r = i % 4096, co = r >> 6, ci = r & 63;
        g_w2t[i] = __float2half(cw2[(co * 64 + ci) * 9 + tap]);
    }
    if (i < 9 * 8 * 64) {
        int tap = i / 512, r = i % 512, o = r >> 6, ci = r & 63;
        g_w3t[i] = __float2half((o < 2) ? cw3[(o * 64 + ci) * 9 + tap] : 0.f);
    }
}
__global__ __launch_bounds__(256) void adj_cvt_k(const float* __restrict__ adj) {
    size_t i = ((size_t)blockIdx.x * 256 + threadIdx.x) * 4;
    float4 v = *(const float4*)(adj + i);
    __nv_bfloat162* o = (__nv_bfloat162*)(g_adjb + i);
    o[0] = __floats2bfloat162_rn(v.x, v.y);
    o[1] = __floats2bfloat162_rn(v.z, v.w);
}

// ---------------- conv1: 2 -> 64, relu; smem-staged input, 4 px x 8 ch/thread ----------------
__global__ __launch_bounds__(256) void conv1_k(const float* __restrict__ in,
                                               const float* __restrict__ w,
                                               const float* __restrict__ bias) {
    __shared__ float ws[18 * 64];
    __shared__ float sIn[2][3][132];
    for (int i = threadIdx.x; i < 1152; i += 256) {
        int co = i / 18, q = i % 18;
        ws[q * 64 + co] = w[i];
    }
    int tid = threadIdx.x;
    int cog = tid & 7;
    int pq  = tid >> 3;
    int chunk = blockIdx.x % 3;
    int rowid = blockIdx.x / 3;
    int y = rowid % HH, b = rowid / HH;
    int px_base = chunk * 128;
    int px0 = px_base + pq * 4;
    for (int i = tid; i < 792; i += 256) {
        int ci = i / 396, rem = i % 396, r = rem / 132, xx = rem % 132;
        int gxx = px_base - 1 + xx;
        int yy = y + r - 1;
        float v = 0.f;
        if (xx < 131 && (unsigned)gxx < WW && (unsigned)yy < HH)
            v = __ldg(in + (b * 2 + ci) * HW + yy * WW + gxx);
        sIn[ci][r][xx] = v;
    }
    __syncthreads();
    float iv[2][3][6];
#pragma unroll
    for (int ci = 0; ci < 2; ci++)
#pragma unroll
        for (int ry = 0; ry < 3; ry++)
#pragma unroll
            for (int cx = 0; cx < 6; cx++)
                iv[ci][ry][cx] = sIn[ci][ry][pq * 4 + cx];
    float acc[4][8];
    float bz[8];
#pragma unroll
    for (int j = 0; j < 8; j++) bz[j] = __ldg(bias + cog * 8 + j);
#pragma unroll
    for (int px = 0; px < 4; px++)
#pragma unroll
        for (int j = 0; j < 8; j++) acc[px][j] = bz[j];
#pragma unroll
    for (int ci = 0; ci < 2; ci++)
#pragma unroll
        for (int ky = 0; ky < 3; ky++)
#pragma unroll
            for (int kx = 0; kx < 3; kx++) {
                int q = ci * 9 + ky * 3 + kx;
                const float4* wp = (const float4*)&ws[q * 64 + cog * 8];
                float4 wa = wp[0], wb = wp[1];
                float w8[8] = {wa.x, wa.y, wa.z, wa.w, wb.x, wb.y, wb.z, wb.w};
#pragma unroll
                for (int px = 0; px < 4; px++) {
                    float v = iv[ci][ky][kx + px];
#pragma unroll
                    for (int j = 0; j < 8; j++) acc[px][j] += v * w8[j];
                }
            }
#pragma unroll
    for (int px = 0; px < 4; px++) {
        size_t p = (size_t)b * HW + (size_t)y * WW + (px0 + px);
        __half2 h4[4];
#pragma unroll
        for (int j = 0; j < 8; j += 2)
            h4[j >> 1] = __floats2half2_rn(fmaxf(acc[px][j], 0.f), fmaxf(acc[px][j + 1], 0.f));
        *(uint4*)(g_h1n + p * 64 + cog * 8) = *(const uint4*)h4;
    }
}

// ---------------- conv2: 64->64 mma fp16; 3-buffer B rotation, ONE sync/tap ----------------
// grid (6, 192, 4), 128 thr = 4 warps; 58.4KB dynamic smem -> 3 blocks/SM
__global__ __launch_bounds__(128) void conv2_mma(const float* __restrict__ bias) {
    extern __shared__ uint4 dsm2[];
    uint4* s_a  = dsm2;          // 2112 uint4 (33.8KB)
    uint4* s_b3 = dsm2 + 2112;   // 3 x 512 uint4 (24.6KB)
    int x0 = blockIdx.x * 64, y0 = blockIdx.y * 2, b = blockIdx.z;
    int tid = threadIdx.x, wid = tid >> 5, lane = tid & 31;
    int g = lane >> 2, t = lane & 3;
    uint32_t sbq = (uint32_t)__cvta_generic_to_shared(s_b3);
    uint32_t sa = (uint32_t)__cvta_generic_to_shared(s_a);
    // stage B tap0 (group 0)
#pragma unroll
    for (int j = 0; j < 4; j++) {
        int idx = tid + j * 128;
        int co = idx >> 3, cc = idx & 7;
        CP_ASYNC16(sbq + (co * 8 + (cc ^ (co & 7))) * 16, g_w2t + co * 64 + cc * 8);
    }
    CP_COMMIT();
    // stage A tile (group 1)
    for (int idx = tid; idx < 2112; idx += 128) {
        int r = idx / 528, rem = idx % 528, p = rem >> 3, cc = rem & 7;
        int gx = x0 - 1 + p, yy = y0 - 1 + r;
        bool ok = ((unsigned)gx < WW) && ((unsigned)yy < HH);
        const __half* src = g_h1n + ((size_t)(b * HH + (ok ? yy : 0)) * WW + (ok ? gx : 0)) * 64 + cc * 8;
        CP_ASYNC16Z(sa + ((r * 66 + p) * 8 + (cc ^ (p & 7))) * 16, src, ok ? 16 : 0);
    }
    CP_COMMIT();
    // stage B tap1 (group 2)
#pragma unroll
    for (int j = 0; j < 4; j++) {
        int idx = tid + j * 128;
        int co = idx >> 3, cc = idx & 7;
        CP_ASYNC16(sbq + (512 + co * 8 + (cc ^ (co & 7))) * 16, g_w2t + 4096 + co * 64 + cc * 8);
    }
    CP_COMMIT();
    int lrow = lane & 7, msel = lane >> 3;
    int a_pofs = ((msel & 1) << 3) + lrow;
    int a_hi = msel >> 1;
    int lq = lane >> 3;
    float acc[2][8][4];
#pragma unroll
    for (int r = 0; r < 2; r++)
#pragma unroll
        for (int i = 0; i < 8; i++)
#pragma unroll
            for (int j = 0; j < 4; j++) acc[r][i][j] = 0.f;

    for (int tap = 0; tap < 9; tap++) {
        if (tap < 8) CP_WAIT1(); else CP_WAIT0();
        __syncthreads();               // data ready + prev-tap compute done
        if (tap < 7) {                 // stage B[tap+2] into buf (tap+2)%3
            int buf = (tap + 2) % 3;
#pragma unroll
            for (int j = 0; j < 4; j++) {
                int idx = tid + j * 128;
                int co = idx >> 3, cc = idx & 7;
                CP_ASYNC16(sbq + (buf * 512 + co * 8 + (cc ^ (co & 7))) * 16,
                           g_w2t + (tap + 2) * 4096 + co * 64 + cc * 8);
            }
            CP_COMMIT();
        }
        int ky = tap / 3, kx = tap % 3;
        int p = wid * 16 + kx + a_pofs;
        int psw = p & 7;
        int arow0 = (ky * 66 + p) * 8, arow1 = arow0 + 528;
        uint32_t sbt = sbq + (tap % 3) * 512 * 16;
#pragma unroll
        for (int kk = 0; kk < 4; kk++) {
            unsigned a0[4], a1[4];
            int chunk = 2 * kk + a_hi;
            ldsm_x4(a0, sa + (arow0 + (chunk ^ psw)) * 16);
            ldsm_x4(a1, sa + (arow1 + (chunk ^ psw)) * 16);
#pragma unroll
            for (int ntp = 0; ntp < 4; ntp++) {
                int co_b = (2 * ntp + (lq >> 1)) * 8 + lrow;
                int bch = 2 * kk + (lq & 1);
                unsigned br[4];
                ldsm_x4(br, sbt + (co_b * 8 + (bch ^ lrow)) * 16);
                mma_f16(acc[0][2 * ntp],     a0[0], a0[1], a0[2], a0[3], br[0], br[1]);
                mma_f16(acc[0][2 * ntp + 1], a0[0], a0[1], a0[2], a0[3], br[2], br[3]);
                mma_f16(acc[1][2 * ntp],     a1[0], a1[1], a1[2], a1[3], br[0], br[1]);
                mma_f16(acc[1][2 * ntp + 1], a1[0], a1[1], a1[2], a1[3], br[2], br[3]);
            }
        }
    }
    int px1 = x0 + wid * 16 + g;
#pragma unroll
    for (int r = 0; r < 2; r++) {
        int y = y0 + r;
        __half* o1 = g_h2n + ((size_t)(b * HH + y) * WW + px1) * 64;
        __half* o2 = o1 + 8 * 64;
#pragma unroll
        for (int nt = 0; nt < 8; nt++) {
            int n = nt * 8 + 2 * t;
            float b0 = __ldg(bias + n), b1 = __ldg(bias + n + 1);
            *(__half2*)(o1 + n) = __floats2half2_rn(fmaxf(acc[r][nt][0] + b0, 0.f), fmaxf(acc[r][nt][1] + b1, 0.f));
            *(__half2*)(o2 + n) = __floats2half2_rn(fmaxf(acc[r][nt][2] + b0, 0.f), fmaxf(acc[r][nt][3] + b1, 0.f));
        }
    }
}

// ---------------- conv3: 64->2 mma fp16; 4 rows/block, cp.async staging ----------------
__global__ __launch_bounds__(128) void conv3_mma(const float* __restrict__ bias) {
    extern __shared__ uint4 dsm3[];
    uint4* s_a  = dsm3;           // 3168 uint4
    uint4* s_b3 = dsm3 + 3168;    // 576 uint4
    int x0 = blockIdx.x * 64, y0 = blockIdx.y * 4, b = blockIdx.z;
    int tid = threadIdx.x, wid = tid >> 5, lane = tid & 31;
    int g = lane >> 2, t = lane & 3;
    uint32_t sa = (uint32_t)__cvta_generic_to_shared(s_a);
    uint32_t sb = (uint32_t)__cvta_generic_to_shared(s_b3);
    for (int idx = tid; idx < 3168; idx += 128) {
        int r = idx / 528, rem = idx % 528, p = rem >> 3, cc = rem & 7;
        int gx = x0 - 1 + p, yy = y0 - 1 + r;
        bool ok = ((unsigned)gx < WW) && ((unsigned)yy < HH);
        const __half* src = g_h2n + ((size_t)(b * HH + (ok ? yy : 0)) * WW + (ok ? gx : 0)) * 64 + cc * 8;
        CP_ASYNC16Z(sa + ((r * 66 + p) * 8 + (cc ^ (p & 7))) * 16, src, ok ? 16 : 0);
    }
    for (int idx = tid; idx < 576; idx += 128) {
        int tap = idx / 64, rem = idx % 64, co = rem >> 3, cc = rem & 7;
        CP_ASYNC16(sb + (tap * 64 + co * 8 + (cc ^ co)) * 16,
                   g_w3t + tap * 512 + co * 64 + cc * 8);
    }
    CP_COMMIT();
    CP_WAIT0();
    __syncthreads();
    int lrow = lane & 7, msel = lane >> 3;
    int a_pofs = ((msel & 1) << 3) + lrow;
    int a_hi = msel >> 1;
    int b_hi = (lane >> 3) & 1;
    float acc[2][2][4];
#pragma unroll
    for (int rp = 0; rp < 2; rp++)
#pragma unroll
        for (int r = 0; r < 2; r++)
#pragma unroll
            for (int j = 0; j < 4; j++) acc[rp][r][j] = 0.f;
#pragma unroll
    for (int rp = 0; rp < 2; rp++)
        for (int ky = 0; ky < 3; ky++)
            for (int kx = 0; kx < 3; kx++) {
                int tap = ky * 3 + kx;
                int p = wid * 16 + kx + a_pofs;
                int psw = p & 7;
                int arow0 = ((2 * rp + ky) * 66 + p) * 8, arow1 = arow0 + 528;
#pragma unroll
                for (int kk = 0; kk < 4; kk++) {
                    unsigned a0[4], a1[4];
                    int chunk = 2 * kk + a_hi;
                    ldsm_x4(a0, sa + (arow0 + (chunk ^ psw)) * 16);
                    ldsm_x4(a1, sa + (arow1 + (chunk ^ psw)) * 16);
                    unsigned b0, b1;
                    int bch = 2 * kk + b_hi;
                    ldsm_x2(b0, b1, sb + (tap * 64 + lrow * 8 + (bch ^ lrow)) * 16);
                    mma_f16(acc[rp][0], a0[0], a0[1], a0[2], a0[3], b0, b1);
                    mma_f16(acc[rp][1], a1[0], a1[1], a1[2], a1[3], b0, b1);
                }
            }
    if (t == 0) {
        float b0 = __ldg(bias + 0), b1 = __ldg(bias + 1);
        int px1 = x0 + wid * 16 + g, px2 = px1 + 8;
#pragma unroll
        for (int rp = 0; rp < 2; rp++)
#pragma unroll
            for (int r = 0; r < 2; r++) {
                int base = (y0 + 2 * rp + r) * WW;
                g_tmp2[(b * 2 + 0) * HW + base + px1] = acc[rp][r][0] + b0;
                g_tmp2[(b * 2 + 1) * HW + base + px1] = acc[rp][r][1] + b1;
                g_tmp2[(b * 2 + 0) * HW + base + px2] = acc[rp][r][2] + b0;
                g_tmp2[(b * 2 + 1) * HW + base + px2] = acc[rp][r][3] + b1;
            }
    }
}

// ---------------- GCN: s^T = (feat @ W1)^T, bf16, coalesced via smem transpose ----------------
__global__ __launch_bounds__(128) void gcn_s_k(const float* __restrict__ in,
                                               const float* __restrict__ W1) {
    __shared__ float w[36 * 64];
    __shared__ __nv_bfloat16 tb[16][136];
    for (int i = threadIdx.x; i < 2304; i += 128) w[i] = W1[i];
    __syncthreads();
    int idx = blockIdx.x * 128 + threadIdx.x;
    int n = idx & 4095, b = (idx >> 12) & 3, c = idx >> 14;
    int n0 = (blockIdx.x * 128) & 4095;
    int gy = n >> 6, gx = n & 63;
    const float* base = in + (b * 2 + c) * HW + (gy * 6) * WW + gx * 6;
    float f[36];
#pragma unroll
    for (int py = 0; py < 6; py++)
#pragma unroll
        for (int px = 0; px < 6; px++) f[py * 6 + px] = __ldg(base + py * WW + px);
    float acc[64];
#pragma unroll
    for (int o = 0; o < 64; o++) acc[o] = 0.f;
#pragma unroll
    for (int ff = 0; ff < 36; ff++) {
        float fv = f[ff];
        const float* wr = &w[ff * 64];
#pragma unroll
        for (int o = 0; o < 64; o++) acc[o] += fv * wr[o];
    }
    int nl = threadIdx.x;
    size_t orow = (size_t)(c * 256 + b * 64);
    for (int ch = 0; ch < 4; ch++) {
        __syncthreads();
#pragma unroll
        for (int o = 0; o < 16; o++) tb[o][nl] = __float2bfloat16(acc[ch * 16 + o]);
        __syncthreads();
        int r = nl >> 3, cw = (nl & 7) * 16;
        const uint4* src = (const uint4*)&tb[r][cw];
        uint4 v0 = src[0], v1 = src[1];
        uint4* dst = (uint4*)(g_st + (orow + ch * 16 + r) * NN + n0 + cw);
        dst[0] = v0; dst[1] = v1;
    }
}

// ---------------- adj GEMM: 3-stage cp.async pipeline; which=0 fuses relu+W3 proj ----------------
__global__ __launch_bounds__(256) void gemm2_k(int which, int Nvalid, const float* __restrict__ W3) {
    __shared__ uint4 smem_u[3 * 512 + 3 * 256];
    uint4* sA = smem_u;
    uint4* sB = smem_u + 3 * 512;
    int c = blockIdx.z;
    const __nv_bfloat16* A = g_adjb + (size_t)c * NN * NN;
    const __nv_bfloat16* Bm; float* C; int Ncols;
    if (which == 0) { Bm = g_st  + (size_t)c * 256 * NN; C = nullptr;            Ncols = 256; }
    else            { Bm = g_s3t + (size_t)c * 144 * NN; C = g_t3 + (size_t)c * NN * 144; Ncols = 144; }
    int n0 = blockIdx.x * 64, m0 = blockIdx.y * 128;
    int tid = threadIdx.x, wid = tid >> 5, lane = tid & 31;
    int g = lane >> 2, t = lane & 3;
    int wm = (wid >> 1) * 32, wn = (wid & 1) * 32;
    uint32_t sab = (uint32_t)__cvta_generic_to_shared(sA);
    uint32_t sbb = (uint32_t)__cvta_generic_to_shared(sB);

    int arow[2], aswz[2];
#pragma unroll
    for (int f = 0; f < 2; f++) {
        arow[f] = wm + f * 16 + (lane & 7) + ((lane >> 3) & 1) * 8;
        aswz[f] = (arow[f] >> 1) & 3;
    }
    int akc = (lane >> 4) & 1;
    int brow[2], bswz[2];
#pragma unroll
    for (int p = 0; p < 2; p++) {
        brow[p] = wn + p * 16 + (lane & 7) + ((lane >> 4) << 3);
        bswz[p] = (brow[p] >> 1) & 3;
    }
    int bkc = (lane >> 3) & 1;

    float acc[2][4][4];
#pragma unroll
    for (int f = 0; f < 2; f++)
#pragma unroll
        for (int p = 0; p < 4; p++)
#pragma unroll
            for (int j = 0; j < 4; j++) acc[f][p][j] = 0.f;

    auto stage = [&](int buf, int k0) {
#pragma unroll
        for (int idx = tid; idx < 768; idx += 256) {
            if (idx < 512) {
                int r = idx >> 2, cc = idx & 3;
                uint32_t dst = sab + (buf * 512 + r * 4 + (cc ^ ((r >> 1) & 3))) * 16;
                CP_ASYNC16(dst, A + (size_t)(m0 + r) * NN + k0 + cc * 8);
            } else {
                int j = idx - 512;
                int r = j >> 2, cc = j & 3;
                int row = n0 + r; if (row >= Nvalid) row = Nvalid - 1;
                uint32_t dst = sbb + (buf * 256 + r * 4 + (cc ^ ((r >> 1) & 3))) * 16;
                CP_ASYNC16(dst, Bm + (size_t)row * NN + k0 + cc * 8);
            }
        }
        CP_COMMIT();
    };

    const int NIT = NN / 32;
    stage(0, 0);
    stage(1, 32);
    for (int i = 0; i < NIT; i++) {
        if (i + 1 < NIT) CP_WAIT1(); else CP_WAIT0();
        __syncthreads();
        if (i + 2 < NIT) stage((i + 2) % 3, (i + 2) * 32);
        int buf = i % 3;
        uint32_t sa0 = sab + buf * 512 * 16;
        uint32_t sb0 = sbb + buf * 256 * 16;
#pragma unroll
        for (int s = 0; s < 2; s++) {
            unsigned a[2][4];
#pragma unroll
            for (int f = 0; f < 2; f++)
                ldsm_x4(a[f], sa0 + (arow[f] * 4 + ((2 * s + akc) ^ aswz[f])) * 16);
#pragma unroll
            for (int p = 0; p < 2; p++) {
                unsigned br[4];
                ldsm_x4(br, sb0 + (brow[p] * 4 + ((2 * s + bkc) ^ bswz[p])) * 16);
#pragma unroll
                for (int f = 0; f < 2; f++) {
                    mma_bf16(acc[f][2 * p],     a[f][0], a[f][1], a[f][2], a[f][3], br[0], br[1]);
                    mma_bf16(acc[f][2 * p + 1], a[f][0], a[f][1], a[f][2], a[f][3], br[2], br[3]);
                }
            }
        }
    }
    if (which == 1) {
#pragma unroll
        for (int f = 0; f < 2; f++) {
            int ra = m0 + wm + f * 16 + g, rb = ra + 8;
#pragma unroll
            for (int p = 0; p < 4; p++) {
                int n = n0 + wn + p * 8 + 2 * t;
                if (n >= Nvalid) continue;
                *(float2*)(C + (size_t)ra * Ncols + n) = make_float2(acc[f][p][0], acc[f][p][1]);
                *(float2*)(C + (size_t)rb * Ncols + n) = make_float2(acc[f][p][2], acc[f][p][3]);
            }
        }
        return;
    }
    // ---- which == 0 epilogue: g = relu(acc) -> s3 = g @ W3 -> s3t bf16 ----
    __syncthreads();
    float* gs = (float*)smem_u;             // [128][68] padded
#pragma unroll
    for (int f = 0; f < 2; f++) {
        int ral = wm + f * 16 + g, rbl = ral + 8;
#pragma unroll
        for (int p = 0; p < 4; p++) {
            int nl = wn + p * 8 + 2 * t;
            gs[ral * 68 + nl]     = fmaxf(acc[f][p][0], 0.f);
            gs[ral * 68 + nl + 1] = fmaxf(acc[f][p][1], 0.f);
            gs[rbl * 68 + nl]     = fmaxf(acc[f][p][2], 0.f);
            gs[rbl * 68 + nl + 1] = fmaxf(acc[f][p][3], 0.f);
        }
    }
    __syncthreads();
    int r = tid >> 1, half = tid & 1;
    float accs[18];
#pragma unroll
    for (int o = 0; o < 18; o++) accs[o] = 0.f;
    for (int k = 0; k < 64; k++) {
        float gv = gs[r * 68 + k];
        const float* wr = W3 + k * 36 + half * 18;
#pragma unroll
        for (int o = 0; o < 18; o++) accs[o] += gv * __ldg(wr + o);
    }
    int b = blockIdx.x;
    size_t rowb = (size_t)(c * 144 + b * 36 + half * 18);
#pragma unroll
    for (int o = 0; o < 18; o++)
        g_s3t[(rowb + o) * NN + m0 + r] = __float2bfloat16(accs[o]);
}

__device__ __forceinline__ float2 cadd(float2 a, float2 b) { return make_float2(a.x + b.x, a.y + b.y); }
__device__ __forceinline__ float2 csub(float2 a, float2 b) { return make_float2(a.x - b.x, a.y - b.y); }

// ---------------- fwd row FFT, 12 coils/block; combine fused at load; fp16 out ----------------
__global__ __launch_bounds__(384) void fwdrow12_k(const float* __restrict__ in,
                                                  const float* __restrict__ arf,
                                                  const float* __restrict__ csr,
                                                  const float* __restrict__ csi) {
    __shared__ float2 sb[12][384];
    int y = blockIdx.x % HH, b = blockIdx.x / HH;
    int tid = threadIdx.x;
    float a = __ldg(arf);
    int gy = y / 6, py = y - gy * 6;
    int gx = tid / 6, px = tid - gx * 6;
    int nnode = gy * 64 + gx, f = py * 6 + px;
    float orr, oii;
    {
        int li0 = (b * 2 + 0) * HW + y * WW + tid;
        int li1 = li0 + HW;
        float t30 = g_t3[(size_t)(0 * NN + nnode) * 144 + b * 36 + f];
        float t31 = g_t3[(size_t)(1 * NN + nnode) * 144 + b * 36 + f];
        orr = in[li0] + (1.f - a) * g_tmp2[li0] + a * t30;
        oii = in[li1] + (1.f - a) * g_tmp2[li1] + a * t31;
    }
    float sgn = ((tid + y) & 1) ? -1.f : 1.f;
    float zr = sgn * orr, zi = sgn * oii;
    int r0 = tid % 3, q0 = tid / 3;
    const float* crb = csr + (size_t)b * CCH * HW + (size_t)y * WW + tid;
    const float* cib = csi + (size_t)b * CCH * HW + (size_t)y * WW + tid;
#pragma unroll
    for (int c = 0; c < CCH; c++) {
        float crv = __ldg(crb + (size_t)c * HW), civ = __ldg(cib + (size_t)c * HW);
        sb[c][r0 * 128 + q0] = make_float2(zr * crv - zi * civ, zr * civ + zi * crv);
    }
    __syncthreads();
#pragma unroll
    for (int len = 128; len >= 2; len >>= 1) {
        int h = len >> 1;
        for (int widx = tid; widx < 2304; widx += 384) {
            int line = widx / 192, bf = widx % 192;
            int seg = bf >> 6, b6 = bf & 63;
            int grp = b6 / h, t = b6 - grp * h;
            int i1 = seg * 128 + grp * len + t;
            float2 u = sb[line][i1], v = sb[line][i1 + h];
            sb[line][i1] = cadd(u, v);
            float2 d = csub(u, v);
            float2 w = g_tw128[t * (128 / len)];
            sb[line][i1 + h] = make_float2(d.x * w.x - d.y * w.y, d.x * w.y + d.y * w.x);
        }
        __syncthreads();
    }
    int k = tid, k0 = k & 127;
    int rv = __brev((unsigned)k0) >> 25;
    float2 c1 = g_tw384[k], c2 = g_tw384[(2 * k) % 384];
#pragma unroll
    for (int c = 0; c < CCH; c++) {
        float2 y0v = sb[c][rv], y1 = sb[c][128 + rv], y2 = sb[c][256 + rv];
        float xr = y0v.x + c1.x * y1.x - c1.y * y1.y + c2.x * y2.x - c2.y * y2.y;
        float xi = y0v.y + c1.x * y1.y + c1.y * y1.x + c2.x * y2.y + c2.y * y2.x;
        g_k[((size_t)(c * BSZ + b)) * HW + (size_t)y * 384 + k] = __floats2half2_rn(xr, xi);
    }
}

// ---------------- FUSED column pass: fwd FFT -> DC -> inverse FFT (fp16 io) ----------------
__global__ __launch_bounds__(192) void fft_col_fused_k(const int* __restrict__ mask,
                                                       const float* __restrict__ tkr,
                                                       const float* __restrict__ tki) {
    __shared__ float2 sb[8 * 384];
    int img = blockIdx.x / 48, cg = blockIdx.x % 48;
    __half2* base = g_k + (size_t)img * HW + cg * 8;
    int tid = threadIdx.x;
    for (int i = tid; i < 3072; i += 192) {
        int col = i & 7, yy = i >> 3;
        float2 Z = __half22float2(base[(size_t)yy * 384 + col]);
        sb[col * 384 + (yy % 3) * 128 + yy / 3] = Z;
    }
    __syncthreads();
#pragma unroll
    for (int len = 128; len >= 2; len >>= 1) {
        int h = len >> 1;
        for (int widx = tid; widx < 1536; widx += 192) {
            int seg = widx >> 6, bf = widx & 63;
            int boff = (seg / 3) * 384 + (seg % 3) * 128;
            int grp = bf / h, t = bf - grp * h;
            int i1 = boff + grp * len + t;
            float2 u = sb[i1], v = sb[i1 + h];
            sb[i1] = cadd(u, v);
            float2 d = csub(u, v);
            float2 w = g_tw128[t * (128 / len)];
            sb[i1 + h] = make_float2(d.x * w.x - d.y * w.y, d.x * w.y + d.y * w.x);
        }
        __syncthreads();
    }
    float2 val[16];
    for (int ii = 0; ii < 16; ii++) {
        int i = tid + ii * 192;
        int col = i & 7, k = i >> 3;
        int k0 = k & 127;
        int rv = __brev((unsigned)k0) >> 25;
        int cb = col * 384;
        float2 y0 = sb[cb + rv], y1 = sb[cb + 128 + rv], y2 = sb[cb + 256 + rv];
        float2 c1 = g_tw384[k], c2 = g_tw384[(2 * k) % 384];
        float xr = y0.x + c1.x * y1.x - c1.y * y1.y + c2.x * y2.x - c2.y * y2.y;
        float xi = y0.y + c1.x * y1.y + c1.y * y1.x + c2.x * y2.y + c2.y * y2.x;
        int gx = cg * 8 + col;
        int p = k * 384 + gx;
        float mv = (float)__ldg(mask + p);
        float sgn = ((gx + k) & 1) ? -1.f : 1.f;
        float coef = 384.f * 0.999999f * mv * sgn;
        float om = 1.f - mv;
        size_t gidx = (size_t)img * HW + p;
        val[ii] = make_float2(om * xr + coef * __ldg(tkr + gidx),
                              om * xi + coef * __ldg(tki + gidx));
    }
    __syncthreads();
    for (int ii = 0; ii < 16; ii++) {
        int i = tid + ii * 192;
        int col = i & 7, k = i >> 3;
        sb[col * 384 + (k % 3) * 128 + k / 3] = val[ii];
    }
    __syncthreads();
#pragma unroll
    for (int len = 128; len >= 2; len >>= 1) {
        int h = len >> 1;
        for (int widx = tid; widx < 1536; widx += 192) {
            int seg = widx >> 6, bf = widx & 63;
            int boff = (seg / 3) * 384 + (seg % 3) * 128;
            int grp = bf / h, t = bf - grp * h;
            int i1 = boff + grp * len + t;
            float2 u = sb[i1], v = sb[i1 + h];
            sb[i1] = cadd(u, v);
            float2 d = csub(u, v);
            float2 w = g_tw128[t * (128 / len)];
            sb[i1 + h] = make_float2(d.x * w.x + d.y * w.y, -d.x * w.y + d.y * w.x);
        }
        __syncthreads();
    }
    for (int i = tid; i < 3072; i += 192) {
        int col = i & 7, k = i >> 3;
        int k0 = k & 127;
        int rv = __brev((unsigned)k0) >> 25;
        int cb = col * 384;
        float2 y0 = sb[cb + rv], y1 = sb[cb + 128 + rv], y2 = sb[cb + 256 + rv];
        float2 c1 = g_tw384[k], c2 = g_tw384[(2 * k) % 384];
        float s1 = -c1.y, s2 = -c2.y;
        float xr = (y0.x + c1.x * y1.x - s1 * y1.y + c2.x * y2.x - s2 * y2.y) * (1.f / 384.f);
        float xi = (y0.y + c1.x * y1.y + s1 * y1.x + c2.x * y2.y + s2 * y2.x) * (1.f / 384.f);
        base[(size_t)k * 384 + col] = __floats2half2_rn(xr, xi);
    }
}

// ---------------- fused inverse row FFT (12 coils) + coil combine (fp16 in) ----------------
__global__ __launch_bounds__(384) void invrow_final_k(const float* __restrict__ csr,
                                                      const float* __restrict__ csi,
                                                      float* __restrict__ out) {
    __shared__ float2 sb[12][384];
    int y = blockIdx.x % HH, b = blockIdx.x / HH;
    int tid = threadIdx.x;
    int r0 = tid % 3, q0 = tid / 3;
#pragma unroll
    for (int c = 0; c < CCH; c++) {
        float2 z = __half22float2(g_k[((size_t)(c * BSZ + b)) * HW + (size_t)y * 384 + tid]);
        sb[c][r0 * 128 + q0] = z;
    }
    __syncthreads();
#pragma unroll
    for (int len = 128; len >= 2; len >>= 1) {
        int h = len >> 1;
        for (int widx = tid; widx < 2304; widx += 384) {
            int line = widx / 192, bf = widx % 192;
            int seg = bf >> 6, b6 = bf & 63;
            int grp = b6 / h, t = b6 - grp * h;
            int i1 = seg * 128 + grp * len + t;
            float2 u = sb[line][i1], v = sb[line][i1 + h];
            sb[line][i1] = cadd(u, v);
            float2 d = csub(u, v);
            float2 w = g_tw128[t * (128 / len)];
            sb[line][i1 + h] = make_float2(d.x * w.x + d.y * w.y, -d.x * w.y + d.y * w.x);
        }
        __syncthreads();
    }
    int k = tid;
    int k0 = k & 127;
    int rv = __brev((unsigned)k0) >> 25;
    float2 c1 = g_tw384[k], c2 = g_tw384[(2 * k) % 384];
    float s1 = -c1.y, s2 = -c2.y;
    float rr = 0.f, ri = 0.f;
    const float* crb = csr + (size_t)b * CCH * HW + (size_t)y * WW + k;
    const float* cib = csi + (size_t)b * CCH * HW + (size_t)y * WW + k;
#pragma unroll
    for (int c = 0; c < CCH; c++) {
        float2 y0 = sb[c][rv], y1 = sb[c][128 + rv], y2 = sb[c][256 + rv];
        float xr = (y0.x + c1.x * y1.x - s1 * y1.y + c2.x * y2.x - s2 * y2.y) * (1.f / 384.f);
        float xi = (y0.y + c1.x * y1.y + s1 * y1.x + c2.x * y2.y + s2 * y2.x) * (1.f / 384.f);
        float cr = __ldg(crb + (size_t)c * HW);
        float ci = __ldg(cib + (size_t)c * HW);
        rr += xr * cr + xi * ci;
        ri += xi * cr - xr * ci;
    }
    float sgn = ((k + y) & 1) ? -1.f : 1.f;
    out[(size_t)(b * 2 + 0) * HW + (size_t)y * WW + k] = sgn * rr;
    out[(size_t)(b * 2 + 1) * HW + (size_t)y * WW + k] = sgn * ri;
}

// ---------------- launch ----------------
extern "C" void kernel_launch(void* const* d_in, const int* in_sizes, int n_in,
                              void* d_out, int out_size) {
    (void)in_sizes; (void)n_in; (void)out_size;
    const float* input = (const float*)d_in[0];
    const float* adj   = (const float*)d_in[1];
    const int*   mask  = (const int*)  d_in[2];
    const float* csr   = (const float*)d_in[3];
    const float* csi   = (const float*)d_in[4];
    const float* tkr   = (const float*)d_in[5];
    const float* tki   = (const float*)d_in[6];
    const float* W1    = (const float*)d_in[7];
    const float* W3    = (const float*)d_in[8];
    const float* arf   = (const float*)d_in[9];
    const float* cw1   = (const float*)d_in[10];
    const float* cb1   = (const float*)d_in[11];
    const float* cw2   = (const float*)d_in[12];
    const float* cb2   = (const float*)d_in[13];
    const float* cw3   = (const float*)d_in[14];
    const float* cb3   = (const float*)d_in[15];
    float* out = (float*)d_out;

    const int CONV2_SMEM = (2112 + 1536) * 16;   // 58368 B
    const int CONV3_SMEM = (3168 + 576) * 16;    // 59904 B
    cudaFuncSetAttribute(conv2_mma, cudaFuncAttributeMaxDynamicSharedMemorySize, CONV2_SMEM);
    cudaFuncSetAttribute(conv3_mma, cudaFuncAttributeMaxDynamicSharedMemorySize, CONV3_SMEM);

    // Order chosen so conv2_mma is launch index 3 (the ncu-captured slot).
    prep_w_k<<<144, 256>>>(cw2, cw3);                        // 0 (incl. twiddles)
    conv1_k<<<4608, 256>>>(input, cw1, cb1);                 // 1
    adj_cvt_k<<<32768, 256>>>(adj);                          // 2
    conv2_mma<<<dim3(6, 192, 4), 128, CONV2_SMEM>>>(cb2);    // 3  <-- profiled
    gcn_s_k<<<256, 128>>>(input, W1);                        // 4
    conv3_mma<<<dim3(6, 96, 4), 128, CONV3_SMEM>>>(cb3);     // 5
    gemm2_k<<<dim3(4, 32, 2), 256>>>(0, 256, W3);            // 6
    gemm2_k<<<dim3(3, 32, 2), 256>>>(1, 144, nullptr);       // 7

    // FFT chain
    fwdrow12_k<<<4 * 384, 384>>>(input, arf, csr, csi);      // 8
    fft_col_fused_k<<<48 * 48, 192>>>(mask, tkr, tki);       // 9
    invrow_final_k<<<4 * 384, 384>>>(csr, csi, out);         // 10
}

// round 16
// speedup vs baseline: 1.5975x; 1.0412x over previous
#include <cuda_runtime.h>
#include <cuda_fp16.h>
#include <cuda_bf16.h>
#include <math.h>
#include <stdint.h>
#include <stddef.h>

#define BSZ 4
#define CCH 12
#define HH 384
#define WW 384
#define HW (HH*WW)
#define NN 4096

// ---------------- static device scratch (no allocs allowed) ----------------
__device__ __half         g_h1n[(size_t)BSZ*HW*64];   // conv1 out, NHWC fp16
__device__ __half         g_h2n[(size_t)BSZ*HW*64];   // conv2 out, NHWC fp16
__device__ __nv_bfloat16  g_adjb[(size_t)2*NN*NN];    // adj bf16
__device__ __half         g_w2t[9*64*64];             // conv2 w [tap][co][ci]
__device__ __half         g_w3t[9*8*64];              // conv3 w [tap][o pad8][ci]
__device__ __nv_bfloat16  g_st [(size_t)2*256*NN];    // s^T  [c][b*64+o][m]
__device__ __nv_bfloat16  g_s3t[(size_t)2*144*NN];    // s3^T [c][b*36+o][m]
__device__ float          g_t3 [(size_t)2*NN*144];    // adj@s3 [c][m][144]
__device__ float          g_tmp2[BSZ*2*HW];
__device__ __half2        g_k[(size_t)CCH*BSZ*HW];    // k-space, fp16 complex (28MB)
__device__ float2         g_tw128[64];
__device__ float2         g_tw384[384];

// ---------------- mma / ldmatrix / cp.async wrappers ----------------
__device__ __forceinline__ void mma_f16(float c[4], unsigned a0, unsigned a1,
                                        unsigned a2, unsigned a3,
                                        unsigned b0, unsigned b1) {
    asm volatile("mma.sync.aligned.m16n8k16.row.col.f32.f16.f16.f32 "
        "{%0,%1,%2,%3}, {%4,%5,%6,%7}, {%8,%9}, {%0,%1,%2,%3};"
        : "+f"(c[0]), "+f"(c[1]), "+f"(c[2]), "+f"(c[3])
        : "r"(a0), "r"(a1), "r"(a2), "r"(a3), "r"(b0), "r"(b1));
}
__device__ __forceinline__ void mma_bf16(float c[4], unsigned a0, unsigned a1,
                                         unsigned a2, unsigned a3,
                                         unsigned b0, unsigned b1) {
    asm volatile("mma.sync.aligned.m16n8k16.row.col.f32.bf16.bf16.f32 "
        "{%0,%1,%2,%3}, {%4,%5,%6,%7}, {%8,%9}, {%0,%1,%2,%3};"
        : "+f"(c[0]), "+f"(c[1]), "+f"(c[2]), "+f"(c[3])
        : "r"(a0), "r"(a1), "r"(a2), "r"(a3), "r"(b0), "r"(b1));
}
__device__ __forceinline__ void ldsm_x4(unsigned r[4], uint32_t a) {
    asm volatile("ldmatrix.sync.aligned.m8n8.x4.shared.b16 {%0,%1,%2,%3}, [%4];"
        : "=r"(r[0]), "=r"(r[1]), "=r"(r[2]), "=r"(r[3]) : "r"(a));
}
__device__ __forceinline__ void ldsm_x2(unsigned& r0, unsigned& r1, uint32_t a) {
    asm volatile("ldmatrix.sync.aligned.m8n8.x2.shared.b16 {%0,%1}, [%2];"
        : "=r"(r0), "=r"(r1) : "r"(a));
}
#define CP_ASYNC16(dst, src) \
    asm volatile("cp.async.cg.shared.global [%0], [%1], 16;" :: "r"(dst), "l"(src))
#define CP_ASYNC16Z(dst, src, sz) \
    asm volatile("cp.async.cg.shared.global [%0], [%1], 16, %2;" :: "r"(dst), "l"(src), "r"(sz))
#define CP_COMMIT()  asm volatile("cp.async.commit_group;")
#define CP_WAIT0()   asm volatile("cp.async.wait_group 0;")
#define CP_WAIT1()   asm volatile("cp.async.wait_group 1;")

// ---------------- init: weights repack + twiddles (merged) ----------------
__global__ void prep_w_k(const float* __restrict__ cw2, const float* __restrict__ cw3) {
    if (blockIdx.x == 0) {
        int t = threadIdx.x;
        if (t < 64) { float s, c; sincospif(-(float)t / 64.f, &s, &c); g_tw128[t] = make_float2(c, s); }
        for (int u = t; u < 384; u += 256) {
            float s, c; sincospif(-(float)u / 192.f, &s, &c);
            g_tw384[u] = make_float2(c, s);
        }
    }
    int i = blockIdx.x * 256 + threadIdx.x;
    if (i < 9 * 64 * 64) {
        int tap = i / 4096, r = i % 4096, co = r >> 6, ci = r & 63;
        g_w2t[i] = __float2half(cw2[(co * 64 + ci) * 9 + tap]);
    }
    if (i < 9 * 8 * 64) {
        int tap = i / 512, r = i % 512, o = r >> 6, ci = r & 63;
        g_w3t[i] = __float2half((o < 2) ? cw3[(o * 64 + ci) * 9 + tap] : 0.f);
    }
}
__global__ __launch_bounds__(256) void adj_cvt_k(const float* __restrict__ adj) {
    size_t i = ((size_t)blockIdx.x * 256 + threadIdx.x) * 4;
    float4 v = *(const float4*)(adj + i);
    __nv_bfloat162* o = (__nv_bfloat162*)(g_adjb + i);
    o[0] = __floats2bfloat162_rn(v.x, v.y);
    o[1] = __floats2bfloat162_rn(v.z, v.w);
}

// ---------------- conv1: 2 -> 64, relu; smem-staged input, 4 px x 8 ch/thread ----------------
__global__ __launch_bounds__(256) void conv1_k(const float* __restrict__ in,
                                               const float* __restrict__ w,
                                               const float* __restrict__ bias) {
    __shared__ float ws[18 * 64];
    __shared__ float sIn[2][3][132];
    for (int i = threadIdx.x; i < 1152; i += 256) {
        int co = i / 18, q = i % 18;
        ws[q * 64 + co] = w[i];
    }
    int tid = threadIdx.x;
    int cog = tid & 7;
    int pq  = tid >> 3;
    int chunk = blockIdx.x % 3;
    int rowid = blockIdx.x / 3;
    int y = rowid % HH, b = rowid / HH;
    int px_base = chunk * 128;
    int px0 = px_base + pq * 4;
    for (int i = tid; i < 792; i += 256) {
        int ci = i / 396, rem = i % 396, r = rem / 132, xx = rem % 132;
        int gxx = px_base - 1 + xx;
        int yy = y + r - 1;
        float v = 0.f;
        if (xx < 131 && (unsigned)gxx < WW && (unsigned)yy < HH)
            v = __ldg(in + (b * 2 + ci) * HW + yy * WW + gxx);
        sIn[ci][r][xx] = v;
    }
    __syncthreads();
    float iv[2][3][6];
#pragma unroll
    for (int ci = 0; ci < 2; ci++)
#pragma unroll
        for (int ry = 0; ry < 3; ry++)
#pragma unroll
            for (int cx = 0; cx < 6; cx++)
                iv[ci][ry][cx] = sIn[ci][ry][pq * 4 + cx];
    float acc[4][8];
    float bz[8];
#pragma unroll
    for (int j = 0; j < 8; j++) bz[j] = __ldg(bias + cog * 8 + j);
#pragma unroll
    for (int px = 0; px < 4; px++)
#pragma unroll
        for (int j = 0; j < 8; j++) acc[px][j] = bz[j];
#pragma unroll
    for (int ci = 0; ci < 2; ci++)
#pragma unroll
        for (int ky = 0; ky < 3; ky++)
#pragma unroll
            for (int kx = 0; kx < 3; kx++) {
                int q = ci * 9 + ky * 3 + kx;
                const float4* wp = (const float4*)&ws[q * 64 + cog * 8];
                float4 wa = wp[0], wb = wp[1];
                float w8[8] = {wa.x, wa.y, wa.z, wa.w, wb.x, wb.y, wb.z, wb.w};
#pragma unroll
                for (int px = 0; px < 4; px++) {
                    float v = iv[ci][ky][kx + px];
#pragma unroll
                    for (int j = 0; j < 8; j++) acc[px][j] += v * w8[j];
                }
            }
#pragma unroll
    for (int px = 0; px < 4; px++) {
        size_t p = (size_t)b * HW + (size_t)y * WW + (px0 + px);
        __half2 h4[4];
#pragma unroll
        for (int j = 0; j < 8; j += 2)
            h4[j >> 1] = __floats2half2_rn(fmaxf(acc[px][j], 0.f), fmaxf(acc[px][j + 1], 0.f));
        *(uint4*)(g_h1n + p * 64 + cog * 8) = *(const uint4*)h4;
    }
}

// ---------------- conv2: 64->64 mma fp16; 3-buffer B rotation, ONE sync/tap ----------------
__global__ __launch_bounds__(128) void conv2_mma(const float* __restrict__ bias) {
    extern __shared__ uint4 dsm2[];
    uint4* s_a  = dsm2;          // 2112 uint4 (33.8KB)
    uint4* s_b3 = dsm2 + 2112;   // 3 x 512 uint4 (24.6KB)
    int x0 = blockIdx.x * 64, y0 = blockIdx.y * 2, b = blockIdx.z;
    int tid = threadIdx.x, wid = tid >> 5, lane = tid & 31;
    int g = lane >> 2, t = lane & 3;
    uint32_t sbq = (uint32_t)__cvta_generic_to_shared(s_b3);
    uint32_t sa = (uint32_t)__cvta_generic_to_shared(s_a);
#pragma unroll
    for (int j = 0; j < 4; j++) {
        int idx = tid + j * 128;
        int co = idx >> 3, cc = idx & 7;
        CP_ASYNC16(sbq + (co * 8 + (cc ^ (co & 7))) * 16, g_w2t + co * 64 + cc * 8);
    }
    CP_COMMIT();
    for (int idx = tid; idx < 2112; idx += 128) {
        int r = idx / 528, rem = idx % 528, p = rem >> 3, cc = rem & 7;
        int gx = x0 - 1 + p, yy = y0 - 1 + r;
        bool ok = ((unsigned)gx < WW) && ((unsigned)yy < HH);
        const __half* src = g_h1n + ((size_t)(b * HH + (ok ? yy : 0)) * WW + (ok ? gx : 0)) * 64 + cc * 8;
        CP_ASYNC16Z(sa + ((r * 66 + p) * 8 + (cc ^ (p & 7))) * 16, src, ok ? 16 : 0);
    }
    CP_COMMIT();
#pragma unroll
    for (int j = 0; j < 4; j++) {
        int idx = tid + j * 128;
        int co = idx >> 3, cc = idx & 7;
        CP_ASYNC16(sbq + (512 + co * 8 + (cc ^ (co & 7))) * 16, g_w2t + 4096 + co * 64 + cc * 8);
    }
    CP_COMMIT();
    int lrow = lane & 7, msel = lane >> 3;
    int a_pofs = ((msel & 1) << 3) + lrow;
    int a_hi = msel >> 1;
    int lq = lane >> 3;
    float acc[2][8][4];
#pragma unroll
    for (int r = 0; r < 2; r++)
#pragma unroll
        for (int i = 0; i < 8; i++)
#pragma unroll
            for (int j = 0; j < 4; j++) acc[r][i][j] = 0.f;

    for (int tap = 0; tap < 9; tap++) {
        if (tap < 8) CP_WAIT1(); else CP_WAIT0();
        __syncthreads();
        if (tap < 7) {
            int buf = (tap + 2) % 3;
#pragma unroll
            for (int j = 0; j < 4; j++) {
                int idx = tid + j * 128;
                int co = idx >> 3, cc = idx & 7;
                CP_ASYNC16(sbq + (buf * 512 + co * 8 + (cc ^ (co & 7))) * 16,
                           g_w2t + (tap + 2) * 4096 + co * 64 + cc * 8);
            }
            CP_COMMIT();
        }
        int ky = tap / 3, kx = tap % 3;
        int p = wid * 16 + kx + a_pofs;
        int psw = p & 7;
        int arow0 = (ky * 66 + p) * 8, arow1 = arow0 + 528;
        uint32_t sbt = sbq + (tap % 3) * 512 * 16;
#pragma unroll
        for (int kk = 0; kk < 4; kk++) {
            unsigned a0[4], a1[4];
            int chunk = 2 * kk + a_hi;
            ldsm_x4(a0, sa + (arow0 + (chunk ^ psw)) * 16);
            ldsm_x4(a1, sa + (arow1 + (chunk ^ psw)) * 16);
#pragma unroll
            for (int ntp = 0; ntp < 4; ntp++) {
                int co_b = (2 * ntp + (lq >> 1)) * 8 + lrow;
                int bch = 2 * kk + (lq & 1);
                unsigned br[4];
                ldsm_x4(br, sbt + (co_b * 8 + (bch ^ lrow)) * 16);
                mma_f16(acc[0][2 * ntp],     a0[0], a0[1], a0[2], a0[3], br[0], br[1]);
                mma_f16(acc[0][2 * ntp + 1], a0[0], a0[1], a0[2], a0[3], br[2], br[3]);
                mma_f16(acc[1][2 * ntp],     a1[0], a1[1], a1[2], a1[3], br[0], br[1]);
                mma_f16(acc[1][2 * ntp + 1], a1[0], a1[1], a1[2], a1[3], br[2], br[3]);
            }
        }
    }
    int px1 = x0 + wid * 16 + g;
#pragma unroll
    for (int r = 0; r < 2; r++) {
        int y = y0 + r;
        __half* o1 = g_h2n + ((size_t)(b * HH + y) * WW + px1) * 64;
        __half* o2 = o1 + 8 * 64;
#pragma unroll
        for (int nt = 0; nt < 8; nt++) {
            int n = nt * 8 + 2 * t;
            float b0 = __ldg(bias + n), b1 = __ldg(bias + n + 1);
            *(__half2*)(o1 + n) = __floats2half2_rn(fmaxf(acc[r][nt][0] + b0, 0.f), fmaxf(acc[r][nt][1] + b1, 0.f));
            *(__half2*)(o2 + n) = __floats2half2_rn(fmaxf(acc[r][nt][2] + b0, 0.f), fmaxf(acc[r][nt][3] + b1, 0.f));
        }
    }
}

// ---------------- conv3: 64->2 mma fp16; 4 rows/block, cp.async staging ----------------
__global__ __launch_bounds__(128) void conv3_mma(const float* __restrict__ bias) {
    extern __shared__ uint4 dsm3[];
    uint4* s_a  = dsm3;
    uint4* s_b3 = dsm3 + 3168;
    int x0 = blockIdx.x * 64, y0 = blockIdx.y * 4, b = blockIdx.z;
    int tid = threadIdx.x, wid = tid >> 5, lane = tid & 31;
    int g = lane >> 2, t = lane & 3;
    uint32_t sa = (uint32_t)__cvta_generic_to_shared(s_a);
    uint32_t sb = (uint32_t)__cvta_generic_to_shared(s_b3);
    for (int idx = tid; idx < 3168; idx += 128) {
        int r = idx / 528, rem = idx % 528, p = rem >> 3, cc = rem & 7;
        int gx = x0 - 1 + p, yy = y0 - 1 + r;
        bool ok = ((unsigned)gx < WW) && ((unsigned)yy < HH);
        const __half* src = g_h2n + ((size_t)(b * HH + (ok ? yy : 0)) * WW + (ok ? gx : 0)) * 64 + cc * 8;
        CP_ASYNC16Z(sa + ((r * 66 + p) * 8 + (cc ^ (p & 7))) * 16, src, ok ? 16 : 0);
    }
    for (int idx = tid; idx < 576; idx += 128) {
        int tap = idx / 64, rem = idx % 64, co = rem >> 3, cc = rem & 7;
        CP_ASYNC16(sb + (tap * 64 + co * 8 + (cc ^ co)) * 16,
                   g_w3t + tap * 512 + co * 64 + cc * 8);
    }
    CP_COMMIT();
    CP_WAIT0();
    __syncthreads();
    int lrow = lane & 7, msel = lane >> 3;
    int a_pofs = ((msel & 1) << 3) + lrow;
    int a_hi = msel >> 1;
    int b_hi = (lane >> 3) & 1;
    float acc[2][2][4];
#pragma unroll
    for (int rp = 0; rp < 2; rp++)
#pragma unroll
        for (int r = 0; r < 2; r++)
#pragma unroll
            for (int j = 0; j < 4; j++) acc[rp][r][j] = 0.f;
#pragma unroll
    for (int rp = 0; rp < 2; rp++)
        for (int ky = 0; ky < 3; ky++)
            for (int kx = 0; kx < 3; kx++) {
                int tap = ky * 3 + kx;
                int p = wid * 16 + kx + a_pofs;
                int psw = p & 7;
                int arow0 = ((2 * rp + ky) * 66 + p) * 8, arow1 = arow0 + 528;
#pragma unroll
                for (int kk = 0; kk < 4; kk++) {
                    unsigned a0[4], a1[4];
                    int chunk = 2 * kk + a_hi;
                    ldsm_x4(a0, sa + (arow0 + (chunk ^ psw)) * 16);
                    ldsm_x4(a1, sa + (arow1 + (chunk ^ psw)) * 16);
                    unsigned b0, b1;
                    int bch = 2 * kk + b_hi;
                    ldsm_x2(b0, b1, sb + (tap * 64 + lrow * 8 + (bch ^ lrow)) * 16);
                    mma_f16(acc[rp][0], a0[0], a0[1], a0[2], a0[3], b0, b1);
                    mma_f16(acc[rp][1], a1[0], a1[1], a1[2], a1[3], b0, b1);
                }
            }
    if (t == 0) {
        float b0 = __ldg(bias + 0), b1 = __ldg(bias + 1);
        int px1 = x0 + wid * 16 + g, px2 = px1 + 8;
#pragma unroll
        for (int rp = 0; rp < 2; rp++)
#pragma unroll
            for (int r = 0; r < 2; r++) {
                int base = (y0 + 2 * rp + r) * WW;
                g_tmp2[(b * 2 + 0) * HW + base + px1] = acc[rp][r][0] + b0;
                g_tmp2[(b * 2 + 1) * HW + base + px1] = acc[rp][r][1] + b1;
                g_tmp2[(b * 2 + 0) * HW + base + px2] = acc[rp][r][2] + b0;
                g_tmp2[(b * 2 + 1) * HW + base + px2] = acc[rp][r][3] + b1;
            }
    }
}

// ---------------- GCN: s^T = (feat @ W1)^T, bf16, coalesced via smem transpose ----------------
__global__ __launch_bounds__(128) void gcn_s_k(const float* __restrict__ in,
                                               const float* __restrict__ W1) {
    __shared__ float w[36 * 64];
    __shared__ __nv_bfloat16 tb[16][136];
    for (int i = threadIdx.x; i < 2304; i += 128) w[i] = W1[i];
    __syncthreads();
    int idx = blockIdx.x * 128 + threadIdx.x;
    int n = idx & 4095, b = (idx >> 12) & 3, c = idx >> 14;
    int n0 = (blockIdx.x * 128) & 4095;
    int gy = n >> 6, gx = n & 63;
    const float* base = in + (b * 2 + c) * HW + (gy * 6) * WW + gx * 6;
    float f[36];
#pragma unroll
    for (int py = 0; py < 6; py++)
#pragma unroll
        for (int px = 0; px < 6; px++) f[py * 6 + px] = __ldg(base + py * WW + px);
    float acc[64];
#pragma unroll
    for (int o = 0; o < 64; o++) acc[o] = 0.f;
#pragma unroll
    for (int ff = 0; ff < 36; ff++) {
        float fv = f[ff];
        const float* wr = &w[ff * 64];
#pragma unroll
        for (int o = 0; o < 64; o++) acc[o] += fv * wr[o];
    }
    int nl = threadIdx.x;
    size_t orow = (size_t)(c * 256 + b * 64);
    for (int ch = 0; ch < 4; ch++) {
        __syncthreads();
#pragma unroll
        for (int o = 0; o < 16; o++) tb[o][nl] = __float2bfloat16(acc[ch * 16 + o]);
        __syncthreads();
        int r = nl >> 3, cw = (nl & 7) * 16;
        const uint4* src = (const uint4*)&tb[r][cw];
        uint4 v0 = src[0], v1 = src[1];
        uint4* dst = (uint4*)(g_st + (orow + ch * 16 + r) * NN + n0 + cw);
        dst[0] = v0; dst[1] = v1;
    }
}

// ---------------- adj GEMM: 3-stage cp.async pipeline; which=0 fuses relu+W3 proj ----------------
__global__ __launch_bounds__(256) void gemm2_k(int which, int Nvalid, const float* __restrict__ W3) {
    __shared__ uint4 smem_u[3 * 512 + 3 * 256];
    uint4* sA = smem_u;
    uint4* sB = smem_u + 3 * 512;
    int c = blockIdx.z;
    const __nv_bfloat16* A = g_adjb + (size_t)c * NN * NN;
    const __nv_bfloat16* Bm; float* C; int Ncols;
    if (which == 0) { Bm = g_st  + (size_t)c * 256 * NN; C = nullptr;            Ncols = 256; }
    else            { Bm = g_s3t + (size_t)c * 144 * NN; C = g_t3 + (size_t)c * NN * 144; Ncols = 144; }
    int n0 = blockIdx.x * 64, m0 = blockIdx.y * 128;
    int tid = threadIdx.x, wid = tid >> 5, lane = tid & 31;
    int g = lane >> 2, t = lane & 3;
    int wm = (wid >> 1) * 32, wn = (wid & 1) * 32;
    uint32_t sab = (uint32_t)__cvta_generic_to_shared(sA);
    uint32_t sbb = (uint32_t)__cvta_generic_to_shared(sB);

    int arow[2], aswz[2];
#pragma unroll
    for (int f = 0; f < 2; f++) {
        arow[f] = wm + f * 16 + (lane & 7) + ((lane >> 3) & 1) * 8;
        aswz[f] = (arow[f] >> 1) & 3;
    }
    int akc = (lane >> 4) & 1;
    int brow[2], bswz[2];
#pragma unroll
    for (int p = 0; p < 2; p++) {
        brow[p] = wn + p * 16 + (lane & 7) + ((lane >> 4) << 3);
        bswz[p] = (brow[p] >> 1) & 3;
    }
    int bkc = (lane >> 3) & 1;

    float acc[2][4][4];
#pragma unroll
    for (int f = 0; f < 2; f++)
#pragma unroll
        for (int p = 0; p < 4; p++)
#pragma unroll
            for (int j = 0; j < 4; j++) acc[f][p][j] = 0.f;

    auto stage = [&](int buf, int k0) {
#pragma unroll
        for (int idx = tid; idx < 768; idx += 256) {
            if (idx < 512) {
                int r = idx >> 2, cc = idx & 3;
                uint32_t dst = sab + (buf * 512 + r * 4 + (cc ^ ((r >> 1) & 3))) * 16;
                CP_ASYNC16(dst, A + (size_t)(m0 + r) * NN + k0 + cc * 8);
            } else {
                int j = idx - 512;
                int r = j >> 2, cc = j & 3;
                int row = n0 + r; if (row >= Nvalid) row = Nvalid - 1;
                uint32_t dst = sbb + (buf * 256 + r * 4 + (cc ^ ((r >> 1) & 3))) * 16;
                CP_ASYNC16(dst, Bm + (size_t)row * NN + k0 + cc * 8);
            }
        }
        CP_COMMIT();
    };

    const int NIT = NN / 32;
    stage(0, 0);
    stage(1, 32);
    for (int i = 0; i < NIT; i++) {
        if (i + 1 < NIT) CP_WAIT1(); else CP_WAIT0();
        __syncthreads();
        if (i + 2 < NIT) stage((i + 2) % 3, (i + 2) * 32);
        int buf = i % 3;
        uint32_t sa0 = sab + buf * 512 * 16;
        uint32_t sb0 = sbb + buf * 256 * 16;
#pragma unroll
        for (int s = 0; s < 2; s++) {
            unsigned a[2][4];
#pragma unroll
            for (int f = 0; f < 2; f++)
                ldsm_x4(a[f], sa0 + (arow[f] * 4 + ((2 * s + akc) ^ aswz[f])) * 16);
#pragma unroll
            for (int p = 0; p < 2; p++) {
                unsigned br[4];
                ldsm_x4(br, sb0 + (brow[p] * 4 + ((2 * s + bkc) ^ bswz[p])) * 16);
#pragma unroll
                for (int f = 0; f < 2; f++) {
                    mma_bf16(acc[f][2 * p],     a[f][0], a[f][1], a[f][2], a[f][3], br[0], br[1]);
                    mma_bf16(acc[f][2 * p + 1], a[f][0], a[f][1], a[f][2], a[f][3], br[2], br[3]);
                }
            }
        }
    }
    if (which == 1) {
#pragma unroll
        for (int f = 0; f < 2; f++) {
            int ra = m0 + wm + f * 16 + g, rb = ra + 8;
#pragma unroll
            for (int p = 0; p < 4; p++) {
                int n = n0 + wn + p * 8 + 2 * t;
                if (n >= Nvalid) continue;
                *(float2*)(C + (size_t)ra * Ncols + n) = make_float2(acc[f][p][0], acc[f][p][1]);
                *(float2*)(C + (size_t)rb * Ncols + n) = make_float2(acc[f][p][2], acc[f][p][3]);
            }
        }
        return;
    }
    // ---- which == 0 epilogue: g = relu(acc) -> s3 = g @ W3 -> s3t bf16 ----
    __syncthreads();
    float* gs = (float*)smem_u;             // [128][68] padded
#pragma unroll
    for (int f = 0; f < 2; f++) {
        int ral = wm + f * 16 + g, rbl = ral + 8;
#pragma unroll
        for (int p = 0; p < 4; p++) {
            int nl = wn + p * 8 + 2 * t;
            gs[ral * 68 + nl]     = fmaxf(acc[f][p][0], 0.f);
            gs[ral * 68 + nl + 1] = fmaxf(acc[f][p][1], 0.f);
            gs[rbl * 68 + nl]     = fmaxf(acc[f][p][2], 0.f);
            gs[rbl * 68 + nl + 1] = fmaxf(acc[f][p][3], 0.f);
        }
    }
    __syncthreads();
    int r = tid >> 1, half = tid & 1;
    float accs[18];
#pragma unroll
    for (int o = 0; o < 18; o++) accs[o] = 0.f;
    for (int k = 0; k < 64; k++) {
        float gv = gs[r * 68 + k];
        const float* wr = W3 + k * 36 + half * 18;
#pragma unroll
        for (int o = 0; o < 18; o++) accs[o] += gv * __ldg(wr + o);
    }
    int b = blockIdx.x;
    size_t rowb = (size_t)(c * 144 + b * 36 + half * 18);
#pragma unroll
    for (int o = 0; o < 18; o++)
        g_s3t[(rowb + o) * NN + m0 + r] = __float2bfloat16(accs[o]);
}

__device__ __forceinline__ float2 cadd(float2 a, float2 b) { return make_float2(a.x + b.x, a.y + b.y); }
__device__ __forceinline__ float2 csub(float2 a, float2 b) { return make_float2(a.x - b.x, a.y - b.y); }

// ---------------- fwd row FFT, 12 coils/block; combine fused at load; fp16 out ----------------
__global__ __launch_bounds__(384) void fwdrow12_k(const float* __restrict__ in,
                                                  const float* __restrict__ arf,
                                                  const float* __restrict__ csr,
                                                  const float* __restrict__ csi) {
    __shared__ float2 sb[12][384];
    int y = blockIdx.x % HH, b = blockIdx.x / HH;
    int tid = threadIdx.x;
    float a = __ldg(arf);
    int gy = y / 6, py = y - gy * 6;
    int gx = tid / 6, px = tid - gx * 6;
    int nnode = gy * 64 + gx, f = py * 6 + px;
    float orr, oii;
    {
        int li0 = (b * 2 + 0) * HW + y * WW + tid;
        int li1 = li0 + HW;
        float t30 = g_t3[(size_t)(0 * NN + nnode) * 144 + b * 36 + f];
        float t31 = g_t3[(size_t)(1 * NN + nnode) * 144 + b * 36 + f];
        orr = in[li0] + (1.f - a) * g_tmp2[li0] + a * t30;
        oii = in[li1] + (1.f - a) * g_tmp2[li1] + a * t31;
    }
    float sgn = ((tid + y) & 1) ? -1.f : 1.f;
    float zr = sgn * orr, zi = sgn * oii;
    int r0 = tid % 3, q0 = tid / 3;
    const float* crb = csr + (size_t)b * CCH * HW + (size_t)y * WW + tid;
    const float* cib = csi + (size_t)b * CCH * HW + (size_t)y * WW + tid;
#pragma unroll
    for (int c = 0; c < CCH; c++) {
        float crv = __ldg(crb + (size_t)c * HW), civ = __ldg(cib + (size_t)c * HW);
        sb[c][r0 * 128 + q0] = make_float2(zr * crv - zi * civ, zr * civ + zi * crv);
    }
    __syncthreads();
#pragma unroll
    for (int len = 128; len >= 2; len >>= 1) {
        int h = len >> 1;
        for (int widx = tid; widx < 2304; widx += 384) {
            int line = widx / 192, bf = widx % 192;
            int seg = bf >> 6, b6 = bf & 63;
            int grp = b6 / h, t = b6 - grp * h;
            int i1 = seg * 128 + grp * len + t;
            float2 u = sb[line][i1], v = sb[line][i1 + h];
            sb[line][i1] = cadd(u, v);
            float2 d = csub(u, v);
            float2 w = g_tw128[t * (128 / len)];
            sb[line][i1 + h] = make_float2(d.x * w.x - d.y * w.y, d.x * w.y + d.y * w.x);
        }
        __syncthreads();
    }
    int k = tid, k0 = k & 127;
    int rv = __brev((unsigned)k0) >> 25;
    float2 c1 = g_tw384[k], c2 = g_tw384[(2 * k) % 384];
#pragma unroll
    for (int c = 0; c < CCH; c++) {
        float2 y0v = sb[c][rv], y1 = sb[c][128 + rv], y2 = sb[c][256 + rv];
        float xr = y0v.x + c1.x * y1.x - c1.y * y1.y + c2.x * y2.x - c2.y * y2.y;
        float xi = y0v.y + c1.x * y1.y + c1.y * y1.x + c2.x * y2.y + c2.y * y2.x;
        g_k[((size_t)(c * BSZ + b)) * HW + (size_t)y * 384 + k] = __floats2half2_rn(xr, xi);
    }
}

// ---------------- FUSED column pass: fwd FFT -> DC -> inverse FFT (fp16 io) ----------------
__global__ __launch_bounds__(192) void fft_col_fused_k(const int* __restrict__ mask,
                                                       const float* __restrict__ tkr,
                                                       const float* __restrict__ tki) {
    __shared__ float2 sb[8 * 384];
    int img = blockIdx.x / 48, cg = blockIdx.x % 48;
    __half2* base = g_k + (size_t)img * HW + cg * 8;
    int tid = threadIdx.x;
    for (int i = tid; i < 3072; i += 192) {
        int col = i & 7, yy = i >> 3;
        float2 Z = __half22float2(base[(size_t)yy * 384 + col]);
        sb[col * 384 + (yy % 3) * 128 + yy / 3] = Z;
    }
    __syncthreads();
#pragma unroll
    for (int len = 128; len >= 2; len >>= 1) {
        int h = len >> 1;
        for (int widx = tid; widx < 1536; widx += 192) {
            int seg = widx >> 6, bf = widx & 63;
            int boff = (seg / 3) * 384 + (seg % 3) * 128;
            int grp = bf / h, t = bf - grp * h;
            int i1 = boff + grp * len + t;
            float2 u = sb[i1], v = sb[i1 + h];
            sb[i1] = cadd(u, v);
            float2 d = csub(u, v);
            float2 w = g_tw128[t * (128 / len)];
            sb[i1 + h] = make_float2(d.x * w.x - d.y * w.y, d.x * w.y + d.y * w.x);
        }
        __syncthreads();
    }
    float2 val[16];
    for (int ii = 0; ii < 16; ii++) {
        int i = tid + ii * 192;
        int col = i & 7, k = i >> 3;
        int k0 = k & 127;
        int rv = __brev((unsigned)k0) >> 25;
        int cb = col * 384;
        float2 y0 = sb[cb + rv], y1 = sb[cb + 128 + rv], y2 = sb[cb + 256 + rv];
        float2 c1 = g_tw384[k], c2 = g_tw384[(2 * k) % 384];
        float xr = y0.x + c1.x * y1.x - c1.y * y1.y + c2.x * y2.x - c2.y * y2.y;
        float xi = y0.y + c1.x * y1.y + c1.y * y1.x + c2.x * y2.y + c2.y * y2.x;
        int gx = cg * 8 + col;
        int p = k * 384 + gx;
        float mv = (float)__ldg(mask + p);
        float sgn = ((gx + k) & 1) ? -1.f : 1.f;
        float coef = 384.f * 0.999999f * mv * sgn;
        float om = 1.f - mv;
        size_t gidx = (size_t)img * HW + p;
        val[ii] = make_float2(om * xr + coef * __ldg(tkr + gidx),
                              om * xi + coef * __ldg(tki + gidx));
    }
    __syncthreads();
    for (int ii = 0; ii < 16; ii++) {
        int i = tid + ii * 192;
        int col = i & 7, k = i >> 3;
        sb[col * 384 + (k % 3) * 128 + k / 3] = val[ii];
    }
    __syncthreads();
#pragma unroll
    for (int len = 128; len >= 2; len >>= 1) {
        int h = len >> 1;
        for (int widx = tid; widx < 1536; widx += 192) {
            int seg = widx >> 6, bf = widx & 63;
            int boff = (seg / 3) * 384 + (seg % 3) * 128;
            int grp = bf / h, t = bf - grp * h;
            int i1 = boff + grp * len + t;
            float2 u = sb[i1], v = sb[i1 + h];
            sb[i1] = cadd(u, v);
            float2 d = csub(u, v);
            float2 w = g_tw128[t * (128 / len)];
            sb[i1 + h] = make_float2(d.x * w.x + d.y * w.y, -d.x * w.y + d.y * w.x);
        }
        __syncthreads();
    }
    for (int i = tid; i < 3072; i += 192) {
        int col = i & 7, k = i >> 3;
        int k0 = k & 127;
        int rv = __brev((unsigned)k0) >> 25;
        int cb = col * 384;
        float2 y0 = sb[cb + rv], y1 = sb[cb + 128 + rv], y2 = sb[cb + 256 + rv];
        float2 c1 = g_tw384[k], c2 = g_tw384[(2 * k) % 384];
        float s1 = -c1.y, s2 = -c2.y;
        float xr = (y0.x + c1.x * y1.x - s1 * y1.y + c2.x * y2.x - s2 * y2.y) * (1.f / 384.f);
        float xi = (y0.y + c1.x * y1.y + s1 * y1.x + c2.x * y2.y + s2 * y2.x) * (1.f / 384.f);
        base[(size_t)k * 384 + col] = __floats2half2_rn(xr, xi);
    }
}

// ---------------- fused inverse row FFT (12 coils) + coil combine (fp16 in) ----------------
__global__ __launch_bounds__(384) void invrow_final_k(const float* __restrict__ csr,
                                                      const float* __restrict__ csi,
                                                      float* __restrict__ out) {
    __shared__ float2 sb[12][384];
    int y = blockIdx.x % HH, b = blockIdx.x / HH;
    int tid = threadIdx.x;
    int r0 = tid % 3, q0 = tid / 3;
#pragma unroll
    for (int c = 0; c < CCH; c++) {
        float2 z = __half22float2(g_k[((size_t)(c * BSZ + b)) * HW + (size_t)y * 384 + tid]);
        sb[c][r0 * 128 + q0] = z;
    }
    __syncthreads();
#pragma unroll
    for (int len = 128; len >= 2; len >>= 1) {
        int h = len >> 1;
        for (int widx = tid; widx < 2304; widx += 384) {
            int line = widx / 192, bf = widx % 192;
            int seg = bf >> 6, b6 = bf & 63;
            int grp = b6 / h, t = b6 - grp * h;
            int i1 = seg * 128 + grp * len + t;
            float2 u = sb[line][i1], v = sb[line][i1 + h];
            sb[line][i1] = cadd(u, v);
            float2 d = csub(u, v);
            float2 w = g_tw128[t * (128 / len)];
            sb[line][i1 + h] = make_float2(d.x * w.x + d.y * w.y, -d.x * w.y + d.y * w.x);
        }
        __syncthreads();
    }
    int k = tid;
    int k0 = k & 127;
    int rv = __brev((unsigned)k0) >> 25;
    float2 c1 = g_tw384[k], c2 = g_tw384[(2 * k) % 384];
    float s1 = -c1.y, s2 = -c2.y;
    float rr = 0.f, ri = 0.f;
    const float* crb = csr + (size_t)b * CCH * HW + (size_t)y * WW + k;
    const float* cib = csi + (size_t)b * CCH * HW + (size_t)y * WW + k;
#pragma unroll
    for (int c = 0; c < CCH; c++) {
        float2 y0 = sb[c][rv], y1 = sb[c][128 + rv], y2 = sb[c][256 + rv];
        float xr = (y0.x + c1.x * y1.x - s1 * y1.y + c2.x * y2.x - s2 * y2.y) * (1.f / 384.f);
        float xi = (y0.y + c1.x * y1.y + s1 * y1.x + c2.x * y2.y + s2 * y2.x) * (1.f / 384.f);
        float cr = __ldg(crb + (size_t)c * HW);
        float ci = __ldg(cib + (size_t)c * HW);
        rr += xr * cr + xi * ci;
        ri += xi * cr - xr * ci;
    }
    float sgn = ((k + y) & 1) ? -1.f : 1.f;
    out[(size_t)(b * 2 + 0) * HW + (size_t)y * WW + k] = sgn * rr;
    out[(size_t)(b * 2 + 1) * HW + (size_t)y * WW + k] = sgn * ri;
}

// ---------------- launch: fork/join dual-stream graph ----------------
extern "C" void kernel_launch(void* const* d_in, const int* in_sizes, int n_in,
                              void* d_out, int out_size) {
    (void)in_sizes; (void)n_in; (void)out_size;
    const float* input = (const float*)d_in[0];
    const float* adj   = (const float*)d_in[1];
    const int*   mask  = (const int*)  d_in[2];
    const float* csr   = (const float*)d_in[3];
    const float* csi   = (const float*)d_in[4];
    const float* tkr   = (const float*)d_in[5];
    const float* tki   = (const float*)d_in[6];
    const float* W1    = (const float*)d_in[7];
    const float* W3    = (const float*)d_in[8];
    const float* arf   = (const float*)d_in[9];
    const float* cw1   = (const float*)d_in[10];
    const float* cb1   = (const float*)d_in[11];
    const float* cw2   = (const float*)d_in[12];
    const float* cb2   = (const float*)d_in[13];
    const float* cw3   = (const float*)d_in[14];
    const float* cb3   = (const float*)d_in[15];
    float* out = (float*)d_out;

    static cudaStream_t s2 = nullptr;
    static cudaEvent_t e_fork = nullptr, e_join = nullptr;
    static int smem_set = 0;
    const int CONV2_SMEM = (2112 + 1536) * 16;   // 58368 B
    const int CONV3_SMEM = (3168 + 576) * 16;    // 59904 B
    if (!s2) {
        cudaStreamCreateWithFlags(&s2, cudaStreamNonBlocking);
        cudaEventCreateWithFlags(&e_fork, cudaEventDisableTiming);
        cudaEventCreateWithFlags(&e_join, cudaEventDisableTiming);
    }
    if (!smem_set) {
        cudaFuncSetAttribute(conv2_mma, cudaFuncAttributeMaxDynamicSharedMemorySize, CONV2_SMEM);
        cudaFuncSetAttribute(conv3_mma, cudaFuncAttributeMaxDynamicSharedMemorySize, CONV3_SMEM);
        smem_set = 1;
    }

    // fork: GCN branch on s2, CNN branch on default stream
    cudaEventRecord(e_fork, 0);
    cudaStreamWaitEvent(s2, e_fork, 0);

    adj_cvt_k<<<32768, 256, 0, s2>>>(adj);                       // 0
    gcn_s_k<<<256, 128, 0, s2>>>(input, W1);                     // 1
    gemm2_k<<<dim3(4, 32, 2), 256, 0, s2>>>(0, 256, W3);         // 2
    gemm2_k<<<dim3(3, 32, 2), 256, 0, s2>>>(1, 144, nullptr);    // 3  <-- profiled
    cudaEventRecord(e_join, s2);

    prep_w_k<<<144, 256>>>(cw2, cw3);                            // 4 (incl. twiddles)
    conv1_k<<<4608, 256>>>(input, cw1, cb1);                     // 5
    conv2_mma<<<dim3(6, 192, 4), 128, CONV2_SMEM>>>(cb2);        // 6
    conv3_mma<<<dim3(6, 96, 4), 128, CONV3_SMEM>>>(cb3);         // 7

    // join, then FFT chain
    cudaStreamWaitEvent(0, e_join, 0);
    fwdrow12_k<<<4 * 384, 384>>>(input, arf, csr, csi);          // 8
    fft_col_fused_k<<<48 * 48, 192>>>(mask, tkr, tki);           // 9
    invrow_final_k<<<4 * 384, 384>>>(csr, csi, out);             // 10
}

// round 17
// speedup vs baseline: 1.6289x; 1.0196x over previous
#include <cuda_runtime.h>
#include <cuda_fp16.h>
#include <cuda_bf16.h>
#include <math.h>
#include <stdint.h>
#include <stddef.h>

#define BSZ 4
#define CCH 12
#define HH 384
#define WW 384
#define HW (HH*WW)
#define NN 4096

// ---------------- static device scratch (no allocs allowed) ----------------
__device__ __half         g_h1n[(size_t)BSZ*HW*64];   // conv1 out, NHWC fp16
__device__ __half         g_h2n[(size_t)BSZ*HW*64];   // conv2 out, NHWC fp16
__device__ __nv_bfloat16  g_adjb[(size_t)2*NN*NN];    // adj bf16
__device__ __half         g_w2t[9*64*64];             // conv2 w [tap][co][ci]
__device__ __half         g_w3t[9*8*64];              // conv3 w [tap][o pad8][ci]
__device__ __nv_bfloat16  g_st [(size_t)2*256*NN];    // s^T  [c][b*64+o][m]
__device__ __nv_bfloat16  g_s3t[(size_t)2*144*NN];    // s3^T [c][b*36+o][m]
__device__ float          g_t3 [(size_t)2*NN*144];    // adj@s3 [c][m][144]
__device__ float          g_tmp2[BSZ*2*HW];
__device__ __half2        g_k[(size_t)CCH*BSZ*HW];    // k-space, fp16 complex (28MB)
__device__ float2         g_tw128[64];
__device__ float2         g_tw384[384];

// ---------------- mma / ldmatrix / cp.async wrappers ----------------
__device__ __forceinline__ void mma_f16(float c[4], unsigned a0, unsigned a1,
                                        unsigned a2, unsigned a3,
                                        unsigned b0, unsigned b1) {
    asm volatile("mma.sync.aligned.m16n8k16.row.col.f32.f16.f16.f32 "
        "{%0,%1,%2,%3}, {%4,%5,%6,%7}, {%8,%9}, {%0,%1,%2,%3};"
        : "+f"(c[0]), "+f"(c[1]), "+f"(c[2]), "+f"(c[3])
        : "r"(a0), "r"(a1), "r"(a2), "r"(a3), "r"(b0), "r"(b1));
}
__device__ __forceinline__ void mma_bf16(float c[4], unsigned a0, unsigned a1,
                                         unsigned a2, unsigned a3,
                                         unsigned b0, unsigned b1) {
    asm volatile("mma.sync.aligned.m16n8k16.row.col.f32.bf16.bf16.f32 "
        "{%0,%1,%2,%3}, {%4,%5,%6,%7}, {%8,%9}, {%0,%1,%2,%3};"
        : "+f"(c[0]), "+f"(c[1]), "+f"(c[2]), "+f"(c[3])
        : "r"(a0), "r"(a1), "r"(a2), "r"(a3), "r"(b0), "r"(b1));
}
__device__ __forceinline__ void ldsm_x4(unsigned r[4], uint32_t a) {
    asm volatile("ldmatrix.sync.aligned.m8n8.x4.shared.b16 {%0,%1,%2,%3}, [%4];"
        : "=r"(r[0]), "=r"(r[1]), "=r"(r[2]), "=r"(r[3]) : "r"(a));
}
__device__ __forceinline__ void ldsm_x2(unsigned& r0, unsigned& r1, uint32_t a) {
    asm volatile("ldmatrix.sync.aligned.m8n8.x2.shared.b16 {%0,%1}, [%2];"
        : "=r"(r0), "=r"(r1) : "r"(a));
}
#define CP_ASYNC16(dst, src) \
    asm volatile("cp.async.cg.shared.global [%0], [%1], 16;" :: "r"(dst), "l"(src))
#define CP_ASYNC16Z(dst, src, sz) \
    asm volatile("cp.async.cg.shared.global [%0], [%1], 16, %2;" :: "r"(dst), "l"(src), "r"(sz))
#define CP_COMMIT()  asm volatile("cp.async.commit_group;")
#define CP_WAIT0()   asm volatile("cp.async.wait_group 0;")
#define CP_WAIT1()   asm volatile("cp.async.wait_group 1;")

// ---------------- init: weights repack + twiddles (merged) ----------------
__global__ void prep_w_k(const float* __restrict__ cw2, const float* __restrict__ cw3) {
    if (blockIdx.x == 0) {
        int t = threadIdx.x;
        if (t < 64) { float s, c; sincospif(-(float)t / 64.f, &s, &c); g_tw128[t] = make_float2(c, s); }
        for (int u = t; u < 384; u += 256) {
            float s, c; sincospif(-(float)u / 192.f, &s, &c);
            g_tw384[u] = make_float2(c, s);
        }
    }
    int i = blockIdx.x * 256 + threadIdx.x;
    if (i < 9 * 64 * 64) {
        int tap = i / 4096, r = i % 4096, co = r >> 6, ci = r & 63;
        g_w2t[i] = __float2half(cw2[(co * 64 + ci) * 9 + tap]);
    }
    if (i < 9 * 8 * 64) {
        int tap = i / 512, r = i % 512, o = r >> 6, ci = r & 63;
        g_w3t[i] = __float2half((o < 2) ? cw3[(o * 64 + ci) * 9 + tap] : 0.f);
    }
}
__global__ __launch_bounds__(256) void adj_cvt_k(const float* __restrict__ adj) {
    size_t i = ((size_t)blockIdx.x * 256 + threadIdx.x) * 4;
    float4 v = *(const float4*)(adj + i);
    __nv_bfloat162* o = (__nv_bfloat162*)(g_adjb + i);
    o[0] = __floats2bfloat162_rn(v.x, v.y);
    o[1] = __floats2bfloat162_rn(v.z, v.w);
}

// ---------------- conv1: 2 -> 64, relu; smem-staged input, 4 px x 8 ch/thread ----------------
__global__ __launch_bounds__(256) void conv1_k(const float* __restrict__ in,
                                               const float* __restrict__ w,
                                               const float* __restrict__ bias) {
    __shared__ float ws[18 * 64];
    __shared__ float sIn[2][3][132];
    for (int i = threadIdx.x; i < 1152; i += 256) {
        int co = i / 18, q = i % 18;
        ws[q * 64 + co] = w[i];
    }
    int tid = threadIdx.x;
    int cog = tid & 7;
    int pq  = tid >> 3;
    int chunk = blockIdx.x % 3;
    int rowid = blockIdx.x / 3;
    int y = rowid % HH, b = rowid / HH;
    int px_base = chunk * 128;
    int px0 = px_base + pq * 4;
    for (int i = tid; i < 792; i += 256) {
        int ci = i / 396, rem = i % 396, r = rem / 132, xx = rem % 132;
        int gxx = px_base - 1 + xx;
        int yy = y + r - 1;
        float v = 0.f;
        if (xx < 131 && (unsigned)gxx < WW && (unsigned)yy < HH)
            v = __ldg(in + (b * 2 + ci) * HW + yy * WW + gxx);
        sIn[ci][r][xx] = v;
    }
    __syncthreads();
    float iv[2][3][6];
#pragma unroll
    for (int ci = 0; ci < 2; ci++)
#pragma unroll
        for (int ry = 0; ry < 3; ry++)
#pragma unroll
            for (int cx = 0; cx < 6; cx++)
                iv[ci][ry][cx] = sIn[ci][ry][pq * 4 + cx];
    float acc[4][8];
    float bz[8];
#pragma unroll
    for (int j = 0; j < 8; j++) bz[j] = __ldg(bias + cog * 8 + j);
#pragma unroll
    for (int px = 0; px < 4; px++)
#pragma unroll
        for (int j = 0; j < 8; j++) acc[px][j] = bz[j];
#pragma unroll
    for (int ci = 0; ci < 2; ci++)
#pragma unroll
        for (int ky = 0; ky < 3; ky++)
#pragma unroll
            for (int kx = 0; kx < 3; kx++) {
                int q = ci * 9 + ky * 3 + kx;
                const float4* wp = (const float4*)&ws[q * 64 + cog * 8];
                float4 wa = wp[0], wb = wp[1];
                float w8[8] = {wa.x, wa.y, wa.z, wa.w, wb.x, wb.y, wb.z, wb.w};
#pragma unroll
                for (int px = 0; px < 4; px++) {
                    float v = iv[ci][ky][kx + px];
#pragma unroll
                    for (int j = 0; j < 8; j++) acc[px][j] += v * w8[j];
                }
            }
#pragma unroll
    for (int px = 0; px < 4; px++) {
        size_t p = (size_t)b * HW + (size_t)y * WW + (px0 + px);
        __half2 h4[4];
#pragma unroll
        for (int j = 0; j < 8; j += 2)
            h4[j >> 1] = __floats2half2_rn(fmaxf(acc[px][j], 0.f), fmaxf(acc[px][j + 1], 0.f));
        *(uint4*)(g_h1n + p * 64 + cog * 8) = *(const uint4*)h4;
    }
}

// ---------------- conv2: 64->64 mma fp16; 3-buffer B rotation, ONE sync/tap ----------------
__global__ __launch_bounds__(128) void conv2_mma(const float* __restrict__ bias) {
    extern __shared__ uint4 dsm2[];
    uint4* s_a  = dsm2;
    uint4* s_b3 = dsm2 + 2112;
    int x0 = blockIdx.x * 64, y0 = blockIdx.y * 2, b = blockIdx.z;
    int tid = threadIdx.x, wid = tid >> 5, lane = tid & 31;
    int g = lane >> 2, t = lane & 3;
    uint32_t sbq = (uint32_t)__cvta_generic_to_shared(s_b3);
    uint32_t sa = (uint32_t)__cvta_generic_to_shared(s_a);
#pragma unroll
    for (int j = 0; j < 4; j++) {
        int idx = tid + j * 128;
        int co = idx >> 3, cc = idx & 7;
        CP_ASYNC16(sbq + (co * 8 + (cc ^ (co & 7))) * 16, g_w2t + co * 64 + cc * 8);
    }
    CP_COMMIT();
    for (int idx = tid; idx < 2112; idx += 128) {
        int r = idx / 528, rem = idx % 528, p = rem >> 3, cc = rem & 7;
        int gx = x0 - 1 + p, yy = y0 - 1 + r;
        bool ok = ((unsigned)gx < WW) && ((unsigned)yy < HH);
        const __half* src = g_h1n + ((size_t)(b * HH + (ok ? yy : 0)) * WW + (ok ? gx : 0)) * 64 + cc * 8;
        CP_ASYNC16Z(sa + ((r * 66 + p) * 8 + (cc ^ (p & 7))) * 16, src, ok ? 16 : 0);
    }
    CP_COMMIT();
#pragma unroll
    for (int j = 0; j < 4; j++) {
        int idx = tid + j * 128;
        int co = idx >> 3, cc = idx & 7;
        CP_ASYNC16(sbq + (512 + co * 8 + (cc ^ (co & 7))) * 16, g_w2t + 4096 + co * 64 + cc * 8);
    }
    CP_COMMIT();
    int lrow = lane & 7, msel = lane >> 3;
    int a_pofs = ((msel & 1) << 3) + lrow;
    int a_hi = msel >> 1;
    int lq = lane >> 3;
    float acc[2][8][4];
#pragma unroll
    for (int r = 0; r < 2; r++)
#pragma unroll
        for (int i = 0; i < 8; i++)
#pragma unroll
            for (int j = 0; j < 4; j++) acc[r][i][j] = 0.f;

    for (int tap = 0; tap < 9; tap++) {
        if (tap < 8) CP_WAIT1(); else CP_WAIT0();
        __syncthreads();
        if (tap < 7) {
            int buf = (tap + 2) % 3;
#pragma unroll
            for (int j = 0; j < 4; j++) {
                int idx = tid + j * 128;
                int co = idx >> 3, cc = idx & 7;
                CP_ASYNC16(sbq + (buf * 512 + co * 8 + (cc ^ (co & 7))) * 16,
                           g_w2t + (tap + 2) * 4096 + co * 64 + cc * 8);
            }
            CP_COMMIT();
        }
        int ky = tap / 3, kx = tap % 3;
        int p = wid * 16 + kx + a_pofs;
        int psw = p & 7;
        int arow0 = (ky * 66 + p) * 8, arow1 = arow0 + 528;
        uint32_t sbt = sbq + (tap % 3) * 512 * 16;
#pragma unroll
        for (int kk = 0; kk < 4; kk++) {
            unsigned a0[4], a1[4];
            int chunk = 2 * kk + a_hi;
            ldsm_x4(a0, sa + (arow0 + (chunk ^ psw)) * 16);
            ldsm_x4(a1, sa + (arow1 + (chunk ^ psw)) * 16);
#pragma unroll
            for (int ntp = 0; ntp < 4; ntp++) {
                int co_b = (2 * ntp + (lq >> 1)) * 8 + lrow;
                int bch = 2 * kk + (lq & 1);
                unsigned br[4];
                ldsm_x4(br, sbt + (co_b * 8 + (bch ^ lrow)) * 16);
                mma_f16(acc[0][2 * ntp],     a0[0], a0[1], a0[2], a0[3], br[0], br[1]);
                mma_f16(acc[0][2 * ntp + 1], a0[0], a0[1], a0[2], a0[3], br[2], br[3]);
                mma_f16(acc[1][2 * ntp],     a1[0], a1[1], a1[2], a1[3], br[0], br[1]);
                mma_f16(acc[1][2 * ntp + 1], a1[0], a1[1], a1[2], a1[3], br[2], br[3]);
            }
        }
    }
    int px1 = x0 + wid * 16 + g;
#pragma unroll
    for (int r = 0; r < 2; r++) {
        int y = y0 + r;
        __half* o1 = g_h2n + ((size_t)(b * HH + y) * WW + px1) * 64;
        __half* o2 = o1 + 8 * 64;
#pragma unroll
        for (int nt = 0; nt < 8; nt++) {
            int n = nt * 8 + 2 * t;
            float b0 = __ldg(bias + n), b1 = __ldg(bias + n + 1);
            *(__half2*)(o1 + n) = __floats2half2_rn(fmaxf(acc[r][nt][0] + b0, 0.f), fmaxf(acc[r][nt][1] + b1, 0.f));
            *(__half2*)(o2 + n) = __floats2half2_rn(fmaxf(acc[r][nt][2] + b0, 0.f), fmaxf(acc[r][nt][3] + b1, 0.f));
        }
    }
}

// ---------------- conv3: 64->2 mma fp16; 4 rows/block, cp.async staging ----------------
__global__ __launch_bounds__(128) void conv3_mma(const float* __restrict__ bias) {
    extern __shared__ uint4 dsm3[];
    uint4* s_a  = dsm3;
    uint4* s_b3 = dsm3 + 3168;
    int x0 = blockIdx.x * 64, y0 = blockIdx.y * 4, b = blockIdx.z;
    int tid = threadIdx.x, wid = tid >> 5, lane = tid & 31;
    int g = lane >> 2, t = lane & 3;
    uint32_t sa = (uint32_t)__cvta_generic_to_shared(s_a);
    uint32_t sb = (uint32_t)__cvta_generic_to_shared(s_b3);
    for (int idx = tid; idx < 3168; idx += 128) {
        int r = idx / 528, rem = idx % 528, p = rem >> 3, cc = rem & 7;
        int gx = x0 - 1 + p, yy = y0 - 1 + r;
        bool ok = ((unsigned)gx < WW) && ((unsigned)yy < HH);
        const __half* src = g_h2n + ((size_t)(b * HH + (ok ? yy : 0)) * WW + (ok ? gx : 0)) * 64 + cc * 8;
        CP_ASYNC16Z(sa + ((r * 66 + p) * 8 + (cc ^ (p & 7))) * 16, src, ok ? 16 : 0);
    }
    for (int idx = tid; idx < 576; idx += 128) {
        int tap = idx / 64, rem = idx % 64, co = rem >> 3, cc = rem & 7;
        CP_ASYNC16(sb + (tap * 64 + co * 8 + (cc ^ co)) * 16,
                   g_w3t + tap * 512 + co * 64 + cc * 8);
    }
    CP_COMMIT();
    CP_WAIT0();
    __syncthreads();
    int lrow = lane & 7, msel = lane >> 3;
    int a_pofs = ((msel & 1) << 3) + lrow;
    int a_hi = msel >> 1;
    int b_hi = (lane >> 3) & 1;
    float acc[2][2][4];
#pragma unroll
    for (int rp = 0; rp < 2; rp++)
#pragma unroll
        for (int r = 0; r < 2; r++)
#pragma unroll
            for (int j = 0; j < 4; j++) acc[rp][r][j] = 0.f;
#pragma unroll
    for (int rp = 0; rp < 2; rp++)
        for (int ky = 0; ky < 3; ky++)
            for (int kx = 0; kx < 3; kx++) {
                int tap = ky * 3 + kx;
                int p = wid * 16 + kx + a_pofs;
                int psw = p & 7;
                int arow0 = ((2 * rp + ky) * 66 + p) * 8, arow1 = arow0 + 528;
#pragma unroll
                for (int kk = 0; kk < 4; kk++) {
                    unsigned a0[4], a1[4];
                    int chunk = 2 * kk + a_hi;
                    ldsm_x4(a0, sa + (arow0 + (chunk ^ psw)) * 16);
                    ldsm_x4(a1, sa + (arow1 + (chunk ^ psw)) * 16);
                    unsigned b0, b1;
                    int bch = 2 * kk + b_hi;
                    ldsm_x2(b0, b1, sb + (tap * 64 + lrow * 8 + (bch ^ lrow)) * 16);
                    mma_f16(acc[rp][0], a0[0], a0[1], a0[2], a0[3], b0, b1);
                    mma_f16(acc[rp][1], a1[0], a1[1], a1[2], a1[3], b0, b1);
                }
            }
    if (t == 0) {
        float b0 = __ldg(bias + 0), b1 = __ldg(bias + 1);
        int px1 = x0 + wid * 16 + g, px2 = px1 + 8;
#pragma unroll
        for (int rp = 0; rp < 2; rp++)
#pragma unroll
            for (int r = 0; r < 2; r++) {
                int base = (y0 + 2 * rp + r) * WW;
                g_tmp2[(b * 2 + 0) * HW + base + px1] = acc[rp][r][0] + b0;
                g_tmp2[(b * 2 + 1) * HW + base + px1] = acc[rp][r][1] + b1;
                g_tmp2[(b * 2 + 0) * HW + base + px2] = acc[rp][r][2] + b0;
                g_tmp2[(b * 2 + 1) * HW + base + px2] = acc[rp][r][3] + b1;
            }
    }
}

// ---------------- GCN: s^T = (feat @ W1)^T, bf16, coalesced via smem transpose ----------------
__global__ __launch_bounds__(128) void gcn_s_k(const float* __restrict__ in,
                                               const float* __restrict__ W1) {
    __shared__ float w[36 * 64];
    __shared__ __nv_bfloat16 tb[16][136];
    for (int i = threadIdx.x; i < 2304; i += 128) w[i] = W1[i];
    __syncthreads();
    int idx = blockIdx.x * 128 + threadIdx.x;
    int n = idx & 4095, b = (idx >> 12) & 3, c = idx >> 14;
    int n0 = (blockIdx.x * 128) & 4095;
    int gy = n >> 6, gx = n & 63;
    const float* base = in + (b * 2 + c) * HW + (gy * 6) * WW + gx * 6;
    float f[36];
#pragma unroll
    for (int py = 0; py < 6; py++)
#pragma unroll
        for (int px = 0; px < 6; px++) f[py * 6 + px] = __ldg(base + py * WW + px);
    float acc[64];
#pragma unroll
    for (int o = 0; o < 64; o++) acc[o] = 0.f;
#pragma unroll
    for (int ff = 0; ff < 36; ff++) {
        float fv = f[ff];
        const float* wr = &w[ff * 64];
#pragma unroll
        for (int o = 0; o < 64; o++) acc[o] += fv * wr[o];
    }
    int nl = threadIdx.x;
    size_t orow = (size_t)(c * 256 + b * 64);
    for (int ch = 0; ch < 4; ch++) {
        __syncthreads();
#pragma unroll
        for (int o = 0; o < 16; o++) tb[o][nl] = __float2bfloat16(acc[ch * 16 + o]);
        __syncthreads();
        int r = nl >> 3, cw = (nl & 7) * 16;
        const uint4* src = (const uint4*)&tb[r][cw];
        uint4 v0 = src[0], v1 = src[1];
        uint4* dst = (uint4*)(g_st + (orow + ch * 16 + r) * NN + n0 + cw);
        dst[0] = v0; dst[1] = v1;
    }
}

// ---------------- adj GEMM: 3-stage cp.async pipeline; which=0 fuses relu+W3 proj ----------------
__global__ __launch_bounds__(256) void gemm2_k(int which, int Nvalid, const float* __restrict__ W3) {
    __shared__ uint4 smem_u[3 * 512 + 3 * 256];
    uint4* sA = smem_u;
    uint4* sB = smem_u + 3 * 512;
    int c = blockIdx.z;
    const __nv_bfloat16* A = g_adjb + (size_t)c * NN * NN;
    const __nv_bfloat16* Bm; float* C; int Ncols;
    if (which == 0) { Bm = g_st  + (size_t)c * 256 * NN; C = nullptr;            Ncols = 256; }
    else            { Bm = g_s3t + (size_t)c * 144 * NN; C = g_t3 + (size_t)c * NN * 144; Ncols = 144; }
    int n0 = blockIdx.x * 64, m0 = blockIdx.y * 128;
    int tid = threadIdx.x, wid = tid >> 5, lane = tid & 31;
    int g = lane >> 2, t = lane & 3;
    int wm = (wid >> 1) * 32, wn = (wid & 1) * 32;
    uint32_t sab = (uint32_t)__cvta_generic_to_shared(sA);
    uint32_t sbb = (uint32_t)__cvta_generic_to_shared(sB);

    int arow[2], aswz[2];
#pragma unroll
    for (int f = 0; f < 2; f++) {
        arow[f] = wm + f * 16 + (lane & 7) + ((lane >> 3) & 1) * 8;
        aswz[f] = (arow[f] >> 1) & 3;
    }
    int akc = (lane >> 4) & 1;
    int brow[2], bswz[2];
#pragma unroll
    for (int p = 0; p < 2; p++) {
        brow[p] = wn + p * 16 + (lane & 7) + ((lane >> 4) << 3);
        bswz[p] = (brow[p] >> 1) & 3;
    }
    int bkc = (lane >> 3) & 1;

    float acc[2][4][4];
#pragma unroll
    for (int f = 0; f < 2; f++)
#pragma unroll
        for (int p = 0; p < 4; p++)
#pragma unroll
            for (int j = 0; j < 4; j++) acc[f][p][j] = 0.f;

    auto stage = [&](int buf, int k0) {
#pragma unroll
        for (int idx = tid; idx < 768; idx += 256) {
            if (idx < 512) {
                int r = idx >> 2, cc = idx & 3;
                uint32_t dst = sab + (buf * 512 + r * 4 + (cc ^ ((r >> 1) & 3))) * 16;
                CP_ASYNC16(dst, A + (size_t)(m0 + r) * NN + k0 + cc * 8);
            } else {
                int j = idx - 512;
                int r = j >> 2, cc = j & 3;
                int row = n0 + r; if (row >= Nvalid) row = Nvalid - 1;
                uint32_t dst = sbb + (buf * 256 + r * 4 + (cc ^ ((r >> 1) & 3))) * 16;
                CP_ASYNC16(dst, Bm + (size_t)row * NN + k0 + cc * 8);
            }
        }
        CP_COMMIT();
    };

    const int NIT = NN / 32;
    stage(0, 0);
    stage(1, 32);
    for (int i = 0; i < NIT; i++) {
        if (i + 1 < NIT) CP_WAIT1(); else CP_WAIT0();
        __syncthreads();
        if (i + 2 < NIT) stage((i + 2) % 3, (i + 2) * 32);
        int buf = i % 3;
        uint32_t sa0 = sab + buf * 512 * 16;
        uint32_t sb0 = sbb + buf * 256 * 16;
#pragma unroll
        for (int s = 0; s < 2; s++) {
            unsigned a[2][4];
#pragma unroll
            for (int f = 0; f < 2; f++)
                ldsm_x4(a[f], sa0 + (arow[f] * 4 + ((2 * s + akc) ^ aswz[f])) * 16);
#pragma unroll
            for (int p = 0; p < 2; p++) {
                unsigned br[4];
                ldsm_x4(br, sb0 + (brow[p] * 4 + ((2 * s + bkc) ^ bswz[p])) * 16);
#pragma unroll
                for (int f = 0; f < 2; f++) {
                    mma_bf16(acc[f][2 * p],     a[f][0], a[f][1], a[f][2], a[f][3], br[0], br[1]);
                    mma_bf16(acc[f][2 * p + 1], a[f][0], a[f][1], a[f][2], a[f][3], br[2], br[3]);
                }
            }
        }
    }
    if (which == 1) {
#pragma unroll
        for (int f = 0; f < 2; f++) {
            int ra = m0 + wm + f * 16 + g, rb = ra + 8;
#pragma unroll
            for (int p = 0; p < 4; p++) {
                int n = n0 + wn + p * 8 + 2 * t;
                if (n >= Nvalid) continue;
                *(float2*)(C + (size_t)ra * Ncols + n) = make_float2(acc[f][p][0], acc[f][p][1]);
                *(float2*)(C + (size_t)rb * Ncols + n) = make_float2(acc[f][p][2], acc[f][p][3]);
            }
        }
        return;
    }
    // ---- which == 0 epilogue: g = relu(acc) -> s3 = g @ W3 -> s3t bf16 ----
    __syncthreads();
    float* gs = (float*)smem_u;             // [128][68] padded
#pragma unroll
    for (int f = 0; f < 2; f++) {
        int ral = wm + f * 16 + g, rbl = ral + 8;
#pragma unroll
        for (int p = 0; p < 4; p++) {
            int nl = wn + p * 8 + 2 * t;
            gs[ral * 68 + nl]     = fmaxf(acc[f][p][0], 0.f);
            gs[ral * 68 + nl + 1] = fmaxf(acc[f][p][1], 0.f);
            gs[rbl * 68 + nl]     = fmaxf(acc[f][p][2], 0.f);
            gs[rbl * 68 + nl + 1] = fmaxf(acc[f][p][3], 0.f);
        }
    }
    __syncthreads();
    int r = tid >> 1, half = tid & 1;
    float accs[18];
#pragma unroll
    for (int o = 0; o < 18; o++) accs[o] = 0.f;
    for (int k = 0; k < 64; k++) {
        float gv = gs[r * 68 + k];
        const float* wr = W3 + k * 36 + half * 18;
#pragma unroll
        for (int o = 0; o < 18; o++) accs[o] += gv * __ldg(wr + o);
    }
    int b = blockIdx.x;
    size_t rowb = (size_t)(c * 144 + b * 36 + half * 18);
#pragma unroll
    for (int o = 0; o < 18; o++)
        g_s3t[(rowb + o) * NN + m0 + r] = __float2bfloat16(accs[o]);
}

__device__ __forceinline__ float2 cadd(float2 a, float2 b) { return make_float2(a.x + b.x, a.y + b.y); }
__device__ __forceinline__ float2 csub(float2 a, float2 b) { return make_float2(a.x - b.x, a.y - b.y); }

// ---------------- fwd row FFT, 12 coils/block, WARP-LOCAL butterflies ----------------
__global__ __launch_bounds__(384) void fwdrow12_k(const float* __restrict__ in,
                                                  const float* __restrict__ arf,
                                                  const float* __restrict__ csr,
                                                  const float* __restrict__ csi) {
    __shared__ float2 sb[12][384];
    int y = blockIdx.x % HH, b = blockIdx.x / HH;
    int tid = threadIdx.x;
    float a = __ldg(arf);
    int gy = y / 6, py = y - gy * 6;
    int gx = tid / 6, px = tid - gx * 6;
    int nnode = gy * 64 + gx, f = py * 6 + px;
    float orr, oii;
    {
        int li0 = (b * 2 + 0) * HW + y * WW + tid;
        int li1 = li0 + HW;
        float t30 = g_t3[(size_t)(0 * NN + nnode) * 144 + b * 36 + f];
        float t31 = g_t3[(size_t)(1 * NN + nnode) * 144 + b * 36 + f];
        orr = in[li0] + (1.f - a) * g_tmp2[li0] + a * t30;
        oii = in[li1] + (1.f - a) * g_tmp2[li1] + a * t31;
    }
    float sgn = ((tid + y) & 1) ? -1.f : 1.f;
    float zr = sgn * orr, zi = sgn * oii;
    int r0 = tid % 3, q0 = tid / 3;
    const float* crb = csr + (size_t)b * CCH * HW + (size_t)y * WW + tid;
    const float* cib = csi + (size_t)b * CCH * HW + (size_t)y * WW + tid;
#pragma unroll
    for (int c = 0; c < CCH; c++) {
        float crv = __ldg(crb + (size_t)c * HW), civ = __ldg(cib + (size_t)c * HW);
        sb[c][r0 * 128 + q0] = make_float2(zr * crv - zi * civ, zr * civ + zi * crv);
    }
    __syncthreads();
    // warp w owns coil line w
    int wl = tid >> 5, lane = tid & 31;
    float2* line = sb[wl];
#pragma unroll
    for (int len = 128; len >= 2; len >>= 1) {
        int h = len >> 1;
#pragma unroll
        for (int jj = 0; jj < 6; jj++) {
            int j = lane + jj * 32;
            int seg = j >> 6, b6 = j & 63;
            int grp = b6 / h, t = b6 - grp * h;
            int i1 = seg * 128 + grp * len + t;
            float2 u = line[i1], v = line[i1 + h];
            line[i1] = cadd(u, v);
            float2 d = csub(u, v);
            float2 w = g_tw128[t * (128 / len)];
            line[i1 + h] = make_float2(d.x * w.x - d.y * w.y, d.x * w.y + d.y * w.x);
        }
        __syncwarp();
    }
    // warp-local radix-3 combine + store
    size_t obase = ((size_t)(wl * BSZ + b)) * HW + (size_t)y * 384;
#pragma unroll
    for (int jj = 0; jj < 12; jj++) {
        int kk = lane + jj * 32;
        int k0 = kk & 127;
        int rv = __brev((unsigned)k0) >> 25;
        float2 c1 = g_tw384[kk], c2 = g_tw384[(2 * kk) % 384];
        float2 y0v = line[rv], y1 = line[128 + rv], y2 = line[256 + rv];
        float xr = y0v.x + c1.x * y1.x - c1.y * y1.y + c2.x * y2.x - c2.y * y2.y;
        float xi = y0v.y + c1.x * y1.y + c1.y * y1.x + c2.x * y2.y + c2.y * y2.x;
        g_k[obase + kk] = __floats2half2_rn(xr, xi);
    }
}

// ---------------- FUSED column pass, 256 thr, warp-per-column butterflies ----------------
__global__ __launch_bounds__(256) void fft_col_fused_k(const int* __restrict__ mask,
                                                       const float* __restrict__ tkr,
                                                       const float* __restrict__ tki) {
    __shared__ float2 sb[8 * 384];
    int img = blockIdx.x / 48, cg = blockIdx.x % 48;
    __half2* base = g_k + (size_t)img * HW + cg * 8;
    int tid = threadIdx.x, wid = tid >> 5, lane = tid & 31;
    for (int i = tid; i < 3072; i += 256) {
        int col = i & 7, yy = i >> 3;
        float2 Z = __half22float2(base[(size_t)yy * 384 + col]);
        sb[col * 384 + (yy % 3) * 128 + yy / 3] = Z;
    }
    __syncthreads();
    float2* line = sb + wid * 384;      // warp per column
#pragma unroll
    for (int len = 128; len >= 2; len >>= 1) {
        int h = len >> 1;
#pragma unroll
        for (int jj = 0; jj < 6; jj++) {
            int j = lane + jj * 32;
            int seg = j >> 6, b6 = j & 63;
            int grp = b6 / h, t = b6 - grp * h;
            int i1 = seg * 128 + grp * len + t;
            float2 u = line[i1], v = line[i1 + h];
            line[i1] = cadd(u, v);
            float2 d = csub(u, v);
            float2 w = g_tw128[t * (128 / len)];
            line[i1 + h] = make_float2(d.x * w.x - d.y * w.y, d.x * w.y + d.y * w.x);
        }
        __syncwarp();
    }
    __syncthreads();
    // radix-3 combine + DC (block-wide for coalesced tkr/tki)
    float2 val[12];
#pragma unroll
    for (int ii = 0; ii < 12; ii++) {
        int i = tid + ii * 256;
        int col = i & 7, k = i >> 3;
        int k0 = k & 127;
        int rv = __brev((unsigned)k0) >> 25;
        int cb = col * 384;
        float2 y0 = sb[cb + rv], y1 = sb[cb + 128 + rv], y2 = sb[cb + 256 + rv];
        float2 c1 = g_tw384[k], c2 = g_tw384[(2 * k) % 384];
        float xr = y0.x + c1.x * y1.x - c1.y * y1.y + c2.x * y2.x - c2.y * y2.y;
        float xi = y0.y + c1.x * y1.y + c1.y * y1.x + c2.x * y2.y + c2.y * y2.x;
        int gx = cg * 8 + col;
        int p = k * 384 + gx;
        float mv = (float)__ldg(mask + p);
        float sgn = ((gx + k) & 1) ? -1.f : 1.f;
        float coef = 384.f * 0.999999f * mv * sgn;
        float om = 1.f - mv;
        size_t gidx = (size_t)img * HW + p;
        val[ii] = make_float2(om * xr + coef * __ldg(tkr + gidx),
                              om * xi + coef * __ldg(tki + gidx));
    }
    __syncthreads();
#pragma unroll
    for (int ii = 0; ii < 12; ii++) {
        int i = tid + ii * 256;
        int col = i & 7, k = i >> 3;
        sb[col * 384 + (k % 3) * 128 + k / 3] = val[ii];
    }
    __syncthreads();
    // inverse butterflies, warp-local
#pragma unroll
    for (int len = 128; len >= 2; len >>= 1) {
        int h = len >> 1;
#pragma unroll
        for (int jj = 0; jj < 6; jj++) {
            int j = lane + jj * 32;
            int seg = j >> 6, b6 = j & 63;
            int grp = b6 / h, t = b6 - grp * h;
            int i1 = seg * 128 + grp * len + t;
            float2 u = line[i1], v = line[i1 + h];
            line[i1] = cadd(u, v);
            float2 d = csub(u, v);
            float2 w = g_tw128[t * (128 / len)];
            line[i1 + h] = make_float2(d.x * w.x + d.y * w.y, -d.x * w.y + d.y * w.x);
        }
        __syncwarp();
    }
    __syncthreads();
    for (int i = tid; i < 3072; i += 256) {
        int col = i & 7, k = i >> 3;
        int k0 = k & 127;
        int rv = __brev((unsigned)k0) >> 25;
        int cb = col * 384;
        float2 y0 = sb[cb + rv], y1 = sb[cb + 128 + rv], y2 = sb[cb + 256 + rv];
        float2 c1 = g_tw384[k], c2 = g_tw384[(2 * k) % 384];
        float s1 = -c1.y, s2 = -c2.y;
        float xr = (y0.x + c1.x * y1.x - s1 * y1.y + c2.x * y2.x - s2 * y2.y) * (1.f / 384.f);
        float xi = (y0.y + c1.x * y1.y + s1 * y1.x + c2.x * y2.y + s2 * y2.x) * (1.f / 384.f);
        base[(size_t)k * 384 + col] = __floats2half2_rn(xr, xi);
    }
}

// ---------------- fused inverse row FFT (12 coils) + coil combine, warp-local ----------------
__global__ __launch_bounds__(384) void invrow_final_k(const float* __restrict__ csr,
                                                      const float* __restrict__ csi,
                                                      float* __restrict__ out) {
    __shared__ float2 sb[12][384];
    int y = blockIdx.x % HH, b = blockIdx.x / HH;
    int tid = threadIdx.x;
    int r0 = tid % 3, q0 = tid / 3;
#pragma unroll
    for (int c = 0; c < CCH; c++) {
        float2 z = __half22float2(g_k[((size_t)(c * BSZ + b)) * HW + (size_t)y * 384 + tid]);
        sb[c][r0 * 128 + q0] = z;
    }
    __syncthreads();
    int wl = tid >> 5, lane = tid & 31;
    float2* line = sb[wl];
#pragma unroll
    for (int len = 128; len >= 2; len >>= 1) {
        int h = len >> 1;
#pragma unroll
        for (int jj = 0; jj < 6; jj++) {
            int j = lane + jj * 32;
            int seg = j >> 6, b6 = j & 63;
            int grp = b6 / h, t = b6 - grp * h;
            int i1 = seg * 128 + grp * len + t;
            float2 u = line[i1], v = line[i1 + h];
            line[i1] = cadd(u, v);
            float2 d = csub(u, v);
            float2 w = g_tw128[t * (128 / len)];
            line[i1 + h] = make_float2(d.x * w.x + d.y * w.y, -d.x * w.y + d.y * w.x);
        }
        __syncwarp();
    }
    __syncthreads();
    int k = tid;
    int k0 = k & 127;
    int rv = __brev((unsigned)k0) >> 25;
    float2 c1 = g_tw384[k], c2 = g_tw384[(2 * k) % 384];
    float s1 = -c1.y, s2 = -c2.y;
    float rr = 0.f, ri = 0.f;
    const float* crb = csr + (size_t)b * CCH * HW + (size_t)y * WW + k;
    const float* cib = csi + (size_t)b * CCH * HW + (size_t)y * WW + k;
#pragma unroll
    for (int c = 0; c < CCH; c++) {
        float2 y0 = sb[c][rv], y1 = sb[c][128 + rv], y2 = sb[c][256 + rv];
        float xr = (y0.x + c1.x * y1.x - s1 * y1.y + c2.x * y2.x - s2 * y2.y) * (1.f / 384.f);
        float xi = (y0.y + c1.x * y1.y + s1 * y1.x + c2.x * y2.y + s2 * y2.x) * (1.f / 384.f);
        float cr = __ldg(crb + (size_t)c * HW);
        float ci = __ldg(cib + (size_t)c * HW);
        rr += xr * cr + xi * ci;
        ri += xi * cr - xr * ci;
    }
    float sgn = ((k + y) & 1) ? -1.f : 1.f;
    out[(size_t)(b * 2 + 0) * HW + (size_t)y * WW + k] = sgn * rr;
    out[(size_t)(b * 2 + 1) * HW + (size_t)y * WW + k] = sgn * ri;
}

// ---------------- launch: fork/join dual-stream graph ----------------
extern "C" void kernel_launch(void* const* d_in, const int* in_sizes, int n_in,
                              void* d_out, int out_size) {
    (void)in_sizes; (void)n_in; (void)out_size;
    const float* input = (const float*)d_in[0];
    const float* adj   = (const float*)d_in[1];
    const int*   mask  = (const int*)  d_in[2];
    const float* csr   = (const float*)d_in[3];
    const float* csi   = (const float*)d_in[4];
    const float* tkr   = (const float*)d_in[5];
    const float* tki   = (const float*)d_in[6];
    const float* W1    = (const float*)d_in[7];
    const float* W3    = (const float*)d_in[8];
    const float* arf   = (const float*)d_in[9];
    const float* cw1   = (const float*)d_in[10];
    const float* cb1   = (const float*)d_in[11];
    const float* cw2   = (const float*)d_in[12];
    const float* cb2   = (const float*)d_in[13];
    const float* cw3   = (const float*)d_in[14];
    const float* cb3   = (const float*)d_in[15];
    float* out = (float*)d_out;

    static cudaStream_t s2 = nullptr;
    static cudaEvent_t e_fork = nullptr, e_join = nullptr;
    static int smem_set = 0;
    const int CONV2_SMEM = (2112 + 1536) * 16;   // 58368 B
    const int CONV3_SMEM = (3168 + 576) * 16;    // 59904 B
    if (!s2) {
        cudaStreamCreateWithFlags(&s2, cudaStreamNonBlocking);
        cudaEventCreateWithFlags(&e_fork, cudaEventDisableTiming);
        cudaEventCreateWithFlags(&e_join, cudaEventDisableTiming);
    }
    if (!smem_set) {
        cudaFuncSetAttribute(conv2_mma, cudaFuncAttributeMaxDynamicSharedMemorySize, CONV2_SMEM);
        cudaFuncSetAttribute(conv3_mma, cudaFuncAttributeMaxDynamicSharedMemorySize, CONV3_SMEM);
        smem_set = 1;
    }

    // fork: GCN branch on s2, CNN branch on default stream
    cudaEventRecord(e_fork, 0);
    cudaStreamWaitEvent(s2, e_fork, 0);

    adj_cvt_k<<<32768, 256, 0, s2>>>(adj);                       // 0
    gcn_s_k<<<256, 128, 0, s2>>>(input, W1);                     // 1
    gemm2_k<<<dim3(4, 32, 2), 256, 0, s2>>>(0, 256, W3);         // 2
    gemm2_k<<<dim3(3, 32, 2), 256, 0, s2>>>(1, 144, nullptr);    // 3  <-- profiled
    cudaEventRecord(e_join, s2);

    prep_w_k<<<144, 256>>>(cw2, cw3);                            // 4 (incl. twiddles)
    conv1_k<<<4608, 256>>>(input, cw1, cb1);                     // 5
    conv2_mma<<<dim3(6, 192, 4), 128, CONV2_SMEM>>>(cb2);        // 6
    conv3_mma<<<dim3(6, 96, 4), 128, CONV3_SMEM>>>(cb3);         // 7

    // join, then FFT chain
    cudaStreamWaitEvent(0, e_join, 0);
    fwdrow12_k<<<4 * 384, 384>>>(input, arf, csr, csi);          // 8
    fft_col_fused_k<<<48 * 48, 256>>>(mask, tkr, tki);           // 9
    invrow_final_k<<<4 * 384, 384>>>(csr, csi, out);             // 10
}